// round 9
// baseline (speedup 1.0000x reference)
#include <cuda_runtime.h>
#include <cuda_bf16.h>
#include <stdint.h>
#include <math.h>

#define NN  50000
#define NE  250000
#define NEA 500000
#define NR  300
#define EHD 300
#define THD 100

// ------------------------------------------------------------------
// Static device scratch
// ------------------------------------------------------------------
struct Scratch {
    float X[(size_t)NN * EHD];
    float Y[(size_t)NN * EHD];   // reused as gate buffer
    float Z[(size_t)NN * EHD];
    float S[(size_t)NN * THD];
    float RF[NR * EHD];
    float ER0[NR * EHD];
    float ER1[NR * EHD];
    float ER2[NR * EHD];
    float cR0[NR];
    float cR1[NR];
    float cR2[NR];
    float xa[NN];
    float xj[NN];
    float wj[NEA];
    int jall[NEA];
    int relh[NE];
    int relt[NE];
    int hr[NE];
    int tr[NE];
    int cnt_all[NN];
    int cnt_h[NN];
    int cnt_t[NN];
    int cnt_r[NR];
    int off_all[NN + 1];
    int off_h[NN + 1];
    int off_t[NN + 1];
    int off_r[NR + 1];
    int cur_all[NN];
    int cur_h[NN];
    int cur_t[NN];
    int cur_r[NR];
};
__device__ Scratch g_scr;

// ------------------------------------------------------------------
// helpers
// ------------------------------------------------------------------
__device__ __forceinline__ float lrelu01(float z) { return z > 0.f ? z : 0.01f * z; }

__device__ __forceinline__ float wredsum(float v) {
    #pragma unroll
    for (int o = 16; o > 0; o >>= 1) v += __shfl_xor_sync(0xffffffffu, v, o);
    return v;
}
__device__ __forceinline__ float wredmax(float v) {
    #pragma unroll
    for (int o = 16; o > 0; o >>= 1) v = fmaxf(v, __shfl_xor_sync(0xffffffffu, v, o));
    return v;
}

__device__ __forceinline__ uint32_t f2tf32(float f) {
    uint32_t r;
    asm("cvt.rna.tf32.f32 %0, %1;" : "=r"(r) : "f"(f));
    return r;
}

static inline int divup(int a, int b) { return (a + b - 1) / b; }

// ------------------------------------------------------------------
// setup kernels
// ------------------------------------------------------------------
__global__ void k_hist4(const int* __restrict__ ii, const int* __restrict__ h,
                        const int* __restrict__ t, const int* __restrict__ rel) {
    int y = blockIdx.y;
    const int* keys; int n; int* cnt;
    if      (y == 0) { keys = ii;  n = NEA; cnt = g_scr.cnt_all; }
    else if (y == 1) { keys = h;   n = NE;  cnt = g_scr.cnt_h; }
    else if (y == 2) { keys = t;   n = NE;  cnt = g_scr.cnt_t; }
    else             { keys = rel; n = NE;  cnt = g_scr.cnt_r; }
    for (int i = blockIdx.x * blockDim.x + threadIdx.x; i < n; i += gridDim.x * blockDim.x)
        atomicAdd(&cnt[keys[i]], 1);
}

// single-launch scan: one block per histogram, warp-shuffle scan per chunk
__global__ void k_scan4() {
    int y = blockIdx.x;
    const int* c; int n; int* off; int* cur;
    if      (y == 0) { c = g_scr.cnt_all; n = NN; off = g_scr.off_all; cur = g_scr.cur_all; }
    else if (y == 1) { c = g_scr.cnt_h;   n = NN; off = g_scr.off_h;   cur = g_scr.cur_h; }
    else if (y == 2) { c = g_scr.cnt_t;   n = NN; off = g_scr.off_t;   cur = g_scr.cur_t; }
    else             { c = g_scr.cnt_r;   n = NR; off = g_scr.off_r;   cur = g_scr.cur_r; }
    __shared__ int wsum[32];
    __shared__ int carrysh;
    int tid = threadIdx.x;
    int wid = tid >> 5, lane = tid & 31;
    if (tid == 0) carrysh = 0;
    __syncthreads();
    for (int base = 0; base < n; base += 1024) {
        int v = (base + tid < n) ? c[base + tid] : 0;
        int s = v;
        #pragma unroll
        for (int o = 1; o < 32; o <<= 1) {
            int t2 = __shfl_up_sync(0xffffffffu, s, o);
            if (lane >= o) s += t2;
        }
        if (lane == 31) wsum[wid] = s;
        __syncthreads();
        if (wid == 0) {
            int w = wsum[lane];
            #pragma unroll
            for (int o = 1; o < 32; o <<= 1) {
                int t2 = __shfl_up_sync(0xffffffffu, w, o);
                if (lane >= o) w += t2;
            }
            wsum[lane] = w;
        }
        __syncthreads();
        int woff = (wid > 0) ? wsum[wid - 1] : 0;
        int total = wsum[31];
        int ex = carrysh + woff + s - v;
        if (base + tid < n) { off[base + tid] = ex; cur[base + tid] = ex; }
        __syncthreads();
        if (tid == 0) carrysh += total;
        __syncthreads();
    }
    if (tid == 0) off[n] = carrysh;
}

__global__ void k_scatter4(const int* __restrict__ ii, const int* __restrict__ jjv,
                           const int* __restrict__ h, const int* __restrict__ t,
                           const int* __restrict__ rel) {
    int y = blockIdx.y;
    int stride = gridDim.x * blockDim.x;
    int i0 = blockIdx.x * blockDim.x + threadIdx.x;
    if (y == 0) {
        for (int i = i0; i < NEA; i += stride) {
            int pos = atomicAdd(&g_scr.cur_all[ii[i]], 1);
            int j = jjv[i];
            int d = g_scr.cnt_all[j];
            g_scr.jall[pos] = j;
            g_scr.wj[pos] = (d > 0) ? rsqrtf((float)d) : 0.0f;
        }
    } else if (y == 1) {
        for (int i = i0; i < NE; i += stride) {
            int pos = atomicAdd(&g_scr.cur_h[h[i]], 1);
            g_scr.relh[pos] = rel[i];
        }
    } else if (y == 2) {
        for (int i = i0; i < NE; i += stride) {
            int pos = atomicAdd(&g_scr.cur_t[t[i]], 1);
            g_scr.relt[pos] = rel[i];
        }
    } else {
        for (int i = i0; i < NE; i += stride) {
            int pos = atomicAdd(&g_scr.cur_r[rel[i]], 1);
            g_scr.hr[pos] = h[i];
            g_scr.tr[pos] = t[i];
        }
    }
}

// ------------------------------------------------------------------
// TF32 tensor-core GEMM, no smem: registers straight from gmem.
// OUT = C + bias           (gate == 0)
// OUT = sigmoid(C + bias)  (gate == 1)
// BM=128, BN=64, 256 threads; warp tile 32x32 (2 m16 x 4 n8).
// ------------------------------------------------------------------
#define MMA_TF32(c, a, b) \
    asm volatile("mma.sync.aligned.m16n8k8.row.col.f32.tf32.tf32.f32 " \
        "{%0,%1,%2,%3}, {%4,%5,%6,%7}, {%8,%9}, {%0,%1,%2,%3};" \
        : "+f"((c)[0]), "+f"((c)[1]), "+f"((c)[2]), "+f"((c)[3]) \
        : "r"((a)[0]), "r"((a)[1]), "r"((a)[2]), "r"((a)[3]), \
          "r"((b)[0]), "r"((b)[1]))

__global__ __launch_bounds__(256) void k_tgemm(
    const float* __restrict__ A, const float* __restrict__ W,
    const float* __restrict__ bias, float* __restrict__ OUT,
    int M, int N, int K, int gate) {
    const int mb = blockIdx.x * 128, nb = blockIdx.y * 64;
    const int tid = threadIdx.x;
    const int lane = tid & 31;
    const int wid = tid >> 5;
    const int warp_m = (wid & 3) * 32;
    const int warp_n = (wid >> 2) * 32;
    const int r = lane >> 2;     // 0..7
    const int c = lane & 3;      // 0..3

    float acc[2][4][4];
    #pragma unroll
    for (int mt = 0; mt < 2; mt++)
        #pragma unroll
        for (int nt = 0; nt < 4; nt++)
            #pragma unroll
            for (int q = 0; q < 4; q++) acc[mt][nt][q] = 0.f;

    // clamped A row pointers (OOB rows produce garbage discarded in epilogue)
    const float* ar[2][2];
    #pragma unroll
    for (int mt = 0; mt < 2; mt++) {
        int gm0 = mb + warp_m + mt * 16 + r;
        int gm1 = gm0 + 8;
        if (gm0 > M - 1) gm0 = M - 1;
        if (gm1 > M - 1) gm1 = M - 1;
        ar[mt][0] = A + (size_t)gm0 * K;
        ar[mt][1] = A + (size_t)gm1 * K;
    }
    // clamped B column indices
    int gn[4];
    #pragma unroll
    for (int nt = 0; nt < 4; nt++) {
        int g = nb + warp_n + nt * 8 + r;
        gn[nt] = (g > N - 1) ? (N - 1) : g;
    }

    int kmain = K & ~7;           // full k8 steps where k0+7 < K iff K%8==0
    if (K & 7) kmain = K - (K & 7);
    // main loop: cols k0+c and k0+c+4 both < kmain+8 <= K when k0 < kmain
    for (int k0 = 0; k0 < kmain; k0 += 8) {
        uint32_t a[2][4], b[4][2];
        #pragma unroll
        for (int mt = 0; mt < 2; mt++) {
            a[mt][0] = f2tf32(__ldg(ar[mt][0] + k0 + c));
            a[mt][1] = f2tf32(__ldg(ar[mt][1] + k0 + c));
            a[mt][2] = f2tf32(__ldg(ar[mt][0] + k0 + c + 4));
            a[mt][3] = f2tf32(__ldg(ar[mt][1] + k0 + c + 4));
        }
        const float* w0 = W + (size_t)(k0 + c) * N;
        const float* w1 = W + (size_t)(k0 + c + 4) * N;
        #pragma unroll
        for (int nt = 0; nt < 4; nt++) {
            b[nt][0] = f2tf32(__ldg(w0 + gn[nt]));
            b[nt][1] = f2tf32(__ldg(w1 + gn[nt]));
        }
        #pragma unroll
        for (int mt = 0; mt < 2; mt++)
            #pragma unroll
            for (int nt = 0; nt < 4; nt++)
                MMA_TF32(acc[mt][nt], a[mt], b[nt]);
    }
    if (K & 7) {
        int k0 = kmain;
        uint32_t a[2][4], b[4][2];
        int k_lo = k0 + c, k_hi = k0 + c + 4;
        bool lo_ok = k_lo < K, hi_ok = k_hi < K;
        #pragma unroll
        for (int mt = 0; mt < 2; mt++) {
            a[mt][0] = lo_ok ? f2tf32(__ldg(ar[mt][0] + k_lo)) : 0u;
            a[mt][1] = lo_ok ? f2tf32(__ldg(ar[mt][1] + k_lo)) : 0u;
            a[mt][2] = hi_ok ? f2tf32(__ldg(ar[mt][0] + k_hi)) : 0u;
            a[mt][3] = hi_ok ? f2tf32(__ldg(ar[mt][1] + k_hi)) : 0u;
        }
        const float* w0 = W + (size_t)k_lo * N;
        const float* w1 = W + (size_t)k_hi * N;
        #pragma unroll
        for (int nt = 0; nt < 4; nt++) {
            b[nt][0] = lo_ok ? f2tf32(__ldg(w0 + gn[nt])) : 0u;
            b[nt][1] = hi_ok ? f2tf32(__ldg(w1 + gn[nt])) : 0u;
        }
        #pragma unroll
        for (int mt = 0; mt < 2; mt++)
            #pragma unroll
            for (int nt = 0; nt < 4; nt++)
                MMA_TF32(acc[mt][nt], a[mt], b[nt]);
    }

    // epilogue
    const int erow = lane >> 2;
    const int ecol = (lane & 3) * 2;
    #pragma unroll
    for (int mt = 0; mt < 2; mt++) {
        #pragma unroll
        for (int nt = 0; nt < 4; nt++) {
            #pragma unroll
            for (int q = 0; q < 4; q++) {
                int gm = mb + warp_m + mt * 16 + erow + (q >> 1) * 8;
                int gc = nb + warp_n + nt * 8 + ecol + (q & 1);
                if (gm >= M || gc >= N) continue;
                float v = acc[mt][nt][q] + bias[gc];
                if (gate) v = 1.f / (1.f + expf(-v));
                OUT[(size_t)gm * N + gc] = v;
            }
        }
    }
}

// ------------------------------------------------------------------
// GCN + highway combine: xout = g*relu(dinv_n * gather) + (1-g)*xin_row
// warp per node, float4, presorted j/w
// ------------------------------------------------------------------
__global__ void k_gcnhw(const float* __restrict__ xin, const float* __restrict__ gate,
                        float* __restrict__ xout) {
    int n = (blockIdx.x * blockDim.x + threadIdx.x) >> 5;
    if (n >= NN) return;
    int lane = threadIdx.x & 31;
    int s0 = g_scr.off_all[n], s1 = g_scr.off_all[n + 1];
    bool l2ok = (64 + lane) < 75;
    float4 a0 = {0,0,0,0}, a1 = {0,0,0,0}, a2 = {0,0,0,0};
    for (int p = s0; p < s1; p++) {
        int j = g_scr.jall[p];
        float w = g_scr.wj[p];
        const float4* xr = (const float4*)(xin + (size_t)j * EHD);
        float4 v0 = __ldg(xr + lane);
        float4 v1 = __ldg(xr + 32 + lane);
        a0.x += w*v0.x; a0.y += w*v0.y; a0.z += w*v0.z; a0.w += w*v0.w;
        a1.x += w*v1.x; a1.y += w*v1.y; a1.z += w*v1.z; a1.w += w*v1.w;
        if (l2ok) {
            float4 v2 = __ldg(xr + 64 + lane);
            a2.x += w*v2.x; a2.y += w*v2.y; a2.z += w*v2.z; a2.w += w*v2.w;
        }
    }
    int dcnt = s1 - s0;
    float dn = (dcnt > 0) ? rsqrtf((float)dcnt) : 0.0f;
    const float4* xp = (const float4*)(xin + (size_t)n * EHD);
    const float4* gp = (const float4*)(gate + (size_t)n * EHD);
    float4* yr = (float4*)(xout + (size_t)n * EHD);
    float4 o, g4, p4;

    g4 = gp[lane]; p4 = xp[lane];
    o.x = g4.x * fmaxf(dn*a0.x, 0.f) + (1.f - g4.x) * p4.x;
    o.y = g4.y * fmaxf(dn*a0.y, 0.f) + (1.f - g4.y) * p4.y;
    o.z = g4.z * fmaxf(dn*a0.z, 0.f) + (1.f - g4.z) * p4.z;
    o.w = g4.w * fmaxf(dn*a0.w, 0.f) + (1.f - g4.w) * p4.w;
    yr[lane] = o;

    g4 = gp[32 + lane]; p4 = xp[32 + lane];
    o.x = g4.x * fmaxf(dn*a1.x, 0.f) + (1.f - g4.x) * p4.x;
    o.y = g4.y * fmaxf(dn*a1.y, 0.f) + (1.f - g4.y) * p4.y;
    o.z = g4.z * fmaxf(dn*a1.z, 0.f) + (1.f - g4.z) * p4.z;
    o.w = g4.w * fmaxf(dn*a1.w, 0.f) + (1.f - g4.w) * p4.w;
    yr[32 + lane] = o;

    if (l2ok) {
        g4 = gp[64 + lane]; p4 = xp[64 + lane];
        o.x = g4.x * fmaxf(dn*a2.x, 0.f) + (1.f - g4.x) * p4.x;
        o.y = g4.y * fmaxf(dn*a2.y, 0.f) + (1.f - g4.y) * p4.y;
        o.z = g4.z * fmaxf(dn*a2.z, 0.f) + (1.f - g4.z) * p4.z;
        o.w = g4.w * fmaxf(dn*a2.w, 0.f) + (1.f - g4.w) * p4.w;
        yr[64 + lane] = o;
    }
}

// ------------------------------------------------------------------
// per-relation means + rf2 + RF assembly
// ------------------------------------------------------------------
__global__ __launch_bounds__(256) void k_relmean(const float* __restrict__ sr1w,
                                                 const float* __restrict__ sr1b) {
    int r = blockIdx.x;
    int tid = threadIdx.x;
    __shared__ float acc[200];
    __shared__ float cat[200];
    if (tid < 200) acc[tid] = 0.f;
    __syncthreads();

    int wi = tid >> 5, lane = tid & 31;
    int s0 = g_scr.off_r[r], s1 = g_scr.off_r[r + 1];
    float4 lh = {0,0,0,0}, lt = {0,0,0,0};
    for (int p = s0 + wi; p < s1; p += 8) {
        int hh = g_scr.hr[p], tt = g_scr.tr[p];
        if (lane < 25) {
            const float4* sh_ = (const float4*)(g_scr.S + (size_t)hh * THD);
            const float4* st_ = (const float4*)(g_scr.S + (size_t)tt * THD);
            float4 v = __ldg(sh_ + lane);
            lh.x += v.x; lh.y += v.y; lh.z += v.z; lh.w += v.w;
            float4 u = __ldg(st_ + lane);
            lt.x += u.x; lt.y += u.y; lt.z += u.z; lt.w += u.w;
        }
    }
    if (lane < 25) {
        atomicAdd(&acc[4*lane+0], lh.x); atomicAdd(&acc[4*lane+1], lh.y);
        atomicAdd(&acc[4*lane+2], lh.z); atomicAdd(&acc[4*lane+3], lh.w);
        atomicAdd(&acc[100+4*lane+0], lt.x); atomicAdd(&acc[100+4*lane+1], lt.y);
        atomicAdd(&acc[100+4*lane+2], lt.z); atomicAdd(&acc[100+4*lane+3], lt.w);
    }
    __syncthreads();
    float c = fmaxf((float)(s1 - s0), 1.f);
    if (tid < 200) cat[tid] = acc[tid] / c;
    __syncthreads();
    if (tid < 100) {
        float a = sr1b[tid];
        #pragma unroll 4
        for (int k = 0; k < 200; k++) a += cat[k] * sr1w[k * 100 + tid];
        float* rf = g_scr.RF + (size_t)r * EHD;
        rf[tid]       = a;
        rf[100 + tid] = cat[tid];
        rf[200 + tid] = cat[100 + tid];
    }
}

// ------------------------------------------------------------------
// batched small sgemm: ER_k = RF @ wr_k + br_k
// ------------------------------------------------------------------
__global__ __launch_bounds__(256) void k_sgemm3(
    const float* __restrict__ W0, const float* __restrict__ b0,
    const float* __restrict__ W1, const float* __restrict__ b1,
    const float* __restrict__ W2, const float* __restrict__ b2) {
    const float* W; const float* bias; float* OUT;
    int z = blockIdx.z;
    if      (z == 0) { W = W0; bias = b0; OUT = g_scr.ER0; }
    else if (z == 1) { W = W1; bias = b1; OUT = g_scr.ER1; }
    else             { W = W2; bias = b2; OUT = g_scr.ER2; }
    const float* A = g_scr.RF;
    const int M = NR, N = EHD, K = EHD;

    __shared__ float As[16][128];
    __shared__ float Bs[16][64];
    int mb = blockIdx.x * 128, nb = blockIdx.y * 64;
    int tid = threadIdx.x;
    int ty = tid >> 4;
    int tx = tid & 15;
    float acc[8][4];
    #pragma unroll
    for (int i = 0; i < 8; i++)
        #pragma unroll
        for (int j = 0; j < 4; j++) acc[i][j] = 0.f;

    for (int k0 = 0; k0 < K; k0 += 16) {
        #pragma unroll
        for (int l = 0; l < 8; l++) {
            int idx = tid + l * 256;
            int arr = idx >> 4, ak = idx & 15;
            int gm = mb + arr, gk = k0 + ak;
            As[ak][arr] = (gm < M && gk < K) ? A[(size_t)gm * K + gk] : 0.f;
        }
        #pragma unroll
        for (int l = 0; l < 4; l++) {
            int idx = tid + l * 256;
            int bn = idx & 63, bk = idx >> 6;
            int gk = k0 + bk, gnn = nb + bn;
            Bs[bk][bn] = (gk < K && gnn < N) ? W[(size_t)gk * N + gnn] : 0.f;
        }
        __syncthreads();
        #pragma unroll
        for (int k = 0; k < 16; k++) {
            float a[8], b[4];
            #pragma unroll
            for (int i = 0; i < 8; i++) a[i] = As[k][ty * 8 + i];
            #pragma unroll
            for (int j = 0; j < 4; j++) b[j] = Bs[k][tx * 4 + j];
            #pragma unroll
            for (int i = 0; i < 8; i++)
                #pragma unroll
                for (int j = 0; j < 4; j++) acc[i][j] += a[i] * b[j];
        }
        __syncthreads();
    }
    #pragma unroll
    for (int i = 0; i < 8; i++) {
        int gm = mb + ty * 8 + i;
        if (gm >= M) continue;
        #pragma unroll
        for (int j = 0; j < 4; j++) {
            int gnn = nb + tx * 4 + j;
            if (gnn >= N) continue;
            OUT[(size_t)gm * N + gnn] = acc[i][j] + bias[gnn];
        }
    }
}

// ------------------------------------------------------------------
// batched rowdot over ER matrices: cR_k = ER_k . ar_k
// ------------------------------------------------------------------
__global__ void k_rowdot3(const float* __restrict__ v0, const float* __restrict__ v1,
                          const float* __restrict__ v2) {
    int y = blockIdx.y;
    const float* Mtx; const float* v; float* out;
    if      (y == 0) { Mtx = g_scr.ER0; v = v0; out = g_scr.cR0; }
    else if (y == 1) { Mtx = g_scr.ER1; v = v1; out = g_scr.cR1; }
    else             { Mtx = g_scr.ER2; v = v2; out = g_scr.cR2; }
    int r = (blockIdx.x * blockDim.x + threadIdx.x) >> 5;
    int lane = threadIdx.x & 31;
    if (r >= NR) return;
    const float4* mr = (const float4*)(Mtx + (size_t)r * EHD);
    const float4* vv = (const float4*)v;
    float s = 0.f;
    float4 a = mr[lane], b = vv[lane];
    s += a.x*b.x + a.y*b.y + a.z*b.z + a.w*b.w;
    a = mr[32 + lane]; b = vv[32 + lane];
    s += a.x*b.x + a.y*b.y + a.z*b.z + a.w*b.w;
    if (lane < 11) {
        a = mr[64 + lane]; b = vv[64 + lane];
        s += a.x*b.x + a.y*b.y + a.z*b.z + a.w*b.w;
    }
    s = wredsum(s);
    if (lane == 0) out[r] = s;
}

// ------------------------------------------------------------------
// rowdot over Z: xa = Z . v
// ------------------------------------------------------------------
__global__ void k_rowdotZ(const float* __restrict__ v, float* __restrict__ out) {
    int n = (blockIdx.x * blockDim.x + threadIdx.x) >> 5;
    int lane = threadIdx.x & 31;
    if (n >= NN) return;
    const float4* mr = (const float4*)(g_scr.Z + (size_t)n * EHD);
    const float4* vv = (const float4*)v;
    float s = 0.f;
    float4 a = mr[lane], b = vv[lane];
    s += a.x*b.x + a.y*b.y + a.z*b.z + a.w*b.w;
    a = mr[32 + lane]; b = vv[32 + lane];
    s += a.x*b.x + a.y*b.y + a.z*b.z + a.w*b.w;
    if (lane < 11) {
        a = mr[64 + lane]; b = vv[64 + lane];
        s += a.x*b.x + a.y*b.y + a.z*b.z + a.w*b.w;
    }
    s = wredsum(s);
    if (lane == 0) out[n] = s;
}

// ------------------------------------------------------------------
// fused r2e
// ------------------------------------------------------------------
__global__ void k_r2e(const float* __restrict__ ER, const float* __restrict__ cR,
                      const int* __restrict__ off, const int* __restrict__ rels,
                      const float* __restrict__ an1, const float* __restrict__ an2,
                      float* __restrict__ xa1, float* __restrict__ xj2, int dual) {
    int n = (blockIdx.x * blockDim.x + threadIdx.x) >> 5;
    if (n >= NN) return;
    int lane = threadIdx.x & 31;
    int s0 = off[n], s1 = off[n + 1];
    bool l2ok = (64 + lane) < 75;
    float4 a0 = {0,0,0,0}, a1 = {0,0,0,0}, a2 = {0,0,0,0};

    if (s1 > s0) {
        float xan = g_scr.xa[n];
        float m = -1e30f;
        for (int p = s0 + lane; p < s1; p += 32)
            m = fmaxf(m, lrelu01(xan + cR[rels[p]]));
        m = wredmax(m);
        float den = 0.f;
        for (int p = s0 + lane; p < s1; p += 32)
            den += expf(lrelu01(xan + cR[rels[p]]) - m);
        den = wredsum(den);
        float inv = 1.f / den;
        for (int p = s0; p < s1; p++) {
            int r = rels[p];
            float w = expf(lrelu01(xan + cR[r]) - m) * inv;
            const float4* er = (const float4*)(ER + (size_t)r * EHD);
            float4 v0 = __ldg(er + lane);
            float4 v1 = __ldg(er + 32 + lane);
            a0.x += w*v0.x; a0.y += w*v0.y; a0.z += w*v0.z; a0.w += w*v0.w;
            a1.x += w*v1.x; a1.y += w*v1.y; a1.z += w*v1.z; a1.w += w*v1.w;
            if (l2ok) {
                float4 v2 = __ldg(er + 64 + lane);
                a2.x += w*v2.x; a2.y += w*v2.y; a2.z += w*v2.z; a2.w += w*v2.w;
            }
        }
    }
    float4* xr = (float4*)(g_scr.Z + (size_t)n * EHD);
    const float4* w1 = (const float4*)an1;
    const float4* w2 = (const float4*)an2;
    float d1 = 0.f, d2 = 0.f;

    float4 v = xr[lane];
    v.x += fmaxf(a0.x, 0.f); v.y += fmaxf(a0.y, 0.f); v.z += fmaxf(a0.z, 0.f); v.w += fmaxf(a0.w, 0.f);
    xr[lane] = v;
    float4 q = w1[lane];
    d1 += v.x*q.x + v.y*q.y + v.z*q.z + v.w*q.w;
    if (dual) { float4 q2 = w2[lane]; d2 += v.x*q2.x + v.y*q2.y + v.z*q2.z + v.w*q2.w; }

    v = xr[32 + lane];
    v.x += fmaxf(a1.x, 0.f); v.y += fmaxf(a1.y, 0.f); v.z += fmaxf(a1.z, 0.f); v.w += fmaxf(a1.w, 0.f);
    xr[32 + lane] = v;
    q = w1[32 + lane];
    d1 += v.x*q.x + v.y*q.y + v.z*q.z + v.w*q.w;
    if (dual) { float4 q2 = w2[32 + lane]; d2 += v.x*q2.x + v.y*q2.y + v.z*q2.z + v.w*q2.w; }

    if (l2ok) {
        v = xr[64 + lane];
        v.x += fmaxf(a2.x, 0.f); v.y += fmaxf(a2.y, 0.f); v.z += fmaxf(a2.z, 0.f); v.w += fmaxf(a2.w, 0.f);
        xr[64 + lane] = v;
        q = w1[64 + lane];
        d1 += v.x*q.x + v.y*q.y + v.z*q.z + v.w*q.w;
        if (dual) { float4 q2 = w2[64 + lane]; d2 += v.x*q2.x + v.y*q2.y + v.z*q2.z + v.w*q2.w; }
    }
    d1 = wredsum(d1);
    if (lane == 0) xa1[n] = d1;
    if (dual) {
        d2 = wredsum(d2);
        if (lane == 0) xj2[n] = d2;
    }
}

// ------------------------------------------------------------------
// final GAT + fc output
// ------------------------------------------------------------------
__global__ void k_gatfinal(const float* __restrict__ fcw, const float* __restrict__ fcb,
                           float* __restrict__ outp) {
    int n = (blockIdx.x * blockDim.x + threadIdx.x) >> 5;
    if (n >= NN) return;
    int lane = threadIdx.x & 31;
    int s0 = g_scr.off_all[n], s1 = g_scr.off_all[n + 1];
    bool l2ok = (64 + lane) < 75;
    float4 a0 = {0,0,0,0}, a1 = {0,0,0,0}, a2 = {0,0,0,0};

    if (s1 > s0) {
        float xin = g_scr.xa[n];
        float m = -1e30f;
        for (int p = s0 + lane; p < s1; p += 32)
            m = fmaxf(m, lrelu01(xin + g_scr.xj[g_scr.jall[p]]));
        m = wredmax(m);
        float den = 0.f;
        for (int p = s0 + lane; p < s1; p += 32)
            den += expf(lrelu01(xin + g_scr.xj[g_scr.jall[p]]) - m);
        den = wredsum(den);
        float inv = 1.f / den;
        for (int p = s0; p < s1; p++) {
            int j = g_scr.jall[p];
            float w = expf(lrelu01(xin + g_scr.xj[j]) - m) * inv;
            const float4* xr = (const float4*)(g_scr.Z + (size_t)j * EHD);
            float4 v0 = __ldg(xr + lane);
            float4 v1 = __ldg(xr + 32 + lane);
            a0.x += w*v0.x; a0.y += w*v0.y; a0.z += w*v0.z; a0.w += w*v0.w;
            a1.x += w*v1.x; a1.y += w*v1.y; a1.z += w*v1.z; a1.w += w*v1.w;
            if (l2ok) {
                float4 v2 = __ldg(xr + 64 + lane);
                a2.x += w*v2.x; a2.y += w*v2.y; a2.z += w*v2.z; a2.w += w*v2.w;
            }
        }
    }
    const float4* xn = (const float4*)(g_scr.Z + (size_t)n * EHD);
    const float4* f1 = (const float4*)fcw;
    const float4* f2 = (const float4*)(fcw + EHD);
    float local = 0.f;

    float4 v = xn[lane], q = f1[lane], g = f2[lane];
    local += v.x*q.x + v.y*q.y + v.z*q.z + v.w*q.w;
    local += fmaxf(a0.x,0.f)*g.x + fmaxf(a0.y,0.f)*g.y + fmaxf(a0.z,0.f)*g.z + fmaxf(a0.w,0.f)*g.w;
    v = xn[32+lane]; q = f1[32+lane]; g = f2[32+lane];
    local += v.x*q.x + v.y*q.y + v.z*q.z + v.w*q.w;
    local += fmaxf(a1.x,0.f)*g.x + fmaxf(a1.y,0.f)*g.y + fmaxf(a1.z,0.f)*g.z + fmaxf(a1.w,0.f)*g.w;
    if (l2ok) {
        v = xn[64+lane]; q = f1[64+lane]; g = f2[64+lane];
        local += v.x*q.x + v.y*q.y + v.z*q.z + v.w*q.w;
        local += fmaxf(a2.x,0.f)*g.x + fmaxf(a2.y,0.f)*g.y + fmaxf(a2.z,0.f)*g.z + fmaxf(a2.w,0.f)*g.w;
    }
    local = wredsum(local);
    if (lane == 0) outp[n] = local + fcb[0];
}

// ------------------------------------------------------------------
// launcher
// ------------------------------------------------------------------
extern "C" void kernel_launch(void* const* d_in, const int* in_sizes, int n_in,
                              void* d_out, int out_size) {
    const float* x      = (const float*)d_in[0];
    const int*   ei     = (const int*)d_in[1];
    const int*   rel    = (const int*)d_in[2];
    const int*   eia    = (const int*)d_in[3];
    const float* hw1_w  = (const float*)d_in[5];
    const float* hw1_b  = (const float*)d_in[6];
    const float* hw2_w  = (const float*)d_in[7];
    const float* hw2_b  = (const float*)d_in[8];
    const float* tc1_w  = (const float*)d_in[9];
    const float* tc1_b  = (const float*)d_in[10];
    const float* sr1_w  = (const float*)d_in[11];
    const float* sr1_b  = (const float*)d_in[12];
    const float* wr_w   = (const float*)d_in[15];
    const float* wr_b   = (const float*)d_in[16];
    const float* wr1_w  = (const float*)d_in[17];
    const float* wr1_b  = (const float*)d_in[18];
    const float* wr2_w  = (const float*)d_in[19];
    const float* wr2_b  = (const float*)d_in[20];
    const float* ah_w   = (const float*)d_in[21];
    const float* ah1_w  = (const float*)d_in[22];
    const float* at_w   = (const float*)d_in[23];
    const float* ar1_w  = (const float*)d_in[24];
    const float* ar2_w  = (const float*)d_in[25];
    const float* ar3_w  = (const float*)d_in[26];
    const float* ai_w   = (const float*)d_in[27];
    const float* aj_w   = (const float*)d_in[28];
    const float* fc_w   = (const float*)d_in[29];
    const float* fc_b   = (const float*)d_in[30];
    float* out = (float*)d_out;

    const int* h  = ei;
    const int* t  = ei + NE;
    const int* jj = eia;
    const int* ii = eia + NEA;

    Scratch* g = nullptr;
    cudaGetSymbolAddress((void**)&g, g_scr);

    const int TPB = 256;
    const int NODE_BLKS = divup(NN * 32, TPB);

    cudaMemsetAsync(g->cnt_all, 0, (size_t)(3 * NN + NR) * sizeof(int));

    k_hist4<<<dim3(128, 4), TPB>>>(ii, h, t, rel);        // 1
    k_scan4<<<4, 1024>>>();                               // 2
    k_scatter4<<<dim3(512, 4), TPB>>>(ii, jj, h, t, rel); // 3

    dim3 gemmGrid300(divup(NN, 128), divup(EHD, 64));
    dim3 gemmGrid100(divup(NN, 128), divup(THD, 64));
    // gate-first highway: gate GEMM independent of GCN
    k_tgemm<<<gemmGrid300, 256>>>(x, hw1_w, hw1_b, g->Y, NN, EHD, EHD, 1);   // 4 (profiled)
    k_gcnhw<<<NODE_BLKS, TPB>>>(x, g->Y, g->X);                               // 5
    k_tgemm<<<gemmGrid300, 256>>>(g->X, hw2_w, hw2_b, g->Y, NN, EHD, EHD, 1); // 6
    k_gcnhw<<<NODE_BLKS, TPB>>>(g->X, g->Y, g->Z);                            // 7
    k_tgemm<<<gemmGrid100, 256>>>(g->Z, tc1_w, tc1_b, g->S, NN, THD, EHD, 0); // 8

    k_relmean<<<NR, 256>>>(sr1_w, sr1_b);
    dim3 gemmGridR(divup(NR, 128), divup(EHD, 64), 3);
    k_sgemm3<<<gemmGridR, 256>>>(wr_w, wr_b, wr1_w, wr1_b, wr2_w, wr2_b);
    k_rowdot3<<<dim3(divup(NR * 32, TPB), 3), TPB>>>(ar1_w, ar2_w, ar3_w);

    k_rowdotZ<<<NODE_BLKS, TPB>>>(ah_w, g->xa);
    k_r2e<<<NODE_BLKS, TPB>>>(g->ER0, g->cR0, g->off_h, g->relh, at_w, nullptr, g->xa, nullptr, 0);
    k_r2e<<<NODE_BLKS, TPB>>>(g->ER1, g->cR1, g->off_t, g->relt, ah1_w, nullptr, g->xa, nullptr, 0);
    k_r2e<<<NODE_BLKS, TPB>>>(g->ER2, g->cR2, g->off_h, g->relh, ai_w, aj_w, g->xa, g->xj, 1);

    k_gatfinal<<<NODE_BLKS, TPB>>>(fc_w, fc_b, out);
    (void)in_sizes; (void)n_in; (void)out_size;
}

// round 10
// speedup vs baseline: 1.0726x; 1.0726x over previous
#include <cuda_runtime.h>
#include <cuda_bf16.h>
#include <stdint.h>
#include <math.h>

#define NN  50000
#define NE  250000
#define NEA 500000
#define NR  300
#define EHD 300
#define THD 100

// ------------------------------------------------------------------
// Static device scratch
// ------------------------------------------------------------------
struct Scratch {
    float X[(size_t)NN * EHD];
    float Y[(size_t)NN * EHD];   // gate buffer
    float Z[(size_t)NN * EHD];
    float S[(size_t)NN * THD];
    float RF[NR * EHD];
    float ER0[NR * EHD];
    float ER1[NR * EHD];
    float ER2[NR * EHD];
    float cR0[NR];
    float cR1[NR];
    float cR2[NR];
    float xa[NN];
    float xj[NN];
    float wj[NEA];
    int jall[NEA];
    int relh[NE];
    int relt[NE];
    int hr[NE];
    int tr[NE];
    int cnt_all[NN];
    int cnt_h[NN];
    int cnt_t[NN];
    int cnt_r[NR];
    int off_all[NN + 1];
    int off_h[NN + 1];
    int off_t[NN + 1];
    int off_r[NR + 1];
    int cur_all[NN];
    int cur_h[NN];
    int cur_t[NN];
    int cur_r[NR];
};
__device__ Scratch g_scr;

// ------------------------------------------------------------------
// helpers
// ------------------------------------------------------------------
__device__ __forceinline__ float lrelu01(float z) { return z > 0.f ? z : 0.01f * z; }

__device__ __forceinline__ float wredsum(float v) {
    #pragma unroll
    for (int o = 16; o > 0; o >>= 1) v += __shfl_xor_sync(0xffffffffu, v, o);
    return v;
}
__device__ __forceinline__ float wredmax(float v) {
    #pragma unroll
    for (int o = 16; o > 0; o >>= 1) v = fmaxf(v, __shfl_xor_sync(0xffffffffu, v, o));
    return v;
}

__device__ __forceinline__ float f2tf32f(float f) {
    uint32_t r;
    asm("cvt.rna.tf32.f32 %0, %1;" : "=r"(r) : "f"(f));
    return __uint_as_float(r);
}

static inline int divup(int a, int b) { return (a + b - 1) / b; }

// ------------------------------------------------------------------
// setup kernels
// ------------------------------------------------------------------
__global__ void k_hist4(const int* __restrict__ ii, const int* __restrict__ h,
                        const int* __restrict__ t, const int* __restrict__ rel) {
    int y = blockIdx.y;
    const int* keys; int n; int* cnt;
    if      (y == 0) { keys = ii;  n = NEA; cnt = g_scr.cnt_all; }
    else if (y == 1) { keys = h;   n = NE;  cnt = g_scr.cnt_h; }
    else if (y == 2) { keys = t;   n = NE;  cnt = g_scr.cnt_t; }
    else             { keys = rel; n = NE;  cnt = g_scr.cnt_r; }
    for (int i = blockIdx.x * blockDim.x + threadIdx.x; i < n; i += gridDim.x * blockDim.x)
        atomicAdd(&cnt[keys[i]], 1);
}

__global__ void k_scan4() {
    int y = blockIdx.x;
    const int* c; int n; int* off; int* cur;
    if      (y == 0) { c = g_scr.cnt_all; n = NN; off = g_scr.off_all; cur = g_scr.cur_all; }
    else if (y == 1) { c = g_scr.cnt_h;   n = NN; off = g_scr.off_h;   cur = g_scr.cur_h; }
    else if (y == 2) { c = g_scr.cnt_t;   n = NN; off = g_scr.off_t;   cur = g_scr.cur_t; }
    else             { c = g_scr.cnt_r;   n = NR; off = g_scr.off_r;   cur = g_scr.cur_r; }
    __shared__ int wsum[32];
    __shared__ int carrysh;
    int tid = threadIdx.x;
    int wid = tid >> 5, lane = tid & 31;
    if (tid == 0) carrysh = 0;
    __syncthreads();
    for (int base = 0; base < n; base += 1024) {
        int v = (base + tid < n) ? c[base + tid] : 0;
        int s = v;
        #pragma unroll
        for (int o = 1; o < 32; o <<= 1) {
            int t2 = __shfl_up_sync(0xffffffffu, s, o);
            if (lane >= o) s += t2;
        }
        if (lane == 31) wsum[wid] = s;
        __syncthreads();
        if (wid == 0) {
            int w = wsum[lane];
            #pragma unroll
            for (int o = 1; o < 32; o <<= 1) {
                int t2 = __shfl_up_sync(0xffffffffu, w, o);
                if (lane >= o) w += t2;
            }
            wsum[lane] = w;
        }
        __syncthreads();
        int woff = (wid > 0) ? wsum[wid - 1] : 0;
        int total = wsum[31];
        int ex = carrysh + woff + s - v;
        if (base + tid < n) { off[base + tid] = ex; cur[base + tid] = ex; }
        __syncthreads();
        if (tid == 0) carrysh += total;
        __syncthreads();
    }
    if (tid == 0) off[n] = carrysh;
}

__global__ void k_scatter4(const int* __restrict__ ii, const int* __restrict__ jjv,
                           const int* __restrict__ h, const int* __restrict__ t,
                           const int* __restrict__ rel) {
    int y = blockIdx.y;
    int stride = gridDim.x * blockDim.x;
    int i0 = blockIdx.x * blockDim.x + threadIdx.x;
    if (y == 0) {
        for (int i = i0; i < NEA; i += stride) {
            int pos = atomicAdd(&g_scr.cur_all[ii[i]], 1);
            int j = jjv[i];
            int d = g_scr.cnt_all[j];
            g_scr.jall[pos] = j;
            g_scr.wj[pos] = (d > 0) ? rsqrtf((float)d) : 0.0f;
        }
    } else if (y == 1) {
        for (int i = i0; i < NE; i += stride) {
            int pos = atomicAdd(&g_scr.cur_h[h[i]], 1);
            g_scr.relh[pos] = rel[i];
        }
    } else if (y == 2) {
        for (int i = i0; i < NE; i += stride) {
            int pos = atomicAdd(&g_scr.cur_t[t[i]], 1);
            g_scr.relt[pos] = rel[i];
        }
    } else {
        for (int i = i0; i < NE; i += stride) {
            int pos = atomicAdd(&g_scr.cur_r[rel[i]], 1);
            g_scr.hr[pos] = h[i];
            g_scr.tr[pos] = t[i];
        }
    }
}

// ------------------------------------------------------------------
// TF32 tensor-core GEMM with smem staging, double-buffered.
// OUT = C + bias (gate 0) | sigmoid(C + bias) (gate 1)
// BM=128, BN=64, BK=16, 256 threads; warp tile 32x32 (2 m16 x 4 n8).
// A smem stride 20 floats, B smem stride 72 floats (conflict-free frags).
// ------------------------------------------------------------------
#define MMA_TF32(c, a, b) \
    asm volatile("mma.sync.aligned.m16n8k8.row.col.f32.tf32.tf32.f32 " \
        "{%0,%1,%2,%3}, {%4,%5,%6,%7}, {%8,%9}, {%0,%1,%2,%3};" \
        : "+f"((c)[0]), "+f"((c)[1]), "+f"((c)[2]), "+f"((c)[3]) \
        : "r"((a)[0]), "r"((a)[1]), "r"((a)[2]), "r"((a)[3]), \
          "r"((b)[0]), "r"((b)[1]))

#define ASTR 20
#define BSTR 72

__global__ __launch_bounds__(256) void k_tgemm(
    const float* __restrict__ A, const float* __restrict__ W,
    const float* __restrict__ bias, float* __restrict__ OUT,
    int M, int N, int K, int gate) {
    __shared__ float sA[2][128 * ASTR];
    __shared__ float sB[2][16 * BSTR];

    const int mb = blockIdx.x * 128, nb = blockIdx.y * 64;
    const int tid = threadIdx.x;
    const int lane = tid & 31;
    const int wid = tid >> 5;
    const int warp_m = (wid & 3) * 32;
    const int warp_n = (wid >> 2) * 32;
    const int r = lane >> 2;     // 0..7
    const int c = lane & 3;      // 0..3

    float acc[2][4][4];
    #pragma unroll
    for (int mt = 0; mt < 2; mt++)
        #pragma unroll
        for (int nt = 0; nt < 4; nt++)
            #pragma unroll
            for (int q = 0; q < 4; q++) acc[mt][nt][q] = 0.f;

    // global-load assignments
    const int la_row = tid >> 1, la_cb = (tid & 1) * 8;   // A: 128 rows x 16 cols
    const int lb_row = tid >> 4, lb_cb = (tid & 15) * 4;  // B: 16 rows x 64 cols

    float ra[8], rb[4];
    auto load_tile = [&](int k0) {
        int gm = mb + la_row;
        #pragma unroll
        for (int q = 0; q < 8; q++) {
            int gk = k0 + la_cb + q;
            ra[q] = (gm < M && gk < K) ? __ldg(&A[(size_t)gm * K + gk]) : 0.f;
        }
        int gk = k0 + lb_row;
        #pragma unroll
        for (int q = 0; q < 4; q++) {
            int gn = nb + lb_cb + q;
            rb[q] = (gk < K && gn < N) ? __ldg(&W[(size_t)gk * N + gn]) : 0.f;
        }
    };
    auto store_tile = [&](int buf) {
        #pragma unroll
        for (int q = 0; q < 8; q++)
            sA[buf][la_row * ASTR + la_cb + q] = f2tf32f(ra[q]);
        #pragma unroll
        for (int q = 0; q < 4; q++)
            sB[buf][lb_row * BSTR + lb_cb + q] = f2tf32f(rb[q]);
    };

    int nk = (K + 15) / 16;
    load_tile(0);
    store_tile(0);
    __syncthreads();

    for (int ki = 0; ki < nk; ki++) {
        int buf = ki & 1;
        bool nxt = (ki + 1 < nk);
        if (nxt) load_tile((ki + 1) * 16);

        const float* a_base = sA[buf];
        const float* b_base = sB[buf];
        #pragma unroll
        for (int ks = 0; ks < 2; ks++) {
            int kk = ks * 8;
            uint32_t a[2][4], b[4][2];
            #pragma unroll
            for (int mt = 0; mt < 2; mt++) {
                int row0 = warp_m + mt * 16 + r;
                a[mt][0] = __float_as_uint(a_base[row0 * ASTR + kk + c]);
                a[mt][1] = __float_as_uint(a_base[(row0 + 8) * ASTR + kk + c]);
                a[mt][2] = __float_as_uint(a_base[row0 * ASTR + kk + c + 4]);
                a[mt][3] = __float_as_uint(a_base[(row0 + 8) * ASTR + kk + c + 4]);
            }
            #pragma unroll
            for (int nt = 0; nt < 4; nt++) {
                int col = warp_n + nt * 8 + r;
                b[nt][0] = __float_as_uint(b_base[(kk + c) * BSTR + col]);
                b[nt][1] = __float_as_uint(b_base[(kk + c + 4) * BSTR + col]);
            }
            #pragma unroll
            for (int mt = 0; mt < 2; mt++)
                #pragma unroll
                for (int nt = 0; nt < 4; nt++)
                    MMA_TF32(acc[mt][nt], a[mt], b[nt]);
        }
        if (nxt) store_tile(buf ^ 1);
        __syncthreads();
    }

    // epilogue
    const int erow = lane >> 2;
    const int ecol = (lane & 3) * 2;
    #pragma unroll
    for (int mt = 0; mt < 2; mt++) {
        #pragma unroll
        for (int nt = 0; nt < 4; nt++) {
            #pragma unroll
            for (int q = 0; q < 4; q++) {
                int gm = mb + warp_m + mt * 16 + erow + (q >> 1) * 8;
                int gc = nb + warp_n + nt * 8 + ecol + (q & 1);
                if (gm >= M || gc >= N) continue;
                float v = acc[mt][nt][q] + bias[gc];
                if (gate) v = 1.f / (1.f + expf(-v));
                OUT[(size_t)gm * N + gc] = v;
            }
        }
    }
}

// ------------------------------------------------------------------
// GCN + highway combine: xout = g*relu(dinv_n * gather) + (1-g)*xin_row
// ------------------------------------------------------------------
__global__ void k_gcnhw(const float* __restrict__ xin, const float* __restrict__ gate,
                        float* __restrict__ xout) {
    int n = (blockIdx.x * blockDim.x + threadIdx.x) >> 5;
    if (n >= NN) return;
    int lane = threadIdx.x & 31;
    int s0 = g_scr.off_all[n], s1 = g_scr.off_all[n + 1];
    bool l2ok = (64 + lane) < 75;
    float4 a0 = {0,0,0,0}, a1 = {0,0,0,0}, a2 = {0,0,0,0};
    for (int p = s0; p < s1; p++) {
        int j = g_scr.jall[p];
        float w = g_scr.wj[p];
        const float4* xr = (const float4*)(xin + (size_t)j * EHD);
        float4 v0 = __ldg(xr + lane);
        float4 v1 = __ldg(xr + 32 + lane);
        a0.x += w*v0.x; a0.y += w*v0.y; a0.z += w*v0.z; a0.w += w*v0.w;
        a1.x += w*v1.x; a1.y += w*v1.y; a1.z += w*v1.z; a1.w += w*v1.w;
        if (l2ok) {
            float4 v2 = __ldg(xr + 64 + lane);
            a2.x += w*v2.x; a2.y += w*v2.y; a2.z += w*v2.z; a2.w += w*v2.w;
        }
    }
    int dcnt = s1 - s0;
    float dn = (dcnt > 0) ? rsqrtf((float)dcnt) : 0.0f;
    const float4* xp = (const float4*)(xin + (size_t)n * EHD);
    const float4* gp = (const float4*)(gate + (size_t)n * EHD);
    float4* yr = (float4*)(xout + (size_t)n * EHD);
    float4 o, g4, p4;

    g4 = gp[lane]; p4 = xp[lane];
    o.x = g4.x * fmaxf(dn*a0.x, 0.f) + (1.f - g4.x) * p4.x;
    o.y = g4.y * fmaxf(dn*a0.y, 0.f) + (1.f - g4.y) * p4.y;
    o.z = g4.z * fmaxf(dn*a0.z, 0.f) + (1.f - g4.z) * p4.z;
    o.w = g4.w * fmaxf(dn*a0.w, 0.f) + (1.f - g4.w) * p4.w;
    yr[lane] = o;

    g4 = gp[32 + lane]; p4 = xp[32 + lane];
    o.x = g4.x * fmaxf(dn*a1.x, 0.f) + (1.f - g4.x) * p4.x;
    o.y = g4.y * fmaxf(dn*a1.y, 0.f) + (1.f - g4.y) * p4.y;
    o.z = g4.z * fmaxf(dn*a1.z, 0.f) + (1.f - g4.z) * p4.z;
    o.w = g4.w * fmaxf(dn*a1.w, 0.f) + (1.f - g4.w) * p4.w;
    yr[32 + lane] = o;

    if (l2ok) {
        g4 = gp[64 + lane]; p4 = xp[64 + lane];
        o.x = g4.x * fmaxf(dn*a2.x, 0.f) + (1.f - g4.x) * p4.x;
        o.y = g4.y * fmaxf(dn*a2.y, 0.f) + (1.f - g4.y) * p4.y;
        o.z = g4.z * fmaxf(dn*a2.z, 0.f) + (1.f - g4.z) * p4.z;
        o.w = g4.w * fmaxf(dn*a2.w, 0.f) + (1.f - g4.w) * p4.w;
        yr[64 + lane] = o;
    }
}

// ------------------------------------------------------------------
// per-relation means + rf2 + RF assembly
// ------------------------------------------------------------------
__global__ __launch_bounds__(256) void k_relmean(const float* __restrict__ sr1w,
                                                 const float* __restrict__ sr1b) {
    int r = blockIdx.x;
    int tid = threadIdx.x;
    __shared__ float acc[200];
    __shared__ float cat[200];
    if (tid < 200) acc[tid] = 0.f;
    __syncthreads();

    int wi = tid >> 5, lane = tid & 31;
    int s0 = g_scr.off_r[r], s1 = g_scr.off_r[r + 1];
    float4 lh = {0,0,0,0}, lt = {0,0,0,0};
    for (int p = s0 + wi; p < s1; p += 8) {
        int hh = g_scr.hr[p], tt = g_scr.tr[p];
        if (lane < 25) {
            const float4* sh_ = (const float4*)(g_scr.S + (size_t)hh * THD);
            const float4* st_ = (const float4*)(g_scr.S + (size_t)tt * THD);
            float4 v = __ldg(sh_ + lane);
            lh.x += v.x; lh.y += v.y; lh.z += v.z; lh.w += v.w;
            float4 u = __ldg(st_ + lane);
            lt.x += u.x; lt.y += u.y; lt.z += u.z; lt.w += u.w;
        }
    }
    if (lane < 25) {
        atomicAdd(&acc[4*lane+0], lh.x); atomicAdd(&acc[4*lane+1], lh.y);
        atomicAdd(&acc[4*lane+2], lh.z); atomicAdd(&acc[4*lane+3], lh.w);
        atomicAdd(&acc[100+4*lane+0], lt.x); atomicAdd(&acc[100+4*lane+1], lt.y);
        atomicAdd(&acc[100+4*lane+2], lt.z); atomicAdd(&acc[100+4*lane+3], lt.w);
    }
    __syncthreads();
    float c = fmaxf((float)(s1 - s0), 1.f);
    if (tid < 200) cat[tid] = acc[tid] / c;
    __syncthreads();
    if (tid < 100) {
        float a = sr1b[tid];
        #pragma unroll 4
        for (int k = 0; k < 200; k++) a += cat[k] * sr1w[k * 100 + tid];
        float* rf = g_scr.RF + (size_t)r * EHD;
        rf[tid]       = a;
        rf[100 + tid] = cat[tid];
        rf[200 + tid] = cat[100 + tid];
    }
}

// ------------------------------------------------------------------
// batched small sgemm: ER_k = RF @ wr_k + br_k
// ------------------------------------------------------------------
__global__ __launch_bounds__(256) void k_sgemm3(
    const float* __restrict__ W0, const float* __restrict__ b0,
    const float* __restrict__ W1, const float* __restrict__ b1,
    const float* __restrict__ W2, const float* __restrict__ b2) {
    const float* W; const float* bias; float* OUT;
    int z = blockIdx.z;
    if      (z == 0) { W = W0; bias = b0; OUT = g_scr.ER0; }
    else if (z == 1) { W = W1; bias = b1; OUT = g_scr.ER1; }
    else             { W = W2; bias = b2; OUT = g_scr.ER2; }
    const float* A = g_scr.RF;
    const int M = NR, N = EHD, K = EHD;

    __shared__ float As[16][128];
    __shared__ float Bs[16][64];
    int mb = blockIdx.x * 128, nb = blockIdx.y * 64;
    int tid = threadIdx.x;
    int ty = tid >> 4;
    int tx = tid & 15;
    float acc[8][4];
    #pragma unroll
    for (int i = 0; i < 8; i++)
        #pragma unroll
        for (int j = 0; j < 4; j++) acc[i][j] = 0.f;

    for (int k0 = 0; k0 < K; k0 += 16) {
        #pragma unroll
        for (int l = 0; l < 8; l++) {
            int idx = tid + l * 256;
            int arr = idx >> 4, ak = idx & 15;
            int gm = mb + arr, gk = k0 + ak;
            As[ak][arr] = (gm < M && gk < K) ? A[(size_t)gm * K + gk] : 0.f;
        }
        #pragma unroll
        for (int l = 0; l < 4; l++) {
            int idx = tid + l * 256;
            int bn = idx & 63, bk = idx >> 6;
            int gk = k0 + bk, gnn = nb + bn;
            Bs[bk][bn] = (gk < K && gnn < N) ? W[(size_t)gk * N + gnn] : 0.f;
        }
        __syncthreads();
        #pragma unroll
        for (int k = 0; k < 16; k++) {
            float a[8], b[4];
            #pragma unroll
            for (int i = 0; i < 8; i++) a[i] = As[k][ty * 8 + i];
            #pragma unroll
            for (int j = 0; j < 4; j++) b[j] = Bs[k][tx * 4 + j];
            #pragma unroll
            for (int i = 0; i < 8; i++)
                #pragma unroll
                for (int j = 0; j < 4; j++) acc[i][j] += a[i] * b[j];
        }
        __syncthreads();
    }
    #pragma unroll
    for (int i = 0; i < 8; i++) {
        int gm = mb + ty * 8 + i;
        if (gm >= M) continue;
        #pragma unroll
        for (int j = 0; j < 4; j++) {
            int gnn = nb + tx * 4 + j;
            if (gnn >= N) continue;
            OUT[(size_t)gm * N + gnn] = acc[i][j] + bias[gnn];
        }
    }
}

// ------------------------------------------------------------------
// batched rowdot over ER matrices: cR_k = ER_k . ar_k
// ------------------------------------------------------------------
__global__ void k_rowdot3(const float* __restrict__ v0, const float* __restrict__ v1,
                          const float* __restrict__ v2) {
    int y = blockIdx.y;
    const float* Mtx; const float* v; float* out;
    if      (y == 0) { Mtx = g_scr.ER0; v = v0; out = g_scr.cR0; }
    else if (y == 1) { Mtx = g_scr.ER1; v = v1; out = g_scr.cR1; }
    else             { Mtx = g_scr.ER2; v = v2; out = g_scr.cR2; }
    int r = (blockIdx.x * blockDim.x + threadIdx.x) >> 5;
    int lane = threadIdx.x & 31;
    if (r >= NR) return;
    const float4* mr = (const float4*)(Mtx + (size_t)r * EHD);
    const float4* vv = (const float4*)v;
    float s = 0.f;
    float4 a = mr[lane], b = vv[lane];
    s += a.x*b.x + a.y*b.y + a.z*b.z + a.w*b.w;
    a = mr[32 + lane]; b = vv[32 + lane];
    s += a.x*b.x + a.y*b.y + a.z*b.z + a.w*b.w;
    if (lane < 11) {
        a = mr[64 + lane]; b = vv[64 + lane];
        s += a.x*b.x + a.y*b.y + a.z*b.z + a.w*b.w;
    }
    s = wredsum(s);
    if (lane == 0) out[r] = s;
}

// ------------------------------------------------------------------
// rowdot over Z: xa = Z . v
// ------------------------------------------------------------------
__global__ void k_rowdotZ(const float* __restrict__ v, float* __restrict__ out) {
    int n = (blockIdx.x * blockDim.x + threadIdx.x) >> 5;
    int lane = threadIdx.x & 31;
    if (n >= NN) return;
    const float4* mr = (const float4*)(g_scr.Z + (size_t)n * EHD);
    const float4* vv = (const float4*)v;
    float s = 0.f;
    float4 a = mr[lane], b = vv[lane];
    s += a.x*b.x + a.y*b.y + a.z*b.z + a.w*b.w;
    a = mr[32 + lane]; b = vv[32 + lane];
    s += a.x*b.x + a.y*b.y + a.z*b.z + a.w*b.w;
    if (lane < 11) {
        a = mr[64 + lane]; b = vv[64 + lane];
        s += a.x*b.x + a.y*b.y + a.z*b.z + a.w*b.w;
    }
    s = wredsum(s);
    if (lane == 0) out[n] = s;
}

// ------------------------------------------------------------------
// fused r2e
// ------------------------------------------------------------------
__global__ void k_r2e(const float* __restrict__ ER, const float* __restrict__ cR,
                      const int* __restrict__ off, const int* __restrict__ rels,
                      const float* __restrict__ an1, const float* __restrict__ an2,
                      float* __restrict__ xa1, float* __restrict__ xj2, int dual) {
    int n = (blockIdx.x * blockDim.x + threadIdx.x) >> 5;
    if (n >= NN) return;
    int lane = threadIdx.x & 31;
    int s0 = off[n], s1 = off[n + 1];
    bool l2ok = (64 + lane) < 75;
    float4 a0 = {0,0,0,0}, a1 = {0,0,0,0}, a2 = {0,0,0,0};

    if (s1 > s0) {
        float xan = g_scr.xa[n];
        float m = -1e30f;
        for (int p = s0 + lane; p < s1; p += 32)
            m = fmaxf(m, lrelu01(xan + cR[rels[p]]));
        m = wredmax(m);
        float den = 0.f;
        for (int p = s0 + lane; p < s1; p += 32)
            den += expf(lrelu01(xan + cR[rels[p]]) - m);
        den = wredsum(den);
        float inv = 1.f / den;
        for (int p = s0; p < s1; p++) {
            int r = rels[p];
            float w = expf(lrelu01(xan + cR[r]) - m) * inv;
            const float4* er = (const float4*)(ER + (size_t)r * EHD);
            float4 v0 = __ldg(er + lane);
            float4 v1 = __ldg(er + 32 + lane);
            a0.x += w*v0.x; a0.y += w*v0.y; a0.z += w*v0.z; a0.w += w*v0.w;
            a1.x += w*v1.x; a1.y += w*v1.y; a1.z += w*v1.z; a1.w += w*v1.w;
            if (l2ok) {
                float4 v2 = __ldg(er + 64 + lane);
                a2.x += w*v2.x; a2.y += w*v2.y; a2.z += w*v2.z; a2.w += w*v2.w;
            }
        }
    }
    float4* xr = (float4*)(g_scr.Z + (size_t)n * EHD);
    const float4* w1 = (const float4*)an1;
    const float4* w2 = (const float4*)an2;
    float d1 = 0.f, d2 = 0.f;

    float4 v = xr[lane];
    v.x += fmaxf(a0.x, 0.f); v.y += fmaxf(a0.y, 0.f); v.z += fmaxf(a0.z, 0.f); v.w += fmaxf(a0.w, 0.f);
    xr[lane] = v;
    float4 q = w1[lane];
    d1 += v.x*q.x + v.y*q.y + v.z*q.z + v.w*q.w;
    if (dual) { float4 q2 = w2[lane]; d2 += v.x*q2.x + v.y*q2.y + v.z*q2.z + v.w*q2.w; }

    v = xr[32 + lane];
    v.x += fmaxf(a1.x, 0.f); v.y += fmaxf(a1.y, 0.f); v.z += fmaxf(a1.z, 0.f); v.w += fmaxf(a1.w, 0.f);
    xr[32 + lane] = v;
    q = w1[32 + lane];
    d1 += v.x*q.x + v.y*q.y + v.z*q.z + v.w*q.w;
    if (dual) { float4 q2 = w2[32 + lane]; d2 += v.x*q2.x + v.y*q2.y + v.z*q2.z + v.w*q2.w; }

    if (l2ok) {
        v = xr[64 + lane];
        v.x += fmaxf(a2.x, 0.f); v.y += fmaxf(a2.y, 0.f); v.z += fmaxf(a2.z, 0.f); v.w += fmaxf(a2.w, 0.f);
        xr[64 + lane] = v;
        q = w1[64 + lane];
        d1 += v.x*q.x + v.y*q.y + v.z*q.z + v.w*q.w;
        if (dual) { float4 q2 = w2[64 + lane]; d2 += v.x*q2.x + v.y*q2.y + v.z*q2.z + v.w*q2.w; }
    }
    d1 = wredsum(d1);
    if (lane == 0) xa1[n] = d1;
    if (dual) {
        d2 = wredsum(d2);
        if (lane == 0) xj2[n] = d2;
    }
}

// ------------------------------------------------------------------
// final GAT + fc output
// ------------------------------------------------------------------
__global__ void k_gatfinal(const float* __restrict__ fcw, const float* __restrict__ fcb,
                           float* __restrict__ outp) {
    int n = (blockIdx.x * blockDim.x + threadIdx.x) >> 5;
    if (n >= NN) return;
    int lane = threadIdx.x & 31;
    int s0 = g_scr.off_all[n], s1 = g_scr.off_all[n + 1];
    bool l2ok = (64 + lane) < 75;
    float4 a0 = {0,0,0,0}, a1 = {0,0,0,0}, a2 = {0,0,0,0};

    if (s1 > s0) {
        float xin = g_scr.xa[n];
        float m = -1e30f;
        for (int p = s0 + lane; p < s1; p += 32)
            m = fmaxf(m, lrelu01(xin + g_scr.xj[g_scr.jall[p]]));
        m = wredmax(m);
        float den = 0.f;
        for (int p = s0 + lane; p < s1; p += 32)
            den += expf(lrelu01(xin + g_scr.xj[g_scr.jall[p]]) - m);
        den = wredsum(den);
        float inv = 1.f / den;
        for (int p = s0; p < s1; p++) {
            int j = g_scr.jall[p];
            float w = expf(lrelu01(xin + g_scr.xj[j]) - m) * inv;
            const float4* xr = (const float4*)(g_scr.Z + (size_t)j * EHD);
            float4 v0 = __ldg(xr + lane);
            float4 v1 = __ldg(xr + 32 + lane);
            a0.x += w*v0.x; a0.y += w*v0.y; a0.z += w*v0.z; a0.w += w*v0.w;
            a1.x += w*v1.x; a1.y += w*v1.y; a1.z += w*v1.z; a1.w += w*v1.w;
            if (l2ok) {
                float4 v2 = __ldg(xr + 64 + lane);
                a2.x += w*v2.x; a2.y += w*v2.y; a2.z += w*v2.z; a2.w += w*v2.w;
            }
        }
    }
    const float4* xn = (const float4*)(g_scr.Z + (size_t)n * EHD);
    const float4* f1 = (const float4*)fcw;
    const float4* f2 = (const float4*)(fcw + EHD);
    float local = 0.f;

    float4 v = xn[lane], q = f1[lane], g = f2[lane];
    local += v.x*q.x + v.y*q.y + v.z*q.z + v.w*q.w;
    local += fmaxf(a0.x,0.f)*g.x + fmaxf(a0.y,0.f)*g.y + fmaxf(a0.z,0.f)*g.z + fmaxf(a0.w,0.f)*g.w;
    v = xn[32+lane]; q = f1[32+lane]; g = f2[32+lane];
    local += v.x*q.x + v.y*q.y + v.z*q.z + v.w*q.w;
    local += fmaxf(a1.x,0.f)*g.x + fmaxf(a1.y,0.f)*g.y + fmaxf(a1.z,0.f)*g.z + fmaxf(a1.w,0.f)*g.w;
    if (l2ok) {
        v = xn[64+lane]; q = f1[64+lane]; g = f2[64+lane];
        local += v.x*q.x + v.y*q.y + v.z*q.z + v.w*q.w;
        local += fmaxf(a2.x,0.f)*g.x + fmaxf(a2.y,0.f)*g.y + fmaxf(a2.z,0.f)*g.z + fmaxf(a2.w,0.f)*g.w;
    }
    local = wredsum(local);
    if (lane == 0) outp[n] = local + fcb[0];
}

// ------------------------------------------------------------------
// launcher
// ------------------------------------------------------------------
extern "C" void kernel_launch(void* const* d_in, const int* in_sizes, int n_in,
                              void* d_out, int out_size) {
    const float* x      = (const float*)d_in[0];
    const int*   ei     = (const int*)d_in[1];
    const int*   rel    = (const int*)d_in[2];
    const int*   eia    = (const int*)d_in[3];
    const float* hw1_w  = (const float*)d_in[5];
    const float* hw1_b  = (const float*)d_in[6];
    const float* hw2_w  = (const float*)d_in[7];
    const float* hw2_b  = (const float*)d_in[8];
    const float* tc1_w  = (const float*)d_in[9];
    const float* tc1_b  = (const float*)d_in[10];
    const float* sr1_w  = (const float*)d_in[11];
    const float* sr1_b  = (const float*)d_in[12];
    const float* wr_w   = (const float*)d_in[15];
    const float* wr_b   = (const float*)d_in[16];
    const float* wr1_w  = (const float*)d_in[17];
    const float* wr1_b  = (const float*)d_in[18];
    const float* wr2_w  = (const float*)d_in[19];
    const float* wr2_b  = (const float*)d_in[20];
    const float* ah_w   = (const float*)d_in[21];
    const float* ah1_w  = (const float*)d_in[22];
    const float* at_w   = (const float*)d_in[23];
    const float* ar1_w  = (const float*)d_in[24];
    const float* ar2_w  = (const float*)d_in[25];
    const float* ar3_w  = (const float*)d_in[26];
    const float* ai_w   = (const float*)d_in[27];
    const float* aj_w   = (const float*)d_in[28];
    const float* fc_w   = (const float*)d_in[29];
    const float* fc_b   = (const float*)d_in[30];
    float* out = (float*)d_out;

    const int* h  = ei;
    const int* t  = ei + NE;
    const int* jj = eia;
    const int* ii = eia + NEA;

    Scratch* g = nullptr;
    cudaGetSymbolAddress((void**)&g, g_scr);

    const int TPB = 256;
    const int NODE_BLKS = divup(NN * 32, TPB);

    cudaMemsetAsync(g->cnt_all, 0, (size_t)(3 * NN + NR) * sizeof(int));

    k_hist4<<<dim3(128, 4), TPB>>>(ii, h, t, rel);        // 1
    k_scan4<<<4, 1024>>>();                               // 2
    k_scatter4<<<dim3(512, 4), TPB>>>(ii, jj, h, t, rel); // 3

    dim3 gemmGrid300(divup(NN, 128), divup(EHD, 64));
    dim3 gemmGrid100(divup(NN, 128), divup(THD, 64));
    k_tgemm<<<gemmGrid300, 256>>>(x, hw1_w, hw1_b, g->Y, NN, EHD, EHD, 1);   // 4 (profiled)
    k_gcnhw<<<NODE_BLKS, TPB>>>(x, g->Y, g->X);
    k_tgemm<<<gemmGrid300, 256>>>(g->X, hw2_w, hw2_b, g->Y, NN, EHD, EHD, 1);
    k_gcnhw<<<NODE_BLKS, TPB>>>(g->X, g->Y, g->Z);
    k_tgemm<<<gemmGrid100, 256>>>(g->Z, tc1_w, tc1_b, g->S, NN, THD, EHD, 0);

    k_relmean<<<NR, 256>>>(sr1_w, sr1_b);
    dim3 gemmGridR(divup(NR, 128), divup(EHD, 64), 3);
    k_sgemm3<<<gemmGridR, 256>>>(wr_w, wr_b, wr1_w, wr1_b, wr2_w, wr2_b);
    k_rowdot3<<<dim3(divup(NR * 32, TPB), 3), TPB>>>(ar1_w, ar2_w, ar3_w);

    k_rowdotZ<<<NODE_BLKS, TPB>>>(ah_w, g->xa);
    k_r2e<<<NODE_BLKS, TPB>>>(g->ER0, g->cR0, g->off_h, g->relh, at_w, nullptr, g->xa, nullptr, 0);
    k_r2e<<<NODE_BLKS, TPB>>>(g->ER1, g->cR1, g->off_t, g->relt, ah1_w, nullptr, g->xa, nullptr, 0);
    k_r2e<<<NODE_BLKS, TPB>>>(g->ER2, g->cR2, g->off_h, g->relh, ai_w, aj_w, g->xa, g->xj, 1);

    k_gatfinal<<<NODE_BLKS, TPB>>>(fc_w, fc_b, out);
    (void)in_sizes; (void)n_in; (void)out_size;
}

// round 11
// speedup vs baseline: 1.0807x; 1.0076x over previous
#include <cuda_runtime.h>
#include <cuda_bf16.h>
#include <stdint.h>
#include <math.h>

#define NN  50000
#define NE  250000
#define NEA 500000
#define NR  300
#define EHD 300
#define THD 100

// ------------------------------------------------------------------
// Static device scratch
// ------------------------------------------------------------------
struct Scratch {
    float X[(size_t)NN * EHD];
    float Y[(size_t)NN * EHD];   // gate buffer
    float Z[(size_t)NN * EHD];
    float S[(size_t)NN * THD];
    float RF[NR * EHD];
    float ER0[NR * EHD];
    float ER1[NR * EHD];
    float ER2[NR * EHD];
    float cR0[NR];
    float cR1[NR];
    float cR2[NR];
    float xa[NN];
    float xj[NN];
    float wj[NEA];
    int jall[NEA];
    int relh[NE];
    int relt[NE];
    int hr[NE];
    int tr[NE];
    int cnt_all[NN];
    int cnt_h[NN];
    int cnt_t[NN];
    int cnt_r[NR];
    int off_all[NN + 1];
    int off_h[NN + 1];
    int off_t[NN + 1];
    int off_r[NR + 1];
    int cur_all[NN];
    int cur_h[NN];
    int cur_t[NN];
    int cur_r[NR];
};
__device__ Scratch g_scr;

// ------------------------------------------------------------------
// helpers
// ------------------------------------------------------------------
__device__ __forceinline__ float lrelu01(float z) { return z > 0.f ? z : 0.01f * z; }

__device__ __forceinline__ float wredsum(float v) {
    #pragma unroll
    for (int o = 16; o > 0; o >>= 1) v += __shfl_xor_sync(0xffffffffu, v, o);
    return v;
}
__device__ __forceinline__ float wredmax(float v) {
    #pragma unroll
    for (int o = 16; o > 0; o >>= 1) v = fmaxf(v, __shfl_xor_sync(0xffffffffu, v, o));
    return v;
}

__device__ __forceinline__ float f2tf32f(float f) {
    uint32_t r;
    asm("cvt.rna.tf32.f32 %0, %1;" : "=r"(r) : "f"(f));
    return __uint_as_float(r);
}

static inline int divup(int a, int b) { return (a + b - 1) / b; }

// ------------------------------------------------------------------
// setup kernels
// ------------------------------------------------------------------
__global__ void k_hist4(const int* __restrict__ ii, const int* __restrict__ h,
                        const int* __restrict__ t, const int* __restrict__ rel) {
    int y = blockIdx.y;
    const int* keys; int n; int* cnt;
    if      (y == 0) { keys = ii;  n = NEA; cnt = g_scr.cnt_all; }
    else if (y == 1) { keys = h;   n = NE;  cnt = g_scr.cnt_h; }
    else if (y == 2) { keys = t;   n = NE;  cnt = g_scr.cnt_t; }
    else             { keys = rel; n = NE;  cnt = g_scr.cnt_r; }
    for (int i = blockIdx.x * blockDim.x + threadIdx.x; i < n; i += gridDim.x * blockDim.x)
        atomicAdd(&cnt[keys[i]], 1);
}

__global__ void k_scan4() {
    int y = blockIdx.x;
    const int* c; int n; int* off; int* cur;
    if      (y == 0) { c = g_scr.cnt_all; n = NN; off = g_scr.off_all; cur = g_scr.cur_all; }
    else if (y == 1) { c = g_scr.cnt_h;   n = NN; off = g_scr.off_h;   cur = g_scr.cur_h; }
    else if (y == 2) { c = g_scr.cnt_t;   n = NN; off = g_scr.off_t;   cur = g_scr.cur_t; }
    else             { c = g_scr.cnt_r;   n = NR; off = g_scr.off_r;   cur = g_scr.cur_r; }
    __shared__ int wsum[32];
    __shared__ int carrysh;
    int tid = threadIdx.x;
    int wid = tid >> 5, lane = tid & 31;
    if (tid == 0) carrysh = 0;
    __syncthreads();
    for (int base = 0; base < n; base += 1024) {
        int v = (base + tid < n) ? c[base + tid] : 0;
        int s = v;
        #pragma unroll
        for (int o = 1; o < 32; o <<= 1) {
            int t2 = __shfl_up_sync(0xffffffffu, s, o);
            if (lane >= o) s += t2;
        }
        if (lane == 31) wsum[wid] = s;
        __syncthreads();
        if (wid == 0) {
            int w = wsum[lane];
            #pragma unroll
            for (int o = 1; o < 32; o <<= 1) {
                int t2 = __shfl_up_sync(0xffffffffu, w, o);
                if (lane >= o) w += t2;
            }
            wsum[lane] = w;
        }
        __syncthreads();
        int woff = (wid > 0) ? wsum[wid - 1] : 0;
        int total = wsum[31];
        int ex = carrysh + woff + s - v;
        if (base + tid < n) { off[base + tid] = ex; cur[base + tid] = ex; }
        __syncthreads();
        if (tid == 0) carrysh += total;
        __syncthreads();
    }
    if (tid == 0) off[n] = carrysh;
}

__global__ void k_scatter4(const int* __restrict__ ii, const int* __restrict__ jjv,
                           const int* __restrict__ h, const int* __restrict__ t,
                           const int* __restrict__ rel) {
    int y = blockIdx.y;
    int stride = gridDim.x * blockDim.x;
    int i0 = blockIdx.x * blockDim.x + threadIdx.x;
    if (y == 0) {
        for (int i = i0; i < NEA; i += stride) {
            int pos = atomicAdd(&g_scr.cur_all[ii[i]], 1);
            int j = jjv[i];
            int d = g_scr.cnt_all[j];
            g_scr.jall[pos] = j;
            g_scr.wj[pos] = (d > 0) ? rsqrtf((float)d) : 0.0f;
        }
    } else if (y == 1) {
        for (int i = i0; i < NE; i += stride) {
            int pos = atomicAdd(&g_scr.cur_h[h[i]], 1);
            g_scr.relh[pos] = rel[i];
        }
    } else if (y == 2) {
        for (int i = i0; i < NE; i += stride) {
            int pos = atomicAdd(&g_scr.cur_t[t[i]], 1);
            g_scr.relt[pos] = rel[i];
        }
    } else {
        for (int i = i0; i < NE; i += stride) {
            int pos = atomicAdd(&g_scr.cur_r[rel[i]], 1);
            g_scr.hr[pos] = h[i];
            g_scr.tr[pos] = t[i];
        }
    }
}

// ------------------------------------------------------------------
// TF32 tensor-core GEMM, smem staged, ldmatrix fragment loads.
// A smem: [128 rows][ASTR], B smem TRANSPOSED: [64 n][BSTR] (k-contig).
// OUT = C + bias (gate 0) | sigmoid(C + bias) (gate 1)
// BM=128, BN=64, BK=16, 256 threads; warp tile 32x32.
// ------------------------------------------------------------------
#define MMA_TF32(c, a, b0v, b1v) \
    asm volatile("mma.sync.aligned.m16n8k8.row.col.f32.tf32.tf32.f32 " \
        "{%0,%1,%2,%3}, {%4,%5,%6,%7}, {%8,%9}, {%0,%1,%2,%3};" \
        : "+f"((c)[0]), "+f"((c)[1]), "+f"((c)[2]), "+f"((c)[3]) \
        : "r"((a)[0]), "r"((a)[1]), "r"((a)[2]), "r"((a)[3]), \
          "r"(b0v), "r"(b1v))

#define LDSM_X4(r, p) \
    asm volatile("ldmatrix.sync.aligned.m8n8.x4.shared.b16 {%0,%1,%2,%3}, [%4];" \
        : "=r"((r)[0]), "=r"((r)[1]), "=r"((r)[2]), "=r"((r)[3]) : "r"(p))

#define ASTR 20
#define BSTR 20

__global__ __launch_bounds__(256) void k_tgemm(
    const float* __restrict__ A, const float* __restrict__ W,
    const float* __restrict__ bias, float* __restrict__ OUT,
    int M, int N, int K, int gate) {
    __shared__ float sA[2][128 * ASTR];
    __shared__ float sB[2][64 * BSTR];

    const int mb = blockIdx.x * 128, nb = blockIdx.y * 64;
    const int tid = threadIdx.x;
    const int lane = tid & 31;
    const int wid = tid >> 5;
    const int warp_m = (wid & 3) * 32;
    const int warp_n = (wid >> 2) * 32;

    float acc[2][4][4];
    #pragma unroll
    for (int mt = 0; mt < 2; mt++)
        #pragma unroll
        for (int nt = 0; nt < 4; nt++)
            #pragma unroll
            for (int q = 0; q < 4; q++) acc[mt][nt][q] = 0.f;

    // ldmatrix lane addressing: group g=lane>>3 -> (row +0/+8, k-seg 0/1)
    const int g4 = lane >> 3;
    const int rsel = (g4 & 1) * 8 + (lane & 7);
    const int segf = (g4 >> 1) * 4;          // float offset of 16B segment
    uint32_t pA[2], pB[2];
    #pragma unroll
    for (int mt = 0; mt < 2; mt++)
        pA[mt] = (uint32_t)__cvta_generic_to_shared(
            &sA[0][(warp_m + mt * 16 + rsel) * ASTR + segf]);
    #pragma unroll
    for (int np = 0; np < 2; np++)
        pB[np] = (uint32_t)__cvta_generic_to_shared(
            &sB[0][(warp_n + np * 16 + rsel) * BSTR + segf]);
    const uint32_t ABUF = 128u * ASTR * 4u;
    const uint32_t BBUF = 64u * BSTR * 4u;

    // global-load assignments
    const int la_row = tid >> 1, la_cb = (tid & 1) * 8;   // A: 128r x 16k
    const int lb_n = tid & 63, lb_kq = (tid >> 6) * 4;    // B: 64n x 16k (n-major)

    float ra[8], rb[4];
    auto load_tile = [&](int k0) {
        int gm = mb + la_row;
        #pragma unroll
        for (int q = 0; q < 8; q++) {
            int gk = k0 + la_cb + q;
            ra[q] = (gm < M && gk < K) ? __ldg(&A[(size_t)gm * K + gk]) : 0.f;
        }
        int gn = nb + lb_n;
        #pragma unroll
        for (int q = 0; q < 4; q++) {
            int gk = k0 + lb_kq + q;
            rb[q] = (gk < K && gn < N) ? __ldg(&W[(size_t)gk * N + gn]) : 0.f;
        }
    };
    auto store_tile = [&](int buf) {
        #pragma unroll
        for (int q = 0; q < 8; q++)
            sA[buf][la_row * ASTR + la_cb + q] = f2tf32f(ra[q]);
        float4 v;
        v.x = f2tf32f(rb[0]); v.y = f2tf32f(rb[1]);
        v.z = f2tf32f(rb[2]); v.w = f2tf32f(rb[3]);
        *(float4*)&sB[buf][lb_n * BSTR + lb_kq] = v;   // transposed: [n][k]
    };

    int nk = (K + 15) / 16;
    load_tile(0);
    store_tile(0);
    __syncthreads();

    for (int ki = 0; ki < nk; ki++) {
        int buf = ki & 1;
        bool nxt = (ki + 1 < nk);
        if (nxt) load_tile((ki + 1) * 16);

        uint32_t aoff = buf * ABUF, boff = buf * BBUF;
        #pragma unroll
        for (int ks = 0; ks < 2; ks++) {
            uint32_t a[2][4], bfrag[2][4];
            #pragma unroll
            for (int mt = 0; mt < 2; mt++)
                LDSM_X4(a[mt], pA[mt] + aoff + ks * 32);
            #pragma unroll
            for (int np = 0; np < 2; np++)
                LDSM_X4(bfrag[np], pB[np] + boff + ks * 32);
            // bfrag[np]: r0/r2 = (b0,b1) of n8 tile np*2; r1/r3 = of np*2+1
            #pragma unroll
            for (int mt = 0; mt < 2; mt++)
                #pragma unroll
                for (int np = 0; np < 2; np++) {
                    MMA_TF32(acc[mt][np * 2],     a[mt], bfrag[np][0], bfrag[np][2]);
                    MMA_TF32(acc[mt][np * 2 + 1], a[mt], bfrag[np][1], bfrag[np][3]);
                }
        }
        if (nxt) store_tile(buf ^ 1);
        __syncthreads();
    }

    // epilogue
    const int erow = lane >> 2;
    const int ecol = (lane & 3) * 2;
    #pragma unroll
    for (int mt = 0; mt < 2; mt++) {
        #pragma unroll
        for (int nt = 0; nt < 4; nt++) {
            #pragma unroll
            for (int q = 0; q < 4; q++) {
                int gm = mb + warp_m + mt * 16 + erow + (q >> 1) * 8;
                int gc = nb + warp_n + nt * 8 + ecol + (q & 1);
                if (gm >= M || gc >= N) continue;
                float v = acc[mt][nt][q] + bias[gc];
                if (gate) v = 1.f / (1.f + expf(-v));
                OUT[(size_t)gm * N + gc] = v;
            }
        }
    }
}

// ------------------------------------------------------------------
// GCN + highway combine: xout = g*relu(dinv_n * gather) + (1-g)*xin_row
// ------------------------------------------------------------------
__global__ void k_gcnhw(const float* __restrict__ xin, const float* __restrict__ gate,
                        float* __restrict__ xout) {
    int n = (blockIdx.x * blockDim.x + threadIdx.x) >> 5;
    if (n >= NN) return;
    int lane = threadIdx.x & 31;
    int s0 = g_scr.off_all[n], s1 = g_scr.off_all[n + 1];
    bool l2ok = (64 + lane) < 75;
    float4 a0 = {0,0,0,0}, a1 = {0,0,0,0}, a2 = {0,0,0,0};
    for (int p = s0; p < s1; p++) {
        int j = g_scr.jall[p];
        float w = g_scr.wj[p];
        const float4* xr = (const float4*)(xin + (size_t)j * EHD);
        float4 v0 = __ldg(xr + lane);
        float4 v1 = __ldg(xr + 32 + lane);
        a0.x += w*v0.x; a0.y += w*v0.y; a0.z += w*v0.z; a0.w += w*v0.w;
        a1.x += w*v1.x; a1.y += w*v1.y; a1.z += w*v1.z; a1.w += w*v1.w;
        if (l2ok) {
            float4 v2 = __ldg(xr + 64 + lane);
            a2.x += w*v2.x; a2.y += w*v2.y; a2.z += w*v2.z; a2.w += w*v2.w;
        }
    }
    int dcnt = s1 - s0;
    float dn = (dcnt > 0) ? rsqrtf((float)dcnt) : 0.0f;
    const float4* xp = (const float4*)(xin + (size_t)n * EHD);
    const float4* gp = (const float4*)(gate + (size_t)n * EHD);
    float4* yr = (float4*)(xout + (size_t)n * EHD);
    float4 o, g4, p4;

    g4 = gp[lane]; p4 = xp[lane];
    o.x = g4.x * fmaxf(dn*a0.x, 0.f) + (1.f - g4.x) * p4.x;
    o.y = g4.y * fmaxf(dn*a0.y, 0.f) + (1.f - g4.y) * p4.y;
    o.z = g4.z * fmaxf(dn*a0.z, 0.f) + (1.f - g4.z) * p4.z;
    o.w = g4.w * fmaxf(dn*a0.w, 0.f) + (1.f - g4.w) * p4.w;
    yr[lane] = o;

    g4 = gp[32 + lane]; p4 = xp[32 + lane];
    o.x = g4.x * fmaxf(dn*a1.x, 0.f) + (1.f - g4.x) * p4.x;
    o.y = g4.y * fmaxf(dn*a1.y, 0.f) + (1.f - g4.y) * p4.y;
    o.z = g4.z * fmaxf(dn*a1.z, 0.f) + (1.f - g4.z) * p4.z;
    o.w = g4.w * fmaxf(dn*a1.w, 0.f) + (1.f - g4.w) * p4.w;
    yr[32 + lane] = o;

    if (l2ok) {
        g4 = gp[64 + lane]; p4 = xp[64 + lane];
        o.x = g4.x * fmaxf(dn*a2.x, 0.f) + (1.f - g4.x) * p4.x;
        o.y = g4.y * fmaxf(dn*a2.y, 0.f) + (1.f - g4.y) * p4.y;
        o.z = g4.z * fmaxf(dn*a2.z, 0.f) + (1.f - g4.z) * p4.z;
        o.w = g4.w * fmaxf(dn*a2.w, 0.f) + (1.f - g4.w) * p4.w;
        yr[64 + lane] = o;
    }
}

// ------------------------------------------------------------------
// per-relation means + rf2 + RF assembly
// ------------------------------------------------------------------
__global__ __launch_bounds__(256) void k_relmean(const float* __restrict__ sr1w,
                                                 const float* __restrict__ sr1b) {
    int r = blockIdx.x;
    int tid = threadIdx.x;
    __shared__ float acc[200];
    __shared__ float cat[200];
    if (tid < 200) acc[tid] = 0.f;
    __syncthreads();

    int wi = tid >> 5, lane = tid & 31;
    int s0 = g_scr.off_r[r], s1 = g_scr.off_r[r + 1];
    float4 lh = {0,0,0,0}, lt = {0,0,0,0};
    for (int p = s0 + wi; p < s1; p += 8) {
        int hh = g_scr.hr[p], tt = g_scr.tr[p];
        if (lane < 25) {
            const float4* sh_ = (const float4*)(g_scr.S + (size_t)hh * THD);
            const float4* st_ = (const float4*)(g_scr.S + (size_t)tt * THD);
            float4 v = __ldg(sh_ + lane);
            lh.x += v.x; lh.y += v.y; lh.z += v.z; lh.w += v.w;
            float4 u = __ldg(st_ + lane);
            lt.x += u.x; lt.y += u.y; lt.z += u.z; lt.w += u.w;
        }
    }
    if (lane < 25) {
        atomicAdd(&acc[4*lane+0], lh.x); atomicAdd(&acc[4*lane+1], lh.y);
        atomicAdd(&acc[4*lane+2], lh.z); atomicAdd(&acc[4*lane+3], lh.w);
        atomicAdd(&acc[100+4*lane+0], lt.x); atomicAdd(&acc[100+4*lane+1], lt.y);
        atomicAdd(&acc[100+4*lane+2], lt.z); atomicAdd(&acc[100+4*lane+3], lt.w);
    }
    __syncthreads();
    float c = fmaxf((float)(s1 - s0), 1.f);
    if (tid < 200) cat[tid] = acc[tid] / c;
    __syncthreads();
    if (tid < 100) {
        float a = sr1b[tid];
        #pragma unroll 4
        for (int k = 0; k < 200; k++) a += cat[k] * sr1w[k * 100 + tid];
        float* rf = g_scr.RF + (size_t)r * EHD;
        rf[tid]       = a;
        rf[100 + tid] = cat[tid];
        rf[200 + tid] = cat[100 + tid];
    }
}

// ------------------------------------------------------------------
// batched small sgemm: ER_k = RF @ wr_k + br_k
// ------------------------------------------------------------------
__global__ __launch_bounds__(256) void k_sgemm3(
    const float* __restrict__ W0, const float* __restrict__ b0,
    const float* __restrict__ W1, const float* __restrict__ b1,
    const float* __restrict__ W2, const float* __restrict__ b2) {
    const float* W; const float* bias; float* OUT;
    int z = blockIdx.z;
    if      (z == 0) { W = W0; bias = b0; OUT = g_scr.ER0; }
    else if (z == 1) { W = W1; bias = b1; OUT = g_scr.ER1; }
    else             { W = W2; bias = b2; OUT = g_scr.ER2; }
    const float* A = g_scr.RF;
    const int M = NR, N = EHD, K = EHD;

    __shared__ float As[16][128];
    __shared__ float Bs[16][64];
    int mb = blockIdx.x * 128, nb = blockIdx.y * 64;
    int tid = threadIdx.x;
    int ty = tid >> 4;
    int tx = tid & 15;
    float acc[8][4];
    #pragma unroll
    for (int i = 0; i < 8; i++)
        #pragma unroll
        for (int j = 0; j < 4; j++) acc[i][j] = 0.f;

    for (int k0 = 0; k0 < K; k0 += 16) {
        #pragma unroll
        for (int l = 0; l < 8; l++) {
            int idx = tid + l * 256;
            int arr = idx >> 4, ak = idx & 15;
            int gm = mb + arr, gk = k0 + ak;
            As[ak][arr] = (gm < M && gk < K) ? A[(size_t)gm * K + gk] : 0.f;
        }
        #pragma unroll
        for (int l = 0; l < 4; l++) {
            int idx = tid + l * 256;
            int bn = idx & 63, bk = idx >> 6;
            int gk = k0 + bk, gnn = nb + bn;
            Bs[bk][bn] = (gk < K && gnn < N) ? W[(size_t)gk * N + gnn] : 0.f;
        }
        __syncthreads();
        #pragma unroll
        for (int k = 0; k < 16; k++) {
            float a[8], b[4];
            #pragma unroll
            for (int i = 0; i < 8; i++) a[i] = As[k][ty * 8 + i];
            #pragma unroll
            for (int j = 0; j < 4; j++) b[j] = Bs[k][tx * 4 + j];
            #pragma unroll
            for (int i = 0; i < 8; i++)
                #pragma unroll
                for (int j = 0; j < 4; j++) acc[i][j] += a[i] * b[j];
        }
        __syncthreads();
    }
    #pragma unroll
    for (int i = 0; i < 8; i++) {
        int gm = mb + ty * 8 + i;
        if (gm >= M) continue;
        #pragma unroll
        for (int j = 0; j < 4; j++) {
            int gnn = nb + tx * 4 + j;
            if (gnn >= N) continue;
            OUT[(size_t)gm * N + gnn] = acc[i][j] + bias[gnn];
        }
    }
}

// ------------------------------------------------------------------
// batched rowdot over ER matrices: cR_k = ER_k . ar_k
// ------------------------------------------------------------------
__global__ void k_rowdot3(const float* __restrict__ v0, const float* __restrict__ v1,
                          const float* __restrict__ v2) {
    int y = blockIdx.y;
    const float* Mtx; const float* v; float* out;
    if      (y == 0) { Mtx = g_scr.ER0; v = v0; out = g_scr.cR0; }
    else if (y == 1) { Mtx = g_scr.ER1; v = v1; out = g_scr.cR1; }
    else             { Mtx = g_scr.ER2; v = v2; out = g_scr.cR2; }
    int r = (blockIdx.x * blockDim.x + threadIdx.x) >> 5;
    int lane = threadIdx.x & 31;
    if (r >= NR) return;
    const float4* mr = (const float4*)(Mtx + (size_t)r * EHD);
    const float4* vv = (const float4*)v;
    float s = 0.f;
    float4 a = mr[lane], b = vv[lane];
    s += a.x*b.x + a.y*b.y + a.z*b.z + a.w*b.w;
    a = mr[32 + lane]; b = vv[32 + lane];
    s += a.x*b.x + a.y*b.y + a.z*b.z + a.w*b.w;
    if (lane < 11) {
        a = mr[64 + lane]; b = vv[64 + lane];
        s += a.x*b.x + a.y*b.y + a.z*b.z + a.w*b.w;
    }
    s = wredsum(s);
    if (lane == 0) out[r] = s;
}

// ------------------------------------------------------------------
// rowdot over Z: xa = Z . v
// ------------------------------------------------------------------
__global__ void k_rowdotZ(const float* __restrict__ v, float* __restrict__ out) {
    int n = (blockIdx.x * blockDim.x + threadIdx.x) >> 5;
    int lane = threadIdx.x & 31;
    if (n >= NN) return;
    const float4* mr = (const float4*)(g_scr.Z + (size_t)n * EHD);
    const float4* vv = (const float4*)v;
    float s = 0.f;
    float4 a = mr[lane], b = vv[lane];
    s += a.x*b.x + a.y*b.y + a.z*b.z + a.w*b.w;
    a = mr[32 + lane]; b = vv[32 + lane];
    s += a.x*b.x + a.y*b.y + a.z*b.z + a.w*b.w;
    if (lane < 11) {
        a = mr[64 + lane]; b = vv[64 + lane];
        s += a.x*b.x + a.y*b.y + a.z*b.z + a.w*b.w;
    }
    s = wredsum(s);
    if (lane == 0) out[n] = s;
}

// ------------------------------------------------------------------
// fused r2e
// ------------------------------------------------------------------
__global__ void k_r2e(const float* __restrict__ ER, const float* __restrict__ cR,
                      const int* __restrict__ off, const int* __restrict__ rels,
                      const float* __restrict__ an1, const float* __restrict__ an2,
                      float* __restrict__ xa1, float* __restrict__ xj2, int dual) {
    int n = (blockIdx.x * blockDim.x + threadIdx.x) >> 5;
    if (n >= NN) return;
    int lane = threadIdx.x & 31;
    int s0 = off[n], s1 = off[n + 1];
    bool l2ok = (64 + lane) < 75;
    float4 a0 = {0,0,0,0}, a1 = {0,0,0,0}, a2 = {0,0,0,0};

    if (s1 > s0) {
        float xan = g_scr.xa[n];
        float m = -1e30f;
        for (int p = s0 + lane; p < s1; p += 32)
            m = fmaxf(m, lrelu01(xan + cR[rels[p]]));
        m = wredmax(m);
        float den = 0.f;
        for (int p = s0 + lane; p < s1; p += 32)
            den += expf(lrelu01(xan + cR[rels[p]]) - m);
        den = wredsum(den);
        float inv = 1.f / den;
        for (int p = s0; p < s1; p++) {
            int r = rels[p];
            float w = expf(lrelu01(xan + cR[r]) - m) * inv;
            const float4* er = (const float4*)(ER + (size_t)r * EHD);
            float4 v0 = __ldg(er + lane);
            float4 v1 = __ldg(er + 32 + lane);
            a0.x += w*v0.x; a0.y += w*v0.y; a0.z += w*v0.z; a0.w += w*v0.w;
            a1.x += w*v1.x; a1.y += w*v1.y; a1.z += w*v1.z; a1.w += w*v1.w;
            if (l2ok) {
                float4 v2 = __ldg(er + 64 + lane);
                a2.x += w*v2.x; a2.y += w*v2.y; a2.z += w*v2.z; a2.w += w*v2.w;
            }
        }
    }
    float4* xr = (float4*)(g_scr.Z + (size_t)n * EHD);
    const float4* w1 = (const float4*)an1;
    const float4* w2 = (const float4*)an2;
    float d1 = 0.f, d2 = 0.f;

    float4 v = xr[lane];
    v.x += fmaxf(a0.x, 0.f); v.y += fmaxf(a0.y, 0.f); v.z += fmaxf(a0.z, 0.f); v.w += fmaxf(a0.w, 0.f);
    xr[lane] = v;
    float4 q = w1[lane];
    d1 += v.x*q.x + v.y*q.y + v.z*q.z + v.w*q.w;
    if (dual) { float4 q2 = w2[lane]; d2 += v.x*q2.x + v.y*q2.y + v.z*q2.z + v.w*q2.w; }

    v = xr[32 + lane];
    v.x += fmaxf(a1.x, 0.f); v.y += fmaxf(a1.y, 0.f); v.z += fmaxf(a1.z, 0.f); v.w += fmaxf(a1.w, 0.f);
    xr[32 + lane] = v;
    q = w1[32 + lane];
    d1 += v.x*q.x + v.y*q.y + v.z*q.z + v.w*q.w;
    if (dual) { float4 q2 = w2[32 + lane]; d2 += v.x*q2.x + v.y*q2.y + v.z*q2.z + v.w*q2.w; }

    if (l2ok) {
        v = xr[64 + lane];
        v.x += fmaxf(a2.x, 0.f); v.y += fmaxf(a2.y, 0.f); v.z += fmaxf(a2.z, 0.f); v.w += fmaxf(a2.w, 0.f);
        xr[64 + lane] = v;
        q = w1[64 + lane];
        d1 += v.x*q.x + v.y*q.y + v.z*q.z + v.w*q.w;
        if (dual) { float4 q2 = w2[64 + lane]; d2 += v.x*q2.x + v.y*q2.y + v.z*q2.z + v.w*q2.w; }
    }
    d1 = wredsum(d1);
    if (lane == 0) xa1[n] = d1;
    if (dual) {
        d2 = wredsum(d2);
        if (lane == 0) xj2[n] = d2;
    }
}

// ------------------------------------------------------------------
// final GAT + fc output
// ------------------------------------------------------------------
__global__ void k_gatfinal(const float* __restrict__ fcw, const float* __restrict__ fcb,
                           float* __restrict__ outp) {
    int n = (blockIdx.x * blockDim.x + threadIdx.x) >> 5;
    if (n >= NN) return;
    int lane = threadIdx.x & 31;
    int s0 = g_scr.off_all[n], s1 = g_scr.off_all[n + 1];
    bool l2ok = (64 + lane) < 75;
    float4 a0 = {0,0,0,0}, a1 = {0,0,0,0}, a2 = {0,0,0,0};

    if (s1 > s0) {
        float xin = g_scr.xa[n];
        float m = -1e30f;
        for (int p = s0 + lane; p < s1; p += 32)
            m = fmaxf(m, lrelu01(xin + g_scr.xj[g_scr.jall[p]]));
        m = wredmax(m);
        float den = 0.f;
        for (int p = s0 + lane; p < s1; p += 32)
            den += expf(lrelu01(xin + g_scr.xj[g_scr.jall[p]]) - m);
        den = wredsum(den);
        float inv = 1.f / den;
        for (int p = s0; p < s1; p++) {
            int j = g_scr.jall[p];
            float w = expf(lrelu01(xin + g_scr.xj[j]) - m) * inv;
            const float4* xr = (const float4*)(g_scr.Z + (size_t)j * EHD);
            float4 v0 = __ldg(xr + lane);
            float4 v1 = __ldg(xr + 32 + lane);
            a0.x += w*v0.x; a0.y += w*v0.y; a0.z += w*v0.z; a0.w += w*v0.w;
            a1.x += w*v1.x; a1.y += w*v1.y; a1.z += w*v1.z; a1.w += w*v1.w;
            if (l2ok) {
                float4 v2 = __ldg(xr + 64 + lane);
                a2.x += w*v2.x; a2.y += w*v2.y; a2.z += w*v2.z; a2.w += w*v2.w;
            }
        }
    }
    const float4* xn = (const float4*)(g_scr.Z + (size_t)n * EHD);
    const float4* f1 = (const float4*)fcw;
    const float4* f2 = (const float4*)(fcw + EHD);
    float local = 0.f;

    float4 v = xn[lane], q = f1[lane], g = f2[lane];
    local += v.x*q.x + v.y*q.y + v.z*q.z + v.w*q.w;
    local += fmaxf(a0.x,0.f)*g.x + fmaxf(a0.y,0.f)*g.y + fmaxf(a0.z,0.f)*g.z + fmaxf(a0.w,0.f)*g.w;
    v = xn[32+lane]; q = f1[32+lane]; g = f2[32+lane];
    local += v.x*q.x + v.y*q.y + v.z*q.z + v.w*q.w;
    local += fmaxf(a1.x,0.f)*g.x + fmaxf(a1.y,0.f)*g.y + fmaxf(a1.z,0.f)*g.z + fmaxf(a1.w,0.f)*g.w;
    if (l2ok) {
        v = xn[64+lane]; q = f1[64+lane]; g = f2[64+lane];
        local += v.x*q.x + v.y*q.y + v.z*q.z + v.w*q.w;
        local += fmaxf(a2.x,0.f)*g.x + fmaxf(a2.y,0.f)*g.y + fmaxf(a2.z,0.f)*g.z + fmaxf(a2.w,0.f)*g.w;
    }
    local = wredsum(local);
    if (lane == 0) outp[n] = local + fcb[0];
}

// ------------------------------------------------------------------
// launcher
// ------------------------------------------------------------------
extern "C" void kernel_launch(void* const* d_in, const int* in_sizes, int n_in,
                              void* d_out, int out_size) {
    const float* x      = (const float*)d_in[0];
    const int*   ei     = (const int*)d_in[1];
    const int*   rel    = (const int*)d_in[2];
    const int*   eia    = (const int*)d_in[3];
    const float* hw1_w  = (const float*)d_in[5];
    const float* hw1_b  = (const float*)d_in[6];
    const float* hw2_w  = (const float*)d_in[7];
    const float* hw2_b  = (const float*)d_in[8];
    const float* tc1_w  = (const float*)d_in[9];
    const float* tc1_b  = (const float*)d_in[10];
    const float* sr1_w  = (const float*)d_in[11];
    const float* sr1_b  = (const float*)d_in[12];
    const float* wr_w   = (const float*)d_in[15];
    const float* wr_b   = (const float*)d_in[16];
    const float* wr1_w  = (const float*)d_in[17];
    const float* wr1_b  = (const float*)d_in[18];
    const float* wr2_w  = (const float*)d_in[19];
    const float* wr2_b  = (const float*)d_in[20];
    const float* ah_w   = (const float*)d_in[21];
    const float* ah1_w  = (const float*)d_in[22];
    const float* at_w   = (const float*)d_in[23];
    const float* ar1_w  = (const float*)d_in[24];
    const float* ar2_w  = (const float*)d_in[25];
    const float* ar3_w  = (const float*)d_in[26];
    const float* ai_w   = (const float*)d_in[27];
    const float* aj_w   = (const float*)d_in[28];
    const float* fc_w   = (const float*)d_in[29];
    const float* fc_b   = (const float*)d_in[30];
    float* out = (float*)d_out;

    const int* h  = ei;
    const int* t  = ei + NE;
    const int* jj = eia;
    const int* ii = eia + NEA;

    Scratch* g = nullptr;
    cudaGetSymbolAddress((void**)&g, g_scr);

    const int TPB = 256;
    const int NODE_BLKS = divup(NN * 32, TPB);

    cudaMemsetAsync(g->cnt_all, 0, (size_t)(3 * NN + NR) * sizeof(int));

    k_hist4<<<dim3(128, 4), TPB>>>(ii, h, t, rel);        // 1
    k_scan4<<<4, 1024>>>();                               // 2
    k_scatter4<<<dim3(512, 4), TPB>>>(ii, jj, h, t, rel); // 3

    dim3 gemmGrid300(divup(NN, 128), divup(EHD, 64));
    dim3 gemmGrid100(divup(NN, 128), divup(THD, 64));
    k_tgemm<<<gemmGrid300, 256>>>(x, hw1_w, hw1_b, g->Y, NN, EHD, EHD, 1);   // 4 (profiled)
    k_gcnhw<<<NODE_BLKS, TPB>>>(x, g->Y, g->X);
    k_tgemm<<<gemmGrid300, 256>>>(g->X, hw2_w, hw2_b, g->Y, NN, EHD, EHD, 1);
    k_gcnhw<<<NODE_BLKS, TPB>>>(g->X, g->Y, g->Z);
    k_tgemm<<<gemmGrid100, 256>>>(g->Z, tc1_w, tc1_b, g->S, NN, THD, EHD, 0);

    k_relmean<<<NR, 256>>>(sr1_w, sr1_b);
    dim3 gemmGridR(divup(NR, 128), divup(EHD, 64), 3);
    k_sgemm3<<<gemmGridR, 256>>>(wr_w, wr_b, wr1_w, wr1_b, wr2_w, wr2_b);
    k_rowdot3<<<dim3(divup(NR * 32, TPB), 3), TPB>>>(ar1_w, ar2_w, ar3_w);

    k_rowdotZ<<<NODE_BLKS, TPB>>>(ah_w, g->xa);
    k_r2e<<<NODE_BLKS, TPB>>>(g->ER0, g->cR0, g->off_h, g->relh, at_w, nullptr, g->xa, nullptr, 0);
    k_r2e<<<NODE_BLKS, TPB>>>(g->ER1, g->cR1, g->off_t, g->relt, ah1_w, nullptr, g->xa, nullptr, 0);
    k_r2e<<<NODE_BLKS, TPB>>>(g->ER2, g->cR2, g->off_h, g->relh, ai_w, aj_w, g->xa, g->xj, 1);

    k_gatfinal<<<NODE_BLKS, TPB>>>(fc_w, fc_b, out);
    (void)in_sizes; (void)n_in; (void)out_size;
}

// round 12
// speedup vs baseline: 1.2933x; 1.1967x over previous
#include <cuda_runtime.h>
#include <cuda_bf16.h>
#include <stdint.h>
#include <math.h>

#define NN  50000
#define NE  250000
#define NEA 500000
#define NR  300
#define EHD 300
#define THD 100

// ------------------------------------------------------------------
// Static device scratch
// ------------------------------------------------------------------
struct Scratch {
    float X[(size_t)NN * EHD];
    float Y[(size_t)NN * EHD];   // gate buffer
    float Z[(size_t)NN * EHD];
    float S[(size_t)NN * THD];
    float RF[NR * EHD];
    float ER0[NR * EHD];
    float ER1[NR * EHD];
    float ER2[NR * EHD];
    float cR0[NR];
    float cR1[NR];
    float cR2[NR];
    float xa[NN];
    float xj[NN];
    float wj[NEA];
    int jall[NEA];
    int relh[NE];
    int relt[NE];
    int hr[NE];
    int tr[NE];
    int cnt_all[NN];
    int cnt_h[NN];
    int cnt_t[NN];
    int cnt_r[NR];
    int off_all[NN + 1];
    int off_h[NN + 1];
    int off_t[NN + 1];
    int off_r[NR + 1];
    int cur_all[NN];
    int cur_h[NN];
    int cur_t[NN];
    int cur_r[NR];
};
__device__ Scratch g_scr;

// ------------------------------------------------------------------
// helpers
// ------------------------------------------------------------------
__device__ __forceinline__ float lrelu01(float z) { return z > 0.f ? z : 0.01f * z; }

__device__ __forceinline__ float wredsum(float v) {
    #pragma unroll
    for (int o = 16; o > 0; o >>= 1) v += __shfl_xor_sync(0xffffffffu, v, o);
    return v;
}
__device__ __forceinline__ float wredmax(float v) {
    #pragma unroll
    for (int o = 16; o > 0; o >>= 1) v = fmaxf(v, __shfl_xor_sync(0xffffffffu, v, o));
    return v;
}

__device__ __forceinline__ float f2tf32f(float f) {
    uint32_t r;
    asm("cvt.rna.tf32.f32 %0, %1;" : "=r"(r) : "f"(f));
    return __uint_as_float(r);
}

static inline int divup(int a, int b) { return (a + b - 1) / b; }

// ------------------------------------------------------------------
// setup kernels
// ------------------------------------------------------------------
__global__ void k_hist4(const int* __restrict__ ii, const int* __restrict__ h,
                        const int* __restrict__ t, const int* __restrict__ rel) {
    int y = blockIdx.y;
    const int* keys; int n; int* cnt;
    if      (y == 0) { keys = ii;  n = NEA; cnt = g_scr.cnt_all; }
    else if (y == 1) { keys = h;   n = NE;  cnt = g_scr.cnt_h; }
    else if (y == 2) { keys = t;   n = NE;  cnt = g_scr.cnt_t; }
    else             { keys = rel; n = NE;  cnt = g_scr.cnt_r; }
    for (int i = blockIdx.x * blockDim.x + threadIdx.x; i < n; i += gridDim.x * blockDim.x)
        atomicAdd(&cnt[keys[i]], 1);
}

__global__ void k_scan4() {
    int y = blockIdx.x;
    const int* c; int n; int* off; int* cur;
    if      (y == 0) { c = g_scr.cnt_all; n = NN; off = g_scr.off_all; cur = g_scr.cur_all; }
    else if (y == 1) { c = g_scr.cnt_h;   n = NN; off = g_scr.off_h;   cur = g_scr.cur_h; }
    else if (y == 2) { c = g_scr.cnt_t;   n = NN; off = g_scr.off_t;   cur = g_scr.cur_t; }
    else             { c = g_scr.cnt_r;   n = NR; off = g_scr.off_r;   cur = g_scr.cur_r; }
    __shared__ int wsum[32];
    __shared__ int carrysh;
    int tid = threadIdx.x;
    int wid = tid >> 5, lane = tid & 31;
    if (tid == 0) carrysh = 0;
    __syncthreads();
    for (int base = 0; base < n; base += 1024) {
        int v = (base + tid < n) ? c[base + tid] : 0;
        int s = v;
        #pragma unroll
        for (int o = 1; o < 32; o <<= 1) {
            int t2 = __shfl_up_sync(0xffffffffu, s, o);
            if (lane >= o) s += t2;
        }
        if (lane == 31) wsum[wid] = s;
        __syncthreads();
        if (wid == 0) {
            int w = wsum[lane];
            #pragma unroll
            for (int o = 1; o < 32; o <<= 1) {
                int t2 = __shfl_up_sync(0xffffffffu, w, o);
                if (lane >= o) w += t2;
            }
            wsum[lane] = w;
        }
        __syncthreads();
        int woff = (wid > 0) ? wsum[wid - 1] : 0;
        int total = wsum[31];
        int ex = carrysh + woff + s - v;
        if (base + tid < n) { off[base + tid] = ex; cur[base + tid] = ex; }
        __syncthreads();
        if (tid == 0) carrysh += total;
        __syncthreads();
    }
    if (tid == 0) off[n] = carrysh;
}

__global__ void k_scatter4(const int* __restrict__ ii, const int* __restrict__ jjv,
                           const int* __restrict__ h, const int* __restrict__ t,
                           const int* __restrict__ rel) {
    int y = blockIdx.y;
    int stride = gridDim.x * blockDim.x;
    int i0 = blockIdx.x * blockDim.x + threadIdx.x;
    if (y == 0) {
        for (int i = i0; i < NEA; i += stride) {
            int pos = atomicAdd(&g_scr.cur_all[ii[i]], 1);
            int j = jjv[i];
            int d = g_scr.cnt_all[j];
            g_scr.jall[pos] = j;
            g_scr.wj[pos] = (d > 0) ? rsqrtf((float)d) : 0.0f;
        }
    } else if (y == 1) {
        for (int i = i0; i < NE; i += stride) {
            int pos = atomicAdd(&g_scr.cur_h[h[i]], 1);
            g_scr.relh[pos] = rel[i];
        }
    } else if (y == 2) {
        for (int i = i0; i < NE; i += stride) {
            int pos = atomicAdd(&g_scr.cur_t[t[i]], 1);
            g_scr.relt[pos] = rel[i];
        }
    } else {
        for (int i = i0; i < NE; i += stride) {
            int pos = atomicAdd(&g_scr.cur_r[rel[i]], 1);
            g_scr.hr[pos] = h[i];
            g_scr.tr[pos] = t[i];
        }
    }
}

// ------------------------------------------------------------------
// TF32 tensor-core GEMM, smem staged, ldmatrix fragments, vectorized I/O
// A smem: [128 rows][ASTR], B smem TRANSPOSED: [64 n][BSTR] (k-contig).
// OUT = C + bias (gate 0) | sigmoid(C + bias) (gate 1)
// ------------------------------------------------------------------
#define MMA_TF32(c, a, b0v, b1v) \
    asm volatile("mma.sync.aligned.m16n8k8.row.col.f32.tf32.tf32.f32 " \
        "{%0,%1,%2,%3}, {%4,%5,%6,%7}, {%8,%9}, {%0,%1,%2,%3};" \
        : "+f"((c)[0]), "+f"((c)[1]), "+f"((c)[2]), "+f"((c)[3]) \
        : "r"((a)[0]), "r"((a)[1]), "r"((a)[2]), "r"((a)[3]), \
          "r"(b0v), "r"(b1v))

#define LDSM_X4(r, p) \
    asm volatile("ldmatrix.sync.aligned.m8n8.x4.shared.b16 {%0,%1,%2,%3}, [%4];" \
        : "=r"((r)[0]), "=r"((r)[1]), "=r"((r)[2]), "=r"((r)[3]) : "r"(p))

#define ASTR 20
#define BSTR 20

__global__ __launch_bounds__(256) void k_tgemm(
    const float* __restrict__ A, const float* __restrict__ W,
    const float* __restrict__ bias, float* __restrict__ OUT,
    int M, int N, int K, int gate) {
    __shared__ float sA[2][128 * ASTR];
    __shared__ float sB[2][64 * BSTR];

    const int mb = blockIdx.x * 128, nb = blockIdx.y * 64;
    const int tid = threadIdx.x;
    const int lane = tid & 31;
    const int wid = tid >> 5;
    const int warp_m = (wid & 3) * 32;
    const int warp_n = (wid >> 2) * 32;

    float acc[2][4][4];
    #pragma unroll
    for (int mt = 0; mt < 2; mt++)
        #pragma unroll
        for (int nt = 0; nt < 4; nt++)
            #pragma unroll
            for (int q = 0; q < 4; q++) acc[mt][nt][q] = 0.f;

    // ldmatrix lane addressing
    const int g4 = lane >> 3;
    const int rsel = (g4 & 1) * 8 + (lane & 7);
    const int segf = (g4 >> 1) * 4;
    uint32_t pA[2], pB[2];
    #pragma unroll
    for (int mt = 0; mt < 2; mt++)
        pA[mt] = (uint32_t)__cvta_generic_to_shared(
            &sA[0][(warp_m + mt * 16 + rsel) * ASTR + segf]);
    #pragma unroll
    for (int np = 0; np < 2; np++)
        pB[np] = (uint32_t)__cvta_generic_to_shared(
            &sB[0][(warp_n + np * 16 + rsel) * BSTR + segf]);
    const uint32_t ABUF = 128u * ASTR * 4u;
    const uint32_t BBUF = 64u * BSTR * 4u;

    const int la_row = tid >> 1, la_cb = (tid & 1) * 8;   // A: 128r x 16k
    const int lb_n = tid & 63, lb_kq = (tid >> 6) * 4;    // B: 64n x 16k (n-major)

    float ra[8], rb[4];
    auto load_tile = [&](int k0) {
        int gm = mb + la_row;
        int c0 = k0 + la_cb;
        if (gm < M && c0 + 8 <= K) {
            const float4* p = (const float4*)(A + (size_t)gm * K + c0);
            float4 v0 = __ldg(p), v1 = __ldg(p + 1);
            ra[0]=v0.x; ra[1]=v0.y; ra[2]=v0.z; ra[3]=v0.w;
            ra[4]=v1.x; ra[5]=v1.y; ra[6]=v1.z; ra[7]=v1.w;
        } else {
            #pragma unroll
            for (int q = 0; q < 8; q++) {
                int gk = c0 + q;
                ra[q] = (gm < M && gk < K) ? A[(size_t)gm * K + gk] : 0.f;
            }
        }
        int gn = nb + lb_n;
        #pragma unroll
        for (int q = 0; q < 4; q++) {
            int gk = k0 + lb_kq + q;
            rb[q] = (gk < K && gn < N) ? __ldg(&W[(size_t)gk * N + gn]) : 0.f;
        }
    };
    auto store_tile = [&](int buf) {
        float4 v;
        v.x = f2tf32f(ra[0]); v.y = f2tf32f(ra[1]);
        v.z = f2tf32f(ra[2]); v.w = f2tf32f(ra[3]);
        *(float4*)&sA[buf][la_row * ASTR + la_cb] = v;
        v.x = f2tf32f(ra[4]); v.y = f2tf32f(ra[5]);
        v.z = f2tf32f(ra[6]); v.w = f2tf32f(ra[7]);
        *(float4*)&sA[buf][la_row * ASTR + la_cb + 4] = v;
        v.x = f2tf32f(rb[0]); v.y = f2tf32f(rb[1]);
        v.z = f2tf32f(rb[2]); v.w = f2tf32f(rb[3]);
        *(float4*)&sB[buf][lb_n * BSTR + lb_kq] = v;   // transposed: [n][k]
    };

    int nk = (K + 15) / 16;
    load_tile(0);
    store_tile(0);
    __syncthreads();

    for (int ki = 0; ki < nk; ki++) {
        int buf = ki & 1;
        bool nxt = (ki + 1 < nk);
        if (nxt) load_tile((ki + 1) * 16);

        uint32_t aoff = buf * ABUF, boff = buf * BBUF;
        #pragma unroll
        for (int ks = 0; ks < 2; ks++) {
            uint32_t a[2][4], bfrag[2][4];
            #pragma unroll
            for (int mt = 0; mt < 2; mt++)
                LDSM_X4(a[mt], pA[mt] + aoff + ks * 32);
            #pragma unroll
            for (int np = 0; np < 2; np++)
                LDSM_X4(bfrag[np], pB[np] + boff + ks * 32);
            #pragma unroll
            for (int mt = 0; mt < 2; mt++)
                #pragma unroll
                for (int np = 0; np < 2; np++) {
                    MMA_TF32(acc[mt][np * 2],     a[mt], bfrag[np][0], bfrag[np][2]);
                    MMA_TF32(acc[mt][np * 2 + 1], a[mt], bfrag[np][1], bfrag[np][3]);
                }
        }
        if (nxt) store_tile(buf ^ 1);
        __syncthreads();
    }

    const int erow = lane >> 2;
    const int ecol = (lane & 3) * 2;
    #pragma unroll
    for (int mt = 0; mt < 2; mt++) {
        #pragma unroll
        for (int nt = 0; nt < 4; nt++) {
            #pragma unroll
            for (int q = 0; q < 4; q++) {
                int gm = mb + warp_m + mt * 16 + erow + (q >> 1) * 8;
                int gc = nb + warp_n + nt * 8 + ecol + (q & 1);
                if (gm >= M || gc >= N) continue;
                float v = acc[mt][nt][q] + bias[gc];
                if (gate) v = 1.f / (1.f + expf(-v));
                OUT[(size_t)gm * N + gc] = v;
            }
        }
    }
}

// ------------------------------------------------------------------
// GCN + highway combine
// ------------------------------------------------------------------
__global__ void k_gcnhw(const float* __restrict__ xin, const float* __restrict__ gate,
                        float* __restrict__ xout) {
    int n = (blockIdx.x * blockDim.x + threadIdx.x) >> 5;
    if (n >= NN) return;
    int lane = threadIdx.x & 31;
    int s0 = g_scr.off_all[n], s1 = g_scr.off_all[n + 1];
    bool l2ok = (64 + lane) < 75;
    float4 a0 = {0,0,0,0}, a1 = {0,0,0,0}, a2 = {0,0,0,0};
    for (int p = s0; p < s1; p++) {
        int j = g_scr.jall[p];
        float w = g_scr.wj[p];
        const float4* xr = (const float4*)(xin + (size_t)j * EHD);
        float4 v0 = __ldg(xr + lane);
        float4 v1 = __ldg(xr + 32 + lane);
        a0.x += w*v0.x; a0.y += w*v0.y; a0.z += w*v0.z; a0.w += w*v0.w;
        a1.x += w*v1.x; a1.y += w*v1.y; a1.z += w*v1.z; a1.w += w*v1.w;
        if (l2ok) {
            float4 v2 = __ldg(xr + 64 + lane);
            a2.x += w*v2.x; a2.y += w*v2.y; a2.z += w*v2.z; a2.w += w*v2.w;
        }
    }
    int dcnt = s1 - s0;
    float dn = (dcnt > 0) ? rsqrtf((float)dcnt) : 0.0f;
    const float4* xp = (const float4*)(xin + (size_t)n * EHD);
    const float4* gp = (const float4*)(gate + (size_t)n * EHD);
    float4* yr = (float4*)(xout + (size_t)n * EHD);
    float4 o, g4, p4;

    g4 = gp[lane]; p4 = xp[lane];
    o.x = g4.x * fmaxf(dn*a0.x, 0.f) + (1.f - g4.x) * p4.x;
    o.y = g4.y * fmaxf(dn*a0.y, 0.f) + (1.f - g4.y) * p4.y;
    o.z = g4.z * fmaxf(dn*a0.z, 0.f) + (1.f - g4.z) * p4.z;
    o.w = g4.w * fmaxf(dn*a0.w, 0.f) + (1.f - g4.w) * p4.w;
    yr[lane] = o;

    g4 = gp[32 + lane]; p4 = xp[32 + lane];
    o.x = g4.x * fmaxf(dn*a1.x, 0.f) + (1.f - g4.x) * p4.x;
    o.y = g4.y * fmaxf(dn*a1.y, 0.f) + (1.f - g4.y) * p4.y;
    o.z = g4.z * fmaxf(dn*a1.z, 0.f) + (1.f - g4.z) * p4.z;
    o.w = g4.w * fmaxf(dn*a1.w, 0.f) + (1.f - g4.w) * p4.w;
    yr[32 + lane] = o;

    if (l2ok) {
        g4 = gp[64 + lane]; p4 = xp[64 + lane];
        o.x = g4.x * fmaxf(dn*a2.x, 0.f) + (1.f - g4.x) * p4.x;
        o.y = g4.y * fmaxf(dn*a2.y, 0.f) + (1.f - g4.y) * p4.y;
        o.z = g4.z * fmaxf(dn*a2.z, 0.f) + (1.f - g4.z) * p4.z;
        o.w = g4.w * fmaxf(dn*a2.w, 0.f) + (1.f - g4.w) * p4.w;
        yr[64 + lane] = o;
    }
}

// ------------------------------------------------------------------
// per-relation means + rf2 + RF assembly
// ------------------------------------------------------------------
__global__ __launch_bounds__(256) void k_relmean(const float* __restrict__ sr1w,
                                                 const float* __restrict__ sr1b) {
    int r = blockIdx.x;
    int tid = threadIdx.x;
    __shared__ float acc[200];
    __shared__ float cat[200];
    if (tid < 200) acc[tid] = 0.f;
    __syncthreads();

    int wi = tid >> 5, lane = tid & 31;
    int s0 = g_scr.off_r[r], s1 = g_scr.off_r[r + 1];
    float4 lh = {0,0,0,0}, lt = {0,0,0,0};
    for (int p = s0 + wi; p < s1; p += 8) {
        int hh = g_scr.hr[p], tt = g_scr.tr[p];
        if (lane < 25) {
            const float4* sh_ = (const float4*)(g_scr.S + (size_t)hh * THD);
            const float4* st_ = (const float4*)(g_scr.S + (size_t)tt * THD);
            float4 v = __ldg(sh_ + lane);
            lh.x += v.x; lh.y += v.y; lh.z += v.z; lh.w += v.w;
            float4 u = __ldg(st_ + lane);
            lt.x += u.x; lt.y += u.y; lt.z += u.z; lt.w += u.w;
        }
    }
    if (lane < 25) {
        atomicAdd(&acc[4*lane+0], lh.x); atomicAdd(&acc[4*lane+1], lh.y);
        atomicAdd(&acc[4*lane+2], lh.z); atomicAdd(&acc[4*lane+3], lh.w);
        atomicAdd(&acc[100+4*lane+0], lt.x); atomicAdd(&acc[100+4*lane+1], lt.y);
        atomicAdd(&acc[100+4*lane+2], lt.z); atomicAdd(&acc[100+4*lane+3], lt.w);
    }
    __syncthreads();
    float c = fmaxf((float)(s1 - s0), 1.f);
    if (tid < 200) cat[tid] = acc[tid] / c;
    __syncthreads();
    if (tid < 100) {
        float a = sr1b[tid];
        #pragma unroll 4
        for (int k = 0; k < 200; k++) a += cat[k] * sr1w[k * 100 + tid];
        float* rf = g_scr.RF + (size_t)r * EHD;
        rf[tid]       = a;
        rf[100 + tid] = cat[tid];
        rf[200 + tid] = cat[100 + tid];
    }
}

// ------------------------------------------------------------------
// batched small sgemm: ER_k = RF @ wr_k + br_k
// ------------------------------------------------------------------
__global__ __launch_bounds__(256) void k_sgemm3(
    const float* __restrict__ W0, const float* __restrict__ b0,
    const float* __restrict__ W1, const float* __restrict__ b1,
    const float* __restrict__ W2, const float* __restrict__ b2) {
    const float* W; const float* bias; float* OUT;
    int z = blockIdx.z;
    if      (z == 0) { W = W0; bias = b0; OUT = g_scr.ER0; }
    else if (z == 1) { W = W1; bias = b1; OUT = g_scr.ER1; }
    else             { W = W2; bias = b2; OUT = g_scr.ER2; }
    const float* A = g_scr.RF;
    const int M = NR, N = EHD, K = EHD;

    __shared__ float As[16][128];
    __shared__ float Bs[16][64];
    int mb = blockIdx.x * 128, nb = blockIdx.y * 64;
    int tid = threadIdx.x;
    int ty = tid >> 4;
    int tx = tid & 15;
    float acc[8][4];
    #pragma unroll
    for (int i = 0; i < 8; i++)
        #pragma unroll
        for (int j = 0; j < 4; j++) acc[i][j] = 0.f;

    for (int k0 = 0; k0 < K; k0 += 16) {
        #pragma unroll
        for (int l = 0; l < 8; l++) {
            int idx = tid + l * 256;
            int arr = idx >> 4, ak = idx & 15;
            int gm = mb + arr, gk = k0 + ak;
            As[ak][arr] = (gm < M && gk < K) ? A[(size_t)gm * K + gk] : 0.f;
        }
        #pragma unroll
        for (int l = 0; l < 4; l++) {
            int idx = tid + l * 256;
            int bn = idx & 63, bk = idx >> 6;
            int gk = k0 + bk, gnn = nb + bn;
            Bs[bk][bn] = (gk < K && gnn < N) ? W[(size_t)gk * N + gnn] : 0.f;
        }
        __syncthreads();
        #pragma unroll
        for (int k = 0; k < 16; k++) {
            float a[8], b[4];
            #pragma unroll
            for (int i = 0; i < 8; i++) a[i] = As[k][ty * 8 + i];
            #pragma unroll
            for (int j = 0; j < 4; j++) b[j] = Bs[k][tx * 4 + j];
            #pragma unroll
            for (int i = 0; i < 8; i++)
                #pragma unroll
                for (int j = 0; j < 4; j++) acc[i][j] += a[i] * b[j];
        }
        __syncthreads();
    }
    #pragma unroll
    for (int i = 0; i < 8; i++) {
        int gm = mb + ty * 8 + i;
        if (gm >= M) continue;
        #pragma unroll
        for (int j = 0; j < 4; j++) {
            int gnn = nb + tx * 4 + j;
            if (gnn >= N) continue;
            OUT[(size_t)gm * N + gnn] = acc[i][j] + bias[gnn];
        }
    }
}

// ------------------------------------------------------------------
// batched rowdot over ER matrices: cR_k = ER_k . ar_k
// ------------------------------------------------------------------
__global__ void k_rowdot3(const float* __restrict__ v0, const float* __restrict__ v1,
                          const float* __restrict__ v2) {
    int y = blockIdx.y;
    const float* Mtx; const float* v; float* out;
    if      (y == 0) { Mtx = g_scr.ER0; v = v0; out = g_scr.cR0; }
    else if (y == 1) { Mtx = g_scr.ER1; v = v1; out = g_scr.cR1; }
    else             { Mtx = g_scr.ER2; v = v2; out = g_scr.cR2; }
    int r = (blockIdx.x * blockDim.x + threadIdx.x) >> 5;
    int lane = threadIdx.x & 31;
    if (r >= NR) return;
    const float4* mr = (const float4*)(Mtx + (size_t)r * EHD);
    const float4* vv = (const float4*)v;
    float s = 0.f;
    float4 a = mr[lane], b = vv[lane];
    s += a.x*b.x + a.y*b.y + a.z*b.z + a.w*b.w;
    a = mr[32 + lane]; b = vv[32 + lane];
    s += a.x*b.x + a.y*b.y + a.z*b.z + a.w*b.w;
    if (lane < 11) {
        a = mr[64 + lane]; b = vv[64 + lane];
        s += a.x*b.x + a.y*b.y + a.z*b.z + a.w*b.w;
    }
    s = wredsum(s);
    if (lane == 0) out[r] = s;
}

// ------------------------------------------------------------------
// FUSED triple r2e: keeps the node row in registers across all 3 rounds,
// then emits xa = row.ai and xj = row.aj and writes the row once.
// ------------------------------------------------------------------
__global__ void k_r2e3(const float* __restrict__ ah, const float* __restrict__ at,
                       const float* __restrict__ ah1, const float* __restrict__ ai,
                       const float* __restrict__ aj) {
    int n = (blockIdx.x * blockDim.x + threadIdx.x) >> 5;
    if (n >= NN) return;
    int lane = threadIdx.x & 31;
    bool l2ok = (64 + lane) < 75;

    float4* zr = (float4*)(g_scr.Z + (size_t)n * EHD);
    float4 v0 = zr[lane];
    float4 v1 = zr[32 + lane];
    float4 v2 = l2ok ? zr[64 + lane] : make_float4(0.f, 0.f, 0.f, 0.f);

    auto dotv = [&](const float* w) -> float {
        const float4* wp = (const float4*)w;
        float4 q = wp[lane];
        float d = v0.x*q.x + v0.y*q.y + v0.z*q.z + v0.w*q.w;
        q = wp[32 + lane];
        d += v1.x*q.x + v1.y*q.y + v1.z*q.z + v1.w*q.w;
        if (l2ok) {
            q = wp[64 + lane];
            d += v2.x*q.x + v2.y*q.y + v2.z*q.z + v2.w*q.w;
        }
        return wredsum(d);
    };

    auto round = [&](const float* ER, const float* cR,
                     const int* off, const int* rels, const float* avec) {
        float xan = dotv(avec);
        int s0 = off[n], s1 = off[n + 1];
        float4 a0 = {0,0,0,0}, a1 = {0,0,0,0}, a2 = {0,0,0,0};
        if (s1 > s0) {
            float m = -1e30f;
            for (int p = s0 + lane; p < s1; p += 32)
                m = fmaxf(m, lrelu01(xan + cR[rels[p]]));
            m = wredmax(m);
            float den = 0.f;
            for (int p = s0 + lane; p < s1; p += 32)
                den += expf(lrelu01(xan + cR[rels[p]]) - m);
            den = wredsum(den);
            float inv = 1.f / den;
            for (int p = s0; p < s1; p++) {
                int r = rels[p];
                float w = expf(lrelu01(xan + cR[r]) - m) * inv;
                const float4* er = (const float4*)(ER + (size_t)r * EHD);
                float4 u0 = __ldg(er + lane);
                float4 u1 = __ldg(er + 32 + lane);
                a0.x += w*u0.x; a0.y += w*u0.y; a0.z += w*u0.z; a0.w += w*u0.w;
                a1.x += w*u1.x; a1.y += w*u1.y; a1.z += w*u1.z; a1.w += w*u1.w;
                if (l2ok) {
                    float4 u2 = __ldg(er + 64 + lane);
                    a2.x += w*u2.x; a2.y += w*u2.y; a2.z += w*u2.z; a2.w += w*u2.w;
                }
            }
        }
        v0.x += fmaxf(a0.x, 0.f); v0.y += fmaxf(a0.y, 0.f);
        v0.z += fmaxf(a0.z, 0.f); v0.w += fmaxf(a0.w, 0.f);
        v1.x += fmaxf(a1.x, 0.f); v1.y += fmaxf(a1.y, 0.f);
        v1.z += fmaxf(a1.z, 0.f); v1.w += fmaxf(a1.w, 0.f);
        v2.x += fmaxf(a2.x, 0.f); v2.y += fmaxf(a2.y, 0.f);
        v2.z += fmaxf(a2.z, 0.f); v2.w += fmaxf(a2.w, 0.f);
    };

    round(g_scr.ER0, g_scr.cR0, g_scr.off_h, g_scr.relh, ah);
    round(g_scr.ER1, g_scr.cR1, g_scr.off_t, g_scr.relt, at);
    round(g_scr.ER2, g_scr.cR2, g_scr.off_h, g_scr.relh, ah1);

    float dai = dotv(ai);
    float daj = dotv(aj);
    if (lane == 0) {
        g_scr.xa[n] = dai;
        g_scr.xj[n] = daj;
    }
    zr[lane] = v0;
    zr[32 + lane] = v1;
    if (l2ok) zr[64 + lane] = v2;
}

// ------------------------------------------------------------------
// final GAT + fc output
// ------------------------------------------------------------------
__global__ void k_gatfinal(const float* __restrict__ fcw, const float* __restrict__ fcb,
                           float* __restrict__ outp) {
    int n = (blockIdx.x * blockDim.x + threadIdx.x) >> 5;
    if (n >= NN) return;
    int lane = threadIdx.x & 31;
    int s0 = g_scr.off_all[n], s1 = g_scr.off_all[n + 1];
    bool l2ok = (64 + lane) < 75;
    float4 a0 = {0,0,0,0}, a1 = {0,0,0,0}, a2 = {0,0,0,0};

    if (s1 > s0) {
        float xin = g_scr.xa[n];
        float m = -1e30f;
        for (int p = s0 + lane; p < s1; p += 32)
            m = fmaxf(m, lrelu01(xin + g_scr.xj[g_scr.jall[p]]));
        m = wredmax(m);
        float den = 0.f;
        for (int p = s0 + lane; p < s1; p += 32)
            den += expf(lrelu01(xin + g_scr.xj[g_scr.jall[p]]) - m);
        den = wredsum(den);
        float inv = 1.f / den;
        for (int p = s0; p < s1; p++) {
            int j = g_scr.jall[p];
            float w = expf(lrelu01(xin + g_scr.xj[j]) - m) * inv;
            const float4* xr = (const float4*)(g_scr.Z + (size_t)j * EHD);
            float4 u0 = __ldg(xr + lane);
            float4 u1 = __ldg(xr + 32 + lane);
            a0.x += w*u0.x; a0.y += w*u0.y; a0.z += w*u0.z; a0.w += w*u0.w;
            a1.x += w*u1.x; a1.y += w*u1.y; a1.z += w*u1.z; a1.w += w*u1.w;
            if (l2ok) {
                float4 u2 = __ldg(xr + 64 + lane);
                a2.x += w*u2.x; a2.y += w*u2.y; a2.z += w*u2.z; a2.w += w*u2.w;
            }
        }
    }
    const float4* xn = (const float4*)(g_scr.Z + (size_t)n * EHD);
    const float4* f1 = (const float4*)fcw;
    const float4* f2 = (const float4*)(fcw + EHD);
    float local = 0.f;

    float4 v = xn[lane], q = f1[lane], g = f2[lane];
    local += v.x*q.x + v.y*q.y + v.z*q.z + v.w*q.w;
    local += fmaxf(a0.x,0.f)*g.x + fmaxf(a0.y,0.f)*g.y + fmaxf(a0.z,0.f)*g.z + fmaxf(a0.w,0.f)*g.w;
    v = xn[32+lane]; q = f1[32+lane]; g = f2[32+lane];
    local += v.x*q.x + v.y*q.y + v.z*q.z + v.w*q.w;
    local += fmaxf(a1.x,0.f)*g.x + fmaxf(a1.y,0.f)*g.y + fmaxf(a1.z,0.f)*g.z + fmaxf(a1.w,0.f)*g.w;
    if (l2ok) {
        v = xn[64+lane]; q = f1[64+lane]; g = f2[64+lane];
        local += v.x*q.x + v.y*q.y + v.z*q.z + v.w*q.w;
        local += fmaxf(a2.x,0.f)*g.x + fmaxf(a2.y,0.f)*g.y + fmaxf(a2.z,0.f)*g.z + fmaxf(a2.w,0.f)*g.w;
    }
    local = wredsum(local);
    if (lane == 0) outp[n] = local + fcb[0];
}

// ------------------------------------------------------------------
// launcher
// ------------------------------------------------------------------
extern "C" void kernel_launch(void* const* d_in, const int* in_sizes, int n_in,
                              void* d_out, int out_size) {
    const float* x      = (const float*)d_in[0];
    const int*   ei     = (const int*)d_in[1];
    const int*   rel    = (const int*)d_in[2];
    const int*   eia    = (const int*)d_in[3];
    const float* hw1_w  = (const float*)d_in[5];
    const float* hw1_b  = (const float*)d_in[6];
    const float* hw2_w  = (const float*)d_in[7];
    const float* hw2_b  = (const float*)d_in[8];
    const float* tc1_w  = (const float*)d_in[9];
    const float* tc1_b  = (const float*)d_in[10];
    const float* sr1_w  = (const float*)d_in[11];
    const float* sr1_b  = (const float*)d_in[12];
    const float* wr_w   = (const float*)d_in[15];
    const float* wr_b   = (const float*)d_in[16];
    const float* wr1_w  = (const float*)d_in[17];
    const float* wr1_b  = (const float*)d_in[18];
    const float* wr2_w  = (const float*)d_in[19];
    const float* wr2_b  = (const float*)d_in[20];
    const float* ah_w   = (const float*)d_in[21];
    const float* ah1_w  = (const float*)d_in[22];
    const float* at_w   = (const float*)d_in[23];
    const float* ar1_w  = (const float*)d_in[24];
    const float* ar2_w  = (const float*)d_in[25];
    const float* ar3_w  = (const float*)d_in[26];
    const float* ai_w   = (const float*)d_in[27];
    const float* aj_w   = (const float*)d_in[28];
    const float* fc_w   = (const float*)d_in[29];
    const float* fc_b   = (const float*)d_in[30];
    float* out = (float*)d_out;

    const int* h  = ei;
    const int* t  = ei + NE;
    const int* jj = eia;
    const int* ii = eia + NEA;

    Scratch* g = nullptr;
    cudaGetSymbolAddress((void**)&g, g_scr);

    const int TPB = 256;
    const int NODE_BLKS = divup(NN * 32, TPB);

    cudaMemsetAsync(g->cnt_all, 0, (size_t)(3 * NN + NR) * sizeof(int));

    k_hist4<<<dim3(128, 4), TPB>>>(ii, h, t, rel);        // 1
    k_scan4<<<4, 1024>>>();                               // 2
    k_scatter4<<<dim3(512, 4), TPB>>>(ii, jj, h, t, rel); // 3

    dim3 gemmGrid300(divup(NN, 128), divup(EHD, 64));
    dim3 gemmGrid100(divup(NN, 128), divup(THD, 64));
    k_tgemm<<<gemmGrid300, 256>>>(x, hw1_w, hw1_b, g->Y, NN, EHD, EHD, 1);   // 4 (profiled)
    k_gcnhw<<<NODE_BLKS, TPB>>>(x, g->Y, g->X);
    k_tgemm<<<gemmGrid300, 256>>>(g->X, hw2_w, hw2_b, g->Y, NN, EHD, EHD, 1);
    k_gcnhw<<<NODE_BLKS, TPB>>>(g->X, g->Y, g->Z);
    k_tgemm<<<gemmGrid100, 256>>>(g->Z, tc1_w, tc1_b, g->S, NN, THD, EHD, 0);

    k_relmean<<<NR, 256>>>(sr1_w, sr1_b);
    dim3 gemmGridR(divup(NR, 128), divup(EHD, 64), 3);
    k_sgemm3<<<gemmGridR, 256>>>(wr_w, wr_b, wr1_w, wr1_b, wr2_w, wr2_b);
    k_rowdot3<<<dim3(divup(NR * 32, TPB), 3), TPB>>>(ar1_w, ar2_w, ar3_w);

    k_r2e3<<<NODE_BLKS, TPB>>>(ah_w, at_w, ah1_w, ai_w, aj_w);
    k_gatfinal<<<NODE_BLKS, TPB>>>(fc_w, fc_b, out);
    (void)in_sizes; (void)n_in; (void)out_size;
}

// round 13
// speedup vs baseline: 1.3018x; 1.0066x over previous
#include <cuda_runtime.h>
#include <cuda_bf16.h>
#include <stdint.h>
#include <math.h>

#define NN  50000
#define NE  250000
#define NEA 500000
#define NR  300
#define EHD 300
#define THD 100

// ------------------------------------------------------------------
// Static device scratch
// ------------------------------------------------------------------
struct Scratch {
    float X[(size_t)NN * EHD];
    float Y[(size_t)NN * EHD];   // gate buffer
    float Z[(size_t)NN * EHD];
    float S[(size_t)NN * THD];
    float RF[NR * EHD];
    float ER0[NR * EHD];
    float ER1[NR * EHD];
    float ER2[NR * EHD];
    float cR0[NR];
    float cR1[NR];
    float cR2[NR];
    float xa[NN];
    float xj[NN];
    float wj[NEA];
    int jall[NEA];
    int relh[NE];
    int relt[NE];
    int hr[NE];
    int tr[NE];
    int cnt_all[NN];
    int cnt_h[NN];
    int cnt_t[NN];
    int cnt_r[NR];
    int off_all[NN + 1];
    int off_h[NN + 1];
    int off_t[NN + 1];
    int off_r[NR + 1];
    int cur_all[NN];
    int cur_h[NN];
    int cur_t[NN];
    int cur_r[NR];
};
__device__ Scratch g_scr;

// ------------------------------------------------------------------
// helpers
// ------------------------------------------------------------------
__device__ __forceinline__ float lrelu01(float z) { return z > 0.f ? z : 0.01f * z; }

__device__ __forceinline__ float wredsum(float v) {
    #pragma unroll
    for (int o = 16; o > 0; o >>= 1) v += __shfl_xor_sync(0xffffffffu, v, o);
    return v;
}
__device__ __forceinline__ float wredmax(float v) {
    #pragma unroll
    for (int o = 16; o > 0; o >>= 1) v = fmaxf(v, __shfl_xor_sync(0xffffffffu, v, o));
    return v;
}

static inline int divup(int a, int b) { return (a + b - 1) / b; }

// ------------------------------------------------------------------
// setup kernels
// ------------------------------------------------------------------
__global__ void k_hist4(const int* __restrict__ ii, const int* __restrict__ h,
                        const int* __restrict__ t, const int* __restrict__ rel) {
    int y = blockIdx.y;
    const int* keys; int n; int* cnt;
    if      (y == 0) { keys = ii;  n = NEA; cnt = g_scr.cnt_all; }
    else if (y == 1) { keys = h;   n = NE;  cnt = g_scr.cnt_h; }
    else if (y == 2) { keys = t;   n = NE;  cnt = g_scr.cnt_t; }
    else             { keys = rel; n = NE;  cnt = g_scr.cnt_r; }
    for (int i = blockIdx.x * blockDim.x + threadIdx.x; i < n; i += gridDim.x * blockDim.x)
        atomicAdd(&cnt[keys[i]], 1);
}

__global__ void k_scan4() {
    int y = blockIdx.x;
    const int* c; int n; int* off; int* cur;
    if      (y == 0) { c = g_scr.cnt_all; n = NN; off = g_scr.off_all; cur = g_scr.cur_all; }
    else if (y == 1) { c = g_scr.cnt_h;   n = NN; off = g_scr.off_h;   cur = g_scr.cur_h; }
    else if (y == 2) { c = g_scr.cnt_t;   n = NN; off = g_scr.off_t;   cur = g_scr.cur_t; }
    else             { c = g_scr.cnt_r;   n = NR; off = g_scr.off_r;   cur = g_scr.cur_r; }
    __shared__ int wsum[32];
    __shared__ int carrysh;
    int tid = threadIdx.x;
    int wid = tid >> 5, lane = tid & 31;
    if (tid == 0) carrysh = 0;
    __syncthreads();
    for (int base = 0; base < n; base += 1024) {
        int v = (base + tid < n) ? c[base + tid] : 0;
        int s = v;
        #pragma unroll
        for (int o = 1; o < 32; o <<= 1) {
            int t2 = __shfl_up_sync(0xffffffffu, s, o);
            if (lane >= o) s += t2;
        }
        if (lane == 31) wsum[wid] = s;
        __syncthreads();
        if (wid == 0) {
            int w = wsum[lane];
            #pragma unroll
            for (int o = 1; o < 32; o <<= 1) {
                int t2 = __shfl_up_sync(0xffffffffu, w, o);
                if (lane >= o) w += t2;
            }
            wsum[lane] = w;
        }
        __syncthreads();
        int woff = (wid > 0) ? wsum[wid - 1] : 0;
        int total = wsum[31];
        int ex = carrysh + woff + s - v;
        if (base + tid < n) { off[base + tid] = ex; cur[base + tid] = ex; }
        __syncthreads();
        if (tid == 0) carrysh += total;
        __syncthreads();
    }
    if (tid == 0) off[n] = carrysh;
}

__global__ void k_scatter4(const int* __restrict__ ii, const int* __restrict__ jjv,
                           const int* __restrict__ h, const int* __restrict__ t,
                           const int* __restrict__ rel) {
    int y = blockIdx.y;
    int stride = gridDim.x * blockDim.x;
    int i0 = blockIdx.x * blockDim.x + threadIdx.x;
    if (y == 0) {
        for (int i = i0; i < NEA; i += stride) {
            int pos = atomicAdd(&g_scr.cur_all[ii[i]], 1);
            int j = jjv[i];
            int d = g_scr.cnt_all[j];
            g_scr.jall[pos] = j;
            g_scr.wj[pos] = (d > 0) ? rsqrtf((float)d) : 0.0f;
        }
    } else if (y == 1) {
        for (int i = i0; i < NE; i += stride) {
            int pos = atomicAdd(&g_scr.cur_h[h[i]], 1);
            g_scr.relh[pos] = rel[i];
        }
    } else if (y == 2) {
        for (int i = i0; i < NE; i += stride) {
            int pos = atomicAdd(&g_scr.cur_t[t[i]], 1);
            g_scr.relt[pos] = rel[i];
        }
    } else {
        for (int i = i0; i < NE; i += stride) {
            int pos = atomicAdd(&g_scr.cur_r[rel[i]], 1);
            g_scr.hr[pos] = h[i];
            g_scr.tr[pos] = t[i];
        }
    }
}

// ------------------------------------------------------------------
// TF32 tensor-core GEMM, smem staged, ldmatrix fragments, vectorized I/O.
// fp32 bits fed directly to the tf32 MMA (hardware truncates to tf32).
// A smem: [128 rows][ASTR], B smem TRANSPOSED: [64 n][BSTR] (k-contig).
// OUT = C + bias (gate 0) | sigmoid(C + bias) (gate 1)
// ------------------------------------------------------------------
#define MMA_TF32(c, a, b0v, b1v) \
    asm volatile("mma.sync.aligned.m16n8k8.row.col.f32.tf32.tf32.f32 " \
        "{%0,%1,%2,%3}, {%4,%5,%6,%7}, {%8,%9}, {%0,%1,%2,%3};" \
        : "+f"((c)[0]), "+f"((c)[1]), "+f"((c)[2]), "+f"((c)[3]) \
        : "r"((a)[0]), "r"((a)[1]), "r"((a)[2]), "r"((a)[3]), \
          "r"(b0v), "r"(b1v))

#define LDSM_X4(r, p) \
    asm volatile("ldmatrix.sync.aligned.m8n8.x4.shared.b16 {%0,%1,%2,%3}, [%4];" \
        : "=r"((r)[0]), "=r"((r)[1]), "=r"((r)[2]), "=r"((r)[3]) : "r"(p))

#define ASTR 20
#define BSTR 20

__global__ __launch_bounds__(256) void k_tgemm(
    const float* __restrict__ A, const float* __restrict__ W,
    const float* __restrict__ bias, float* __restrict__ OUT,
    int M, int N, int K, int gate) {
    __shared__ float sA[2][128 * ASTR];
    __shared__ float sB[2][64 * BSTR];

    const int mb = blockIdx.x * 128, nb = blockIdx.y * 64;
    const int tid = threadIdx.x;
    const int lane = tid & 31;
    const int wid = tid >> 5;
    const int warp_m = (wid & 3) * 32;
    const int warp_n = (wid >> 2) * 32;

    float acc[2][4][4];
    #pragma unroll
    for (int mt = 0; mt < 2; mt++)
        #pragma unroll
        for (int nt = 0; nt < 4; nt++)
            #pragma unroll
            for (int q = 0; q < 4; q++) acc[mt][nt][q] = 0.f;

    // ldmatrix lane addressing
    const int g4 = lane >> 3;
    const int rsel = (g4 & 1) * 8 + (lane & 7);
    const int segf = (g4 >> 1) * 4;
    uint32_t pA[2], pB[2];
    #pragma unroll
    for (int mt = 0; mt < 2; mt++)
        pA[mt] = (uint32_t)__cvta_generic_to_shared(
            &sA[0][(warp_m + mt * 16 + rsel) * ASTR + segf]);
    #pragma unroll
    for (int np = 0; np < 2; np++)
        pB[np] = (uint32_t)__cvta_generic_to_shared(
            &sB[0][(warp_n + np * 16 + rsel) * BSTR + segf]);
    const uint32_t ABUF = 128u * ASTR * 4u;
    const uint32_t BBUF = 64u * BSTR * 4u;

    const int la_row = tid >> 1, la_cb = (tid & 1) * 8;   // A: 128r x 16k
    const int lb_n = tid & 63, lb_kq = (tid >> 6) * 4;    // B: 64n x 16k (n-major)

    float ra[8], rb[4];
    auto load_tile = [&](int k0) {
        int gm = mb + la_row;
        int c0 = k0 + la_cb;
        if (gm < M && c0 + 8 <= K) {
            const float4* p = (const float4*)(A + (size_t)gm * K + c0);
            float4 v0 = __ldg(p), v1 = __ldg(p + 1);
            ra[0]=v0.x; ra[1]=v0.y; ra[2]=v0.z; ra[3]=v0.w;
            ra[4]=v1.x; ra[5]=v1.y; ra[6]=v1.z; ra[7]=v1.w;
        } else {
            #pragma unroll
            for (int q = 0; q < 8; q++) {
                int gk = c0 + q;
                ra[q] = (gm < M && gk < K) ? A[(size_t)gm * K + gk] : 0.f;
            }
        }
        int gn = nb + lb_n;
        #pragma unroll
        for (int q = 0; q < 4; q++) {
            int gk = k0 + lb_kq + q;
            rb[q] = (gk < K && gn < N) ? __ldg(&W[(size_t)gk * N + gn]) : 0.f;
        }
    };
    auto store_tile = [&](int buf) {
        // raw fp32 bits; tf32 MMA truncates mantissa in hardware
        float4 v;
        v.x = ra[0]; v.y = ra[1]; v.z = ra[2]; v.w = ra[3];
        *(float4*)&sA[buf][la_row * ASTR + la_cb] = v;
        v.x = ra[4]; v.y = ra[5]; v.z = ra[6]; v.w = ra[7];
        *(float4*)&sA[buf][la_row * ASTR + la_cb + 4] = v;
        v.x = rb[0]; v.y = rb[1]; v.z = rb[2]; v.w = rb[3];
        *(float4*)&sB[buf][lb_n * BSTR + lb_kq] = v;   // transposed: [n][k]
    };

    int nk = (K + 15) / 16;
    load_tile(0);
    store_tile(0);
    __syncthreads();

    for (int ki = 0; ki < nk; ki++) {
        int buf = ki & 1;
        bool nxt = (ki + 1 < nk);
        if (nxt) load_tile((ki + 1) * 16);

        uint32_t aoff = buf * ABUF, boff = buf * BBUF;
        #pragma unroll
        for (int ks = 0; ks < 2; ks++) {
            uint32_t a[2][4], bfrag[2][4];
            #pragma unroll
            for (int mt = 0; mt < 2; mt++)
                LDSM_X4(a[mt], pA[mt] + aoff + ks * 32);
            #pragma unroll
            for (int np = 0; np < 2; np++)
                LDSM_X4(bfrag[np], pB[np] + boff + ks * 32);
            #pragma unroll
            for (int mt = 0; mt < 2; mt++)
                #pragma unroll
                for (int np = 0; np < 2; np++) {
                    MMA_TF32(acc[mt][np * 2],     a[mt], bfrag[np][0], bfrag[np][2]);
                    MMA_TF32(acc[mt][np * 2 + 1], a[mt], bfrag[np][1], bfrag[np][3]);
                }
        }
        if (nxt) store_tile(buf ^ 1);
        __syncthreads();
    }

    const int erow = lane >> 2;
    const int ecol = (lane & 3) * 2;
    #pragma unroll
    for (int mt = 0; mt < 2; mt++) {
        #pragma unroll
        for (int nt = 0; nt < 4; nt++) {
            #pragma unroll
            for (int q = 0; q < 4; q++) {
                int gm = mb + warp_m + mt * 16 + erow + (q >> 1) * 8;
                int gc = nb + warp_n + nt * 8 + ecol + (q & 1);
                if (gm >= M || gc >= N) continue;
                float v = acc[mt][nt][q] + bias[gc];
                if (gate) v = 1.f / (1.f + expf(-v));
                OUT[(size_t)gm * N + gc] = v;
            }
        }
    }
}

// ------------------------------------------------------------------
// GCN + highway combine
// ------------------------------------------------------------------
__global__ void k_gcnhw(const float* __restrict__ xin, const float* __restrict__ gate,
                        float* __restrict__ xout) {
    int n = (blockIdx.x * blockDim.x + threadIdx.x) >> 5;
    if (n >= NN) return;
    int lane = threadIdx.x & 31;
    int s0 = g_scr.off_all[n], s1 = g_scr.off_all[n + 1];
    bool l2ok = (64 + lane) < 75;
    float4 a0 = {0,0,0,0}, a1 = {0,0,0,0}, a2 = {0,0,0,0};
    for (int p = s0; p < s1; p++) {
        int j = g_scr.jall[p];
        float w = g_scr.wj[p];
        const float4* xr = (const float4*)(xin + (size_t)j * EHD);
        float4 v0 = __ldg(xr + lane);
        float4 v1 = __ldg(xr + 32 + lane);
        a0.x += w*v0.x; a0.y += w*v0.y; a0.z += w*v0.z; a0.w += w*v0.w;
        a1.x += w*v1.x; a1.y += w*v1.y; a1.z += w*v1.z; a1.w += w*v1.w;
        if (l2ok) {
            float4 v2 = __ldg(xr + 64 + lane);
            a2.x += w*v2.x; a2.y += w*v2.y; a2.z += w*v2.z; a2.w += w*v2.w;
        }
    }
    int dcnt = s1 - s0;
    float dn = (dcnt > 0) ? rsqrtf((float)dcnt) : 0.0f;
    const float4* xp = (const float4*)(xin + (size_t)n * EHD);
    const float4* gp = (const float4*)(gate + (size_t)n * EHD);
    float4* yr = (float4*)(xout + (size_t)n * EHD);
    float4 o, g4, p4;

    g4 = gp[lane]; p4 = xp[lane];
    o.x = g4.x * fmaxf(dn*a0.x, 0.f) + (1.f - g4.x) * p4.x;
    o.y = g4.y * fmaxf(dn*a0.y, 0.f) + (1.f - g4.y) * p4.y;
    o.z = g4.z * fmaxf(dn*a0.z, 0.f) + (1.f - g4.z) * p4.z;
    o.w = g4.w * fmaxf(dn*a0.w, 0.f) + (1.f - g4.w) * p4.w;
    yr[lane] = o;

    g4 = gp[32 + lane]; p4 = xp[32 + lane];
    o.x = g4.x * fmaxf(dn*a1.x, 0.f) + (1.f - g4.x) * p4.x;
    o.y = g4.y * fmaxf(dn*a1.y, 0.f) + (1.f - g4.y) * p4.y;
    o.z = g4.z * fmaxf(dn*a1.z, 0.f) + (1.f - g4.z) * p4.z;
    o.w = g4.w * fmaxf(dn*a1.w, 0.f) + (1.f - g4.w) * p4.w;
    yr[32 + lane] = o;

    if (l2ok) {
        g4 = gp[64 + lane]; p4 = xp[64 + lane];
        o.x = g4.x * fmaxf(dn*a2.x, 0.f) + (1.f - g4.x) * p4.x;
        o.y = g4.y * fmaxf(dn*a2.y, 0.f) + (1.f - g4.y) * p4.y;
        o.z = g4.z * fmaxf(dn*a2.z, 0.f) + (1.f - g4.z) * p4.z;
        o.w = g4.w * fmaxf(dn*a2.w, 0.f) + (1.f - g4.w) * p4.w;
        yr[64 + lane] = o;
    }
}

// ------------------------------------------------------------------
// per-relation means + rf2 + RF assembly
// ------------------------------------------------------------------
__global__ __launch_bounds__(256) void k_relmean(const float* __restrict__ sr1w,
                                                 const float* __restrict__ sr1b) {
    int r = blockIdx.x;
    int tid = threadIdx.x;
    __shared__ float acc[200];
    __shared__ float cat[200];
    if (tid < 200) acc[tid] = 0.f;
    __syncthreads();

    int wi = tid >> 5, lane = tid & 31;
    int s0 = g_scr.off_r[r], s1 = g_scr.off_r[r + 1];
    float4 lh = {0,0,0,0}, lt = {0,0,0,0};
    for (int p = s0 + wi; p < s1; p += 8) {
        int hh = g_scr.hr[p], tt = g_scr.tr[p];
        if (lane < 25) {
            const float4* sh_ = (const float4*)(g_scr.S + (size_t)hh * THD);
            const float4* st_ = (const float4*)(g_scr.S + (size_t)tt * THD);
            float4 v = __ldg(sh_ + lane);
            lh.x += v.x; lh.y += v.y; lh.z += v.z; lh.w += v.w;
            float4 u = __ldg(st_ + lane);
            lt.x += u.x; lt.y += u.y; lt.z += u.z; lt.w += u.w;
        }
    }
    if (lane < 25) {
        atomicAdd(&acc[4*lane+0], lh.x); atomicAdd(&acc[4*lane+1], lh.y);
        atomicAdd(&acc[4*lane+2], lh.z); atomicAdd(&acc[4*lane+3], lh.w);
        atomicAdd(&acc[100+4*lane+0], lt.x); atomicAdd(&acc[100+4*lane+1], lt.y);
        atomicAdd(&acc[100+4*lane+2], lt.z); atomicAdd(&acc[100+4*lane+3], lt.w);
    }
    __syncthreads();
    float c = fmaxf((float)(s1 - s0), 1.f);
    if (tid < 200) cat[tid] = acc[tid] / c;
    __syncthreads();
    if (tid < 100) {
        float a = sr1b[tid];
        #pragma unroll 4
        for (int k = 0; k < 200; k++) a += cat[k] * sr1w[k * 100 + tid];
        float* rf = g_scr.RF + (size_t)r * EHD;
        rf[tid]       = a;
        rf[100 + tid] = cat[tid];
        rf[200 + tid] = cat[100 + tid];
    }
}

// ------------------------------------------------------------------
// batched small sgemm: ER_k = RF @ wr_k + br_k
// ------------------------------------------------------------------
__global__ __launch_bounds__(256) void k_sgemm3(
    const float* __restrict__ W0, const float* __restrict__ b0,
    const float* __restrict__ W1, const float* __restrict__ b1,
    const float* __restrict__ W2, const float* __restrict__ b2) {
    const float* W; const float* bias; float* OUT;
    int z = blockIdx.z;
    if      (z == 0) { W = W0; bias = b0; OUT = g_scr.ER0; }
    else if (z == 1) { W = W1; bias = b1; OUT = g_scr.ER1; }
    else             { W = W2; bias = b2; OUT = g_scr.ER2; }
    const float* A = g_scr.RF;
    const int M = NR, N = EHD, K = EHD;

    __shared__ float As[16][128];
    __shared__ float Bs[16][64];
    int mb = blockIdx.x * 128, nb = blockIdx.y * 64;
    int tid = threadIdx.x;
    int ty = tid >> 4;
    int tx = tid & 15;
    float acc[8][4];
    #pragma unroll
    for (int i = 0; i < 8; i++)
        #pragma unroll
        for (int j = 0; j < 4; j++) acc[i][j] = 0.f;

    for (int k0 = 0; k0 < K; k0 += 16) {
        #pragma unroll
        for (int l = 0; l < 8; l++) {
            int idx = tid + l * 256;
            int arr = idx >> 4, ak = idx & 15;
            int gm = mb + arr, gk = k0 + ak;
            As[ak][arr] = (gm < M && gk < K) ? A[(size_t)gm * K + gk] : 0.f;
        }
        #pragma unroll
        for (int l = 0; l < 4; l++) {
            int idx = tid + l * 256;
            int bn = idx & 63, bk = idx >> 6;
            int gk = k0 + bk, gnn = nb + bn;
            Bs[bk][bn] = (gk < K && gnn < N) ? W[(size_t)gk * N + gnn] : 0.f;
        }
        __syncthreads();
        #pragma unroll
        for (int k = 0; k < 16; k++) {
            float a[8], b[4];
            #pragma unroll
            for (int i = 0; i < 8; i++) a[i] = As[k][ty * 8 + i];
            #pragma unroll
            for (int j = 0; j < 4; j++) b[j] = Bs[k][tx * 4 + j];
            #pragma unroll
            for (int i = 0; i < 8; i++)
                #pragma unroll
                for (int j = 0; j < 4; j++) acc[i][j] += a[i] * b[j];
        }
        __syncthreads();
    }
    #pragma unroll
    for (int i = 0; i < 8; i++) {
        int gm = mb + ty * 8 + i;
        if (gm >= M) continue;
        #pragma unroll
        for (int j = 0; j < 4; j++) {
            int gnn = nb + tx * 4 + j;
            if (gnn >= N) continue;
            OUT[(size_t)gm * N + gnn] = acc[i][j] + bias[gnn];
        }
    }
}

// ------------------------------------------------------------------
// batched rowdot over ER matrices: cR_k = ER_k . ar_k
// ------------------------------------------------------------------
__global__ void k_rowdot3(const float* __restrict__ v0, const float* __restrict__ v1,
                          const float* __restrict__ v2) {
    int y = blockIdx.y;
    const float* Mtx; const float* v; float* out;
    if      (y == 0) { Mtx = g_scr.ER0; v = v0; out = g_scr.cR0; }
    else if (y == 1) { Mtx = g_scr.ER1; v = v1; out = g_scr.cR1; }
    else             { Mtx = g_scr.ER2; v = v2; out = g_scr.cR2; }
    int r = (blockIdx.x * blockDim.x + threadIdx.x) >> 5;
    int lane = threadIdx.x & 31;
    if (r >= NR) return;
    const float4* mr = (const float4*)(Mtx + (size_t)r * EHD);
    const float4* vv = (const float4*)v;
    float s = 0.f;
    float4 a = mr[lane], b = vv[lane];
    s += a.x*b.x + a.y*b.y + a.z*b.z + a.w*b.w;
    a = mr[32 + lane]; b = vv[32 + lane];
    s += a.x*b.x + a.y*b.y + a.z*b.z + a.w*b.w;
    if (lane < 11) {
        a = mr[64 + lane]; b = vv[64 + lane];
        s += a.x*b.x + a.y*b.y + a.z*b.z + a.w*b.w;
    }
    s = wredsum(s);
    if (lane == 0) out[r] = s;
}

// ------------------------------------------------------------------
// FUSED triple r2e: keeps the node row in registers across all 3 rounds,
// then emits xa = row.ai and xj = row.aj and writes the row once.
// ------------------------------------------------------------------
__global__ void k_r2e3(const float* __restrict__ ah, const float* __restrict__ at,
                       const float* __restrict__ ah1, const float* __restrict__ ai,
                       const float* __restrict__ aj) {
    int n = (blockIdx.x * blockDim.x + threadIdx.x) >> 5;
    if (n >= NN) return;
    int lane = threadIdx.x & 31;
    bool l2ok = (64 + lane) < 75;

    float4* zr = (float4*)(g_scr.Z + (size_t)n * EHD);
    float4 v0 = zr[lane];
    float4 v1 = zr[32 + lane];
    float4 v2 = l2ok ? zr[64 + lane] : make_float4(0.f, 0.f, 0.f, 0.f);

    auto dotv = [&](const float* w) -> float {
        const float4* wp = (const float4*)w;
        float4 q = wp[lane];
        float d = v0.x*q.x + v0.y*q.y + v0.z*q.z + v0.w*q.w;
        q = wp[32 + lane];
        d += v1.x*q.x + v1.y*q.y + v1.z*q.z + v1.w*q.w;
        if (l2ok) {
            q = wp[64 + lane];
            d += v2.x*q.x + v2.y*q.y + v2.z*q.z + v2.w*q.w;
        }
        return wredsum(d);
    };

    auto round = [&](const float* ER, const float* cR,
                     const int* off, const int* rels, const float* avec) {
        float xan = dotv(avec);
        int s0 = off[n], s1 = off[n + 1];
        float4 a0 = {0,0,0,0}, a1 = {0,0,0,0}, a2 = {0,0,0,0};
        if (s1 > s0) {
            float m = -1e30f;
            for (int p = s0 + lane; p < s1; p += 32)
                m = fmaxf(m, lrelu01(xan + cR[rels[p]]));
            m = wredmax(m);
            float den = 0.f;
            for (int p = s0 + lane; p < s1; p += 32)
                den += expf(lrelu01(xan + cR[rels[p]]) - m);
            den = wredsum(den);
            float inv = 1.f / den;
            for (int p = s0; p < s1; p++) {
                int r = rels[p];
                float w = expf(lrelu01(xan + cR[r]) - m) * inv;
                const float4* er = (const float4*)(ER + (size_t)r * EHD);
                float4 u0 = __ldg(er + lane);
                float4 u1 = __ldg(er + 32 + lane);
                a0.x += w*u0.x; a0.y += w*u0.y; a0.z += w*u0.z; a0.w += w*u0.w;
                a1.x += w*u1.x; a1.y += w*u1.y; a1.z += w*u1.z; a1.w += w*u1.w;
                if (l2ok) {
                    float4 u2 = __ldg(er + 64 + lane);
                    a2.x += w*u2.x; a2.y += w*u2.y; a2.z += w*u2.z; a2.w += w*u2.w;
                }
            }
        }
        v0.x += fmaxf(a0.x, 0.f); v0.y += fmaxf(a0.y, 0.f);
        v0.z += fmaxf(a0.z, 0.f); v0.w += fmaxf(a0.w, 0.f);
        v1.x += fmaxf(a1.x, 0.f); v1.y += fmaxf(a1.y, 0.f);
        v1.z += fmaxf(a1.z, 0.f); v1.w += fmaxf(a1.w, 0.f);
        v2.x += fmaxf(a2.x, 0.f); v2.y += fmaxf(a2.y, 0.f);
        v2.z += fmaxf(a2.z, 0.f); v2.w += fmaxf(a2.w, 0.f);
    };

    round(g_scr.ER0, g_scr.cR0, g_scr.off_h, g_scr.relh, ah);
    round(g_scr.ER1, g_scr.cR1, g_scr.off_t, g_scr.relt, at);
    round(g_scr.ER2, g_scr.cR2, g_scr.off_h, g_scr.relh, ah1);

    float dai = dotv(ai);
    float daj = dotv(aj);
    if (lane == 0) {
        g_scr.xa[n] = dai;
        g_scr.xj[n] = daj;
    }
    zr[lane] = v0;
    zr[32 + lane] = v1;
    if (l2ok) zr[64 + lane] = v2;
}

// ------------------------------------------------------------------
// final GAT + fc output
// ------------------------------------------------------------------
__global__ void k_gatfinal(const float* __restrict__ fcw, const float* __restrict__ fcb,
                           float* __restrict__ outp) {
    int n = (blockIdx.x * blockDim.x + threadIdx.x) >> 5;
    if (n >= NN) return;
    int lane = threadIdx.x & 31;
    int s0 = g_scr.off_all[n], s1 = g_scr.off_all[n + 1];
    bool l2ok = (64 + lane) < 75;
    float4 a0 = {0,0,0,0}, a1 = {0,0,0,0}, a2 = {0,0,0,0};

    if (s1 > s0) {
        float xin = g_scr.xa[n];
        float m = -1e30f;
        for (int p = s0 + lane; p < s1; p += 32)
            m = fmaxf(m, lrelu01(xin + g_scr.xj[g_scr.jall[p]]));
        m = wredmax(m);
        float den = 0.f;
        for (int p = s0 + lane; p < s1; p += 32)
            den += expf(lrelu01(xin + g_scr.xj[g_scr.jall[p]]) - m);
        den = wredsum(den);
        float inv = 1.f / den;
        for (int p = s0; p < s1; p++) {
            int j = g_scr.jall[p];
            float w = expf(lrelu01(xin + g_scr.xj[j]) - m) * inv;
            const float4* xr = (const float4*)(g_scr.Z + (size_t)j * EHD);
            float4 u0 = __ldg(xr + lane);
            float4 u1 = __ldg(xr + 32 + lane);
            a0.x += w*u0.x; a0.y += w*u0.y; a0.z += w*u0.z; a0.w += w*u0.w;
            a1.x += w*u1.x; a1.y += w*u1.y; a1.z += w*u1.z; a1.w += w*u1.w;
            if (l2ok) {
                float4 u2 = __ldg(xr + 64 + lane);
                a2.x += w*u2.x; a2.y += w*u2.y; a2.z += w*u2.z; a2.w += w*u2.w;
            }
        }
    }
    const float4* xn = (const float4*)(g_scr.Z + (size_t)n * EHD);
    const float4* f1 = (const float4*)fcw;
    const float4* f2 = (const float4*)(fcw + EHD);
    float local = 0.f;

    float4 v = xn[lane], q = f1[lane], g = f2[lane];
    local += v.x*q.x + v.y*q.y + v.z*q.z + v.w*q.w;
    local += fmaxf(a0.x,0.f)*g.x + fmaxf(a0.y,0.f)*g.y + fmaxf(a0.z,0.f)*g.z + fmaxf(a0.w,0.f)*g.w;
    v = xn[32+lane]; q = f1[32+lane]; g = f2[32+lane];
    local += v.x*q.x + v.y*q.y + v.z*q.z + v.w*q.w;
    local += fmaxf(a1.x,0.f)*g.x + fmaxf(a1.y,0.f)*g.y + fmaxf(a1.z,0.f)*g.z + fmaxf(a1.w,0.f)*g.w;
    if (l2ok) {
        v = xn[64+lane]; q = f1[64+lane]; g = f2[64+lane];
        local += v.x*q.x + v.y*q.y + v.z*q.z + v.w*q.w;
        local += fmaxf(a2.x,0.f)*g.x + fmaxf(a2.y,0.f)*g.y + fmaxf(a2.z,0.f)*g.z + fmaxf(a2.w,0.f)*g.w;
    }
    local = wredsum(local);
    if (lane == 0) outp[n] = local + fcb[0];
}

// ------------------------------------------------------------------
// launcher
// ------------------------------------------------------------------
extern "C" void kernel_launch(void* const* d_in, const int* in_sizes, int n_in,
                              void* d_out, int out_size) {
    const float* x      = (const float*)d_in[0];
    const int*   ei     = (const int*)d_in[1];
    const int*   rel    = (const int*)d_in[2];
    const int*   eia    = (const int*)d_in[3];
    const float* hw1_w  = (const float*)d_in[5];
    const float* hw1_b  = (const float*)d_in[6];
    const float* hw2_w  = (const float*)d_in[7];
    const float* hw2_b  = (const float*)d_in[8];
    const float* tc1_w  = (const float*)d_in[9];
    const float* tc1_b  = (const float*)d_in[10];
    const float* sr1_w  = (const float*)d_in[11];
    const float* sr1_b  = (const float*)d_in[12];
    const float* wr_w   = (const float*)d_in[15];
    const float* wr_b   = (const float*)d_in[16];
    const float* wr1_w  = (const float*)d_in[17];
    const float* wr1_b  = (const float*)d_in[18];
    const float* wr2_w  = (const float*)d_in[19];
    const float* wr2_b  = (const float*)d_in[20];
    const float* ah_w   = (const float*)d_in[21];
    const float* ah1_w  = (const float*)d_in[22];
    const float* at_w   = (const float*)d_in[23];
    const float* ar1_w  = (const float*)d_in[24];
    const float* ar2_w  = (const float*)d_in[25];
    const float* ar3_w  = (const float*)d_in[26];
    const float* ai_w   = (const float*)d_in[27];
    const float* aj_w   = (const float*)d_in[28];
    const float* fc_w   = (const float*)d_in[29];
    const float* fc_b   = (const float*)d_in[30];
    float* out = (float*)d_out;

    const int* h  = ei;
    const int* t  = ei + NE;
    const int* jj = eia;
    const int* ii = eia + NEA;

    Scratch* g = nullptr;
    cudaGetSymbolAddress((void**)&g, g_scr);

    const int TPB = 256;
    const int NODE_BLKS = divup(NN * 32, TPB);

    cudaMemsetAsync(g->cnt_all, 0, (size_t)(3 * NN + NR) * sizeof(int));

    k_hist4<<<dim3(128, 4), TPB>>>(ii, h, t, rel);        // 1
    k_scan4<<<4, 1024>>>();                               // 2
    k_scatter4<<<dim3(512, 4), TPB>>>(ii, jj, h, t, rel); // 3

    dim3 gemmGrid300(divup(NN, 128), divup(EHD, 64));
    dim3 gemmGrid100(divup(NN, 128), divup(THD, 64));
    k_tgemm<<<gemmGrid300, 256>>>(x, hw1_w, hw1_b, g->Y, NN, EHD, EHD, 1);   // 4 (profiled)
    k_gcnhw<<<NODE_BLKS, TPB>>>(x, g->Y, g->X);
    k_tgemm<<<gemmGrid300, 256>>>(g->X, hw2_w, hw2_b, g->Y, NN, EHD, EHD, 1);
    k_gcnhw<<<NODE_BLKS, TPB>>>(g->X, g->Y, g->Z);
    k_tgemm<<<gemmGrid100, 256>>>(g->Z, tc1_w, tc1_b, g->S, NN, THD, EHD, 0);

    k_relmean<<<NR, 256>>>(sr1_w, sr1_b);
    dim3 gemmGridR(divup(NR, 128), divup(EHD, 64), 3);
    k_sgemm3<<<gemmGridR, 256>>>(wr_w, wr_b, wr1_w, wr1_b, wr2_w, wr2_b);
    k_rowdot3<<<dim3(divup(NR * 32, TPB), 3), TPB>>>(ar1_w, ar2_w, ar3_w);

    k_r2e3<<<NODE_BLKS, TPB>>>(ah_w, at_w, ah1_w, ai_w, aj_w);
    k_gatfinal<<<NODE_BLKS, TPB>>>(fc_w, fc_b, out);
    (void)in_sizes; (void)n_in; (void)out_size;
}

// round 14
// speedup vs baseline: 1.3343x; 1.0250x over previous
#include <cuda_runtime.h>
#include <cuda_bf16.h>
#include <stdint.h>
#include <math.h>

#define NN  50000
#define NE  250000
#define NEA 500000
#define NR  300
#define EHD 300
#define THD 100

// ------------------------------------------------------------------
// Static device scratch
// ------------------------------------------------------------------
struct Scratch {
    float X[(size_t)NN * EHD];
    float Y[(size_t)NN * EHD];   // gate buffer
    float Z[(size_t)NN * EHD];
    float S[(size_t)NN * THD];
    float RF[NR * EHD];
    float ER0[NR * EHD];
    float ER1[NR * EHD];
    float ER2[NR * EHD];
    float cR0[NR];
    float cR1[NR];
    float cR2[NR];
    float xa[NN];
    float xj[NN];
    float wj[NEA];
    int jall[NEA];
    int relh[NE];
    int relt[NE];
    int hr[NE];
    int tr[NE];
    int cnt_all[NN];
    int cnt_h[NN];
    int cnt_t[NN];
    int cnt_r[NR];
    int off_all[NN + 1];
    int off_h[NN + 1];
    int off_t[NN + 1];
    int off_r[NR + 1];
    int cur_all[NN];
    int cur_h[NN];
    int cur_t[NN];
    int cur_r[NR];
};
__device__ Scratch g_scr;

// ------------------------------------------------------------------
// helpers
// ------------------------------------------------------------------
__device__ __forceinline__ float lrelu01(float z) { return z > 0.f ? z : 0.01f * z; }

__device__ __forceinline__ float wredsum(float v) {
    #pragma unroll
    for (int o = 16; o > 0; o >>= 1) v += __shfl_xor_sync(0xffffffffu, v, o);
    return v;
}
__device__ __forceinline__ float wredmax(float v) {
    #pragma unroll
    for (int o = 16; o > 0; o >>= 1) v = fmaxf(v, __shfl_xor_sync(0xffffffffu, v, o));
    return v;
}

static inline int divup(int a, int b) { return (a + b - 1) / b; }

// ------------------------------------------------------------------
// setup kernels
// ------------------------------------------------------------------
__global__ void k_hist4(const int* __restrict__ ii, const int* __restrict__ h,
                        const int* __restrict__ t, const int* __restrict__ rel) {
    int y = blockIdx.y;
    const int* keys; int n; int* cnt;
    if      (y == 0) { keys = ii;  n = NEA; cnt = g_scr.cnt_all; }
    else if (y == 1) { keys = h;   n = NE;  cnt = g_scr.cnt_h; }
    else if (y == 2) { keys = t;   n = NE;  cnt = g_scr.cnt_t; }
    else             { keys = rel; n = NE;  cnt = g_scr.cnt_r; }
    for (int i = blockIdx.x * blockDim.x + threadIdx.x; i < n; i += gridDim.x * blockDim.x)
        atomicAdd(&cnt[keys[i]], 1);
}

__global__ void k_scan4() {
    int y = blockIdx.x;
    const int* c; int n; int* off; int* cur;
    if      (y == 0) { c = g_scr.cnt_all; n = NN; off = g_scr.off_all; cur = g_scr.cur_all; }
    else if (y == 1) { c = g_scr.cnt_h;   n = NN; off = g_scr.off_h;   cur = g_scr.cur_h; }
    else if (y == 2) { c = g_scr.cnt_t;   n = NN; off = g_scr.off_t;   cur = g_scr.cur_t; }
    else             { c = g_scr.cnt_r;   n = NR; off = g_scr.off_r;   cur = g_scr.cur_r; }
    __shared__ int wsum[32];
    __shared__ int carrysh;
    int tid = threadIdx.x;
    int wid = tid >> 5, lane = tid & 31;
    if (tid == 0) carrysh = 0;
    __syncthreads();
    for (int base = 0; base < n; base += 1024) {
        int v = (base + tid < n) ? c[base + tid] : 0;
        int s = v;
        #pragma unroll
        for (int o = 1; o < 32; o <<= 1) {
            int t2 = __shfl_up_sync(0xffffffffu, s, o);
            if (lane >= o) s += t2;
        }
        if (lane == 31) wsum[wid] = s;
        __syncthreads();
        if (wid == 0) {
            int w = wsum[lane];
            #pragma unroll
            for (int o = 1; o < 32; o <<= 1) {
                int t2 = __shfl_up_sync(0xffffffffu, w, o);
                if (lane >= o) w += t2;
            }
            wsum[lane] = w;
        }
        __syncthreads();
        int woff = (wid > 0) ? wsum[wid - 1] : 0;
        int total = wsum[31];
        int ex = carrysh + woff + s - v;
        if (base + tid < n) { off[base + tid] = ex; cur[base + tid] = ex; }
        __syncthreads();
        if (tid == 0) carrysh += total;
        __syncthreads();
    }
    if (tid == 0) off[n] = carrysh;
}

__global__ void k_scatter4(const int* __restrict__ ii, const int* __restrict__ jjv,
                           const int* __restrict__ h, const int* __restrict__ t,
                           const int* __restrict__ rel) {
    int y = blockIdx.y;
    int stride = gridDim.x * blockDim.x;
    int i0 = blockIdx.x * blockDim.x + threadIdx.x;
    if (y == 0) {
        for (int i = i0; i < NEA; i += stride) {
            int pos = atomicAdd(&g_scr.cur_all[ii[i]], 1);
            int j = jjv[i];
            int d = g_scr.cnt_all[j];
            g_scr.jall[pos] = j;
            g_scr.wj[pos] = (d > 0) ? rsqrtf((float)d) : 0.0f;
        }
    } else if (y == 1) {
        for (int i = i0; i < NE; i += stride) {
            int pos = atomicAdd(&g_scr.cur_h[h[i]], 1);
            g_scr.relh[pos] = rel[i];
        }
    } else if (y == 2) {
        for (int i = i0; i < NE; i += stride) {
            int pos = atomicAdd(&g_scr.cur_t[t[i]], 1);
            g_scr.relt[pos] = rel[i];
        }
    } else {
        for (int i = i0; i < NE; i += stride) {
            int pos = atomicAdd(&g_scr.cur_r[rel[i]], 1);
            g_scr.hr[pos] = h[i];
            g_scr.tr[pos] = t[i];
        }
    }
}

// ------------------------------------------------------------------
// TF32 tensor-core GEMM: smem staged, ldmatrix fragments, cp.async A tile.
// fp32 bits fed directly to the tf32 MMA (hardware truncates to tf32).
// A smem: [128 rows][ASTR], B smem TRANSPOSED: [64 n][BSTR] (k-contig).
// OUT = C + bias (gate 0) | sigmoid(C + bias) (gate 1)
// ------------------------------------------------------------------
#define MMA_TF32(c, a, b0v, b1v) \
    asm volatile("mma.sync.aligned.m16n8k8.row.col.f32.tf32.tf32.f32 " \
        "{%0,%1,%2,%3}, {%4,%5,%6,%7}, {%8,%9}, {%0,%1,%2,%3};" \
        : "+f"((c)[0]), "+f"((c)[1]), "+f"((c)[2]), "+f"((c)[3]) \
        : "r"((a)[0]), "r"((a)[1]), "r"((a)[2]), "r"((a)[3]), \
          "r"(b0v), "r"(b1v))

#define LDSM_X4(r, p) \
    asm volatile("ldmatrix.sync.aligned.m8n8.x4.shared.b16 {%0,%1,%2,%3}, [%4];" \
        : "=r"((r)[0]), "=r"((r)[1]), "=r"((r)[2]), "=r"((r)[3]) : "r"(p))

#define CP_ASYNC16(dst, src) \
    asm volatile("cp.async.cg.shared.global [%0], [%1], 16;" \
        :: "r"(dst), "l"(src) : "memory")
#define CP_COMMIT() asm volatile("cp.async.commit_group;" ::: "memory")
#define CP_WAIT0()  asm volatile("cp.async.wait_group 0;" ::: "memory")

#define ASTR 20
#define BSTR 20

__global__ __launch_bounds__(256) void k_tgemm(
    const float* __restrict__ A, const float* __restrict__ W,
    const float* __restrict__ bias, float* __restrict__ OUT,
    int M, int N, int K, int gate) {
    __shared__ float sA[2][128 * ASTR];
    __shared__ float sB[2][64 * BSTR];

    const int mb = blockIdx.x * 128, nb = blockIdx.y * 64;
    const int tid = threadIdx.x;
    const int lane = tid & 31;
    const int wid = tid >> 5;
    const int warp_m = (wid & 3) * 32;
    const int warp_n = (wid >> 2) * 32;

    float acc[2][4][4];
    #pragma unroll
    for (int mt = 0; mt < 2; mt++)
        #pragma unroll
        for (int nt = 0; nt < 4; nt++)
            #pragma unroll
            for (int q = 0; q < 4; q++) acc[mt][nt][q] = 0.f;

    // ldmatrix lane addressing
    const int g4 = lane >> 3;
    const int rsel = (g4 & 1) * 8 + (lane & 7);
    const int segf = (g4 >> 1) * 4;
    uint32_t pA[2], pB[2];
    #pragma unroll
    for (int mt = 0; mt < 2; mt++)
        pA[mt] = (uint32_t)__cvta_generic_to_shared(
            &sA[0][(warp_m + mt * 16 + rsel) * ASTR + segf]);
    #pragma unroll
    for (int np = 0; np < 2; np++)
        pB[np] = (uint32_t)__cvta_generic_to_shared(
            &sB[0][(warp_n + np * 16 + rsel) * BSTR + segf]);
    const uint32_t ABUF = 128u * ASTR * 4u;
    const uint32_t BBUF = 64u * BSTR * 4u;

    const int la_row = tid >> 1, la_cb = (tid & 1) * 8;   // A: 128r x 16k
    const int lb_n = tid & 63, lb_kq = (tid >> 6) * 4;    // B: 64n x 16k (n-major)

    const uint32_t sA0 = (uint32_t)__cvta_generic_to_shared(&sA[0][0]);
    const uint32_t adst0 = sA0 + (uint32_t)(la_row * ASTR + la_cb) * 4u;
    const int gmA = mb + la_row;
    const float* arow = A + (size_t)((gmA < M) ? gmA : (M - 1)) * K;
    const bool arow_ok = (gmA < M);

    // prefetch: fill buf with tile k0 (A via cp.async fast path, B via LDG+STS)
    auto prefetch = [&](int k0, int buf) {
        int c0 = k0 + la_cb;
        uint32_t adst = adst0 + (uint32_t)buf * ABUF;
        if (arow_ok && c0 + 8 <= K) {
            CP_ASYNC16(adst, arow + c0);
            CP_ASYNC16(adst + 16u, arow + c0 + 4);
        } else {
            float tmp[8];
            #pragma unroll
            for (int q = 0; q < 8; q++) {
                int gk = c0 + q;
                tmp[q] = (arow_ok && gk < K) ? arow[gk] : 0.f;
            }
            float4 v;
            v.x = tmp[0]; v.y = tmp[1]; v.z = tmp[2]; v.w = tmp[3];
            *(float4*)&sA[buf][la_row * ASTR + la_cb] = v;
            v.x = tmp[4]; v.y = tmp[5]; v.z = tmp[6]; v.w = tmp[7];
            *(float4*)&sA[buf][la_row * ASTR + la_cb + 4] = v;
        }
        int gn = nb + lb_n;
        float rb[4];
        #pragma unroll
        for (int q = 0; q < 4; q++) {
            int gk = k0 + lb_kq + q;
            rb[q] = (gk < K && gn < N) ? __ldg(&W[(size_t)gk * N + gn]) : 0.f;
        }
        float4 v;
        v.x = rb[0]; v.y = rb[1]; v.z = rb[2]; v.w = rb[3];
        *(float4*)&sB[buf][lb_n * BSTR + lb_kq] = v;   // transposed: [n][k]
        CP_COMMIT();
    };

    int nk = (K + 15) / 16;
    prefetch(0, 0);
    CP_WAIT0();
    __syncthreads();

    for (int ki = 0; ki < nk; ki++) {
        int buf = ki & 1;
        bool nxt = (ki + 1 < nk);
        if (nxt) prefetch((ki + 1) * 16, buf ^ 1);

        uint32_t aoff = buf * ABUF, boff = buf * BBUF;
        #pragma unroll
        for (int ks = 0; ks < 2; ks++) {
            uint32_t a[2][4], bfrag[2][4];
            #pragma unroll
            for (int mt = 0; mt < 2; mt++)
                LDSM_X4(a[mt], pA[mt] + aoff + ks * 32);
            #pragma unroll
            for (int np = 0; np < 2; np++)
                LDSM_X4(bfrag[np], pB[np] + boff + ks * 32);
            #pragma unroll
            for (int mt = 0; mt < 2; mt++)
                #pragma unroll
                for (int np = 0; np < 2; np++) {
                    MMA_TF32(acc[mt][np * 2],     a[mt], bfrag[np][0], bfrag[np][2]);
                    MMA_TF32(acc[mt][np * 2 + 1], a[mt], bfrag[np][1], bfrag[np][3]);
                }
        }
        CP_WAIT0();
        __syncthreads();
    }

    const int erow = lane >> 2;
    const int ecol = (lane & 3) * 2;
    #pragma unroll
    for (int mt = 0; mt < 2; mt++) {
        #pragma unroll
        for (int nt = 0; nt < 4; nt++) {
            #pragma unroll
            for (int q = 0; q < 4; q++) {
                int gm = mb + warp_m + mt * 16 + erow + (q >> 1) * 8;
                int gc = nb + warp_n + nt * 8 + ecol + (q & 1);
                if (gm >= M || gc >= N) continue;
                float v = acc[mt][nt][q] + bias[gc];
                if (gate) v = 1.f / (1.f + expf(-v));
                OUT[(size_t)gm * N + gc] = v;
            }
        }
    }
}

// ------------------------------------------------------------------
// GCN + highway combine
// ------------------------------------------------------------------
__global__ void k_gcnhw(const float* __restrict__ xin, const float* __restrict__ gate,
                        float* __restrict__ xout) {
    int n = (blockIdx.x * blockDim.x + threadIdx.x) >> 5;
    if (n >= NN) return;
    int lane = threadIdx.x & 31;
    int s0 = g_scr.off_all[n], s1 = g_scr.off_all[n + 1];
    bool l2ok = (64 + lane) < 75;
    float4 a0 = {0,0,0,0}, a1 = {0,0,0,0}, a2 = {0,0,0,0};
    for (int p = s0; p < s1; p++) {
        int j = g_scr.jall[p];
        float w = g_scr.wj[p];
        const float4* xr = (const float4*)(xin + (size_t)j * EHD);
        float4 v0 = __ldg(xr + lane);
        float4 v1 = __ldg(xr + 32 + lane);
        a0.x += w*v0.x; a0.y += w*v0.y; a0.z += w*v0.z; a0.w += w*v0.w;
        a1.x += w*v1.x; a1.y += w*v1.y; a1.z += w*v1.z; a1.w += w*v1.w;
        if (l2ok) {
            float4 v2 = __ldg(xr + 64 + lane);
            a2.x += w*v2.x; a2.y += w*v2.y; a2.z += w*v2.z; a2.w += w*v2.w;
        }
    }
    int dcnt = s1 - s0;
    float dn = (dcnt > 0) ? rsqrtf((float)dcnt) : 0.0f;
    const float4* xp = (const float4*)(xin + (size_t)n * EHD);
    const float4* gp = (const float4*)(gate + (size_t)n * EHD);
    float4* yr = (float4*)(xout + (size_t)n * EHD);
    float4 o, g4, p4;

    g4 = gp[lane]; p4 = xp[lane];
    o.x = g4.x * fmaxf(dn*a0.x, 0.f) + (1.f - g4.x) * p4.x;
    o.y = g4.y * fmaxf(dn*a0.y, 0.f) + (1.f - g4.y) * p4.y;
    o.z = g4.z * fmaxf(dn*a0.z, 0.f) + (1.f - g4.z) * p4.z;
    o.w = g4.w * fmaxf(dn*a0.w, 0.f) + (1.f - g4.w) * p4.w;
    yr[lane] = o;

    g4 = gp[32 + lane]; p4 = xp[32 + lane];
    o.x = g4.x * fmaxf(dn*a1.x, 0.f) + (1.f - g4.x) * p4.x;
    o.y = g4.y * fmaxf(dn*a1.y, 0.f) + (1.f - g4.y) * p4.y;
    o.z = g4.z * fmaxf(dn*a1.z, 0.f) + (1.f - g4.z) * p4.z;
    o.w = g4.w * fmaxf(dn*a1.w, 0.f) + (1.f - g4.w) * p4.w;
    yr[32 + lane] = o;

    if (l2ok) {
        g4 = gp[64 + lane]; p4 = xp[64 + lane];
        o.x = g4.x * fmaxf(dn*a2.x, 0.f) + (1.f - g4.x) * p4.x;
        o.y = g4.y * fmaxf(dn*a2.y, 0.f) + (1.f - g4.y) * p4.y;
        o.z = g4.z * fmaxf(dn*a2.z, 0.f) + (1.f - g4.z) * p4.z;
        o.w = g4.w * fmaxf(dn*a2.w, 0.f) + (1.f - g4.w) * p4.w;
        yr[64 + lane] = o;
    }
}

// ------------------------------------------------------------------
// per-relation means + rf2 + RF assembly
// ------------------------------------------------------------------
__global__ __launch_bounds__(256) void k_relmean(const float* __restrict__ sr1w,
                                                 const float* __restrict__ sr1b) {
    int r = blockIdx.x;
    int tid = threadIdx.x;
    __shared__ float acc[200];
    __shared__ float cat[200];
    if (tid < 200) acc[tid] = 0.f;
    __syncthreads();

    int wi = tid >> 5, lane = tid & 31;
    int s0 = g_scr.off_r[r], s1 = g_scr.off_r[r + 1];
    float4 lh = {0,0,0,0}, lt = {0,0,0,0};
    for (int p = s0 + wi; p < s1; p += 8) {
        int hh = g_scr.hr[p], tt = g_scr.tr[p];
        if (lane < 25) {
            const float4* sh_ = (const float4*)(g_scr.S + (size_t)hh * THD);
            const float4* st_ = (const float4*)(g_scr.S + (size_t)tt * THD);
            float4 v = __ldg(sh_ + lane);
            lh.x += v.x; lh.y += v.y; lh.z += v.z; lh.w += v.w;
            float4 u = __ldg(st_ + lane);
            lt.x += u.x; lt.y += u.y; lt.z += u.z; lt.w += u.w;
        }
    }
    if (lane < 25) {
        atomicAdd(&acc[4*lane+0], lh.x); atomicAdd(&acc[4*lane+1], lh.y);
        atomicAdd(&acc[4*lane+2], lh.z); atomicAdd(&acc[4*lane+3], lh.w);
        atomicAdd(&acc[100+4*lane+0], lt.x); atomicAdd(&acc[100+4*lane+1], lt.y);
        atomicAdd(&acc[100+4*lane+2], lt.z); atomicAdd(&acc[100+4*lane+3], lt.w);
    }
    __syncthreads();
    float c = fmaxf((float)(s1 - s0), 1.f);
    if (tid < 200) cat[tid] = acc[tid] / c;
    __syncthreads();
    if (tid < 100) {
        float a = sr1b[tid];
        #pragma unroll 4
        for (int k = 0; k < 200; k++) a += cat[k] * sr1w[k * 100 + tid];
        float* rf = g_scr.RF + (size_t)r * EHD;
        rf[tid]       = a;
        rf[100 + tid] = cat[tid];
        rf[200 + tid] = cat[100 + tid];
    }
}

// ------------------------------------------------------------------
// batched small sgemm: ER_k = RF @ wr_k + br_k
// ------------------------------------------------------------------
__global__ __launch_bounds__(256) void k_sgemm3(
    const float* __restrict__ W0, const float* __restrict__ b0,
    const float* __restrict__ W1, const float* __restrict__ b1,
    const float* __restrict__ W2, const float* __restrict__ b2) {
    const float* W; const float* bias; float* OUT;
    int z = blockIdx.z;
    if      (z == 0) { W = W0; bias = b0; OUT = g_scr.ER0; }
    else if (z == 1) { W = W1; bias = b1; OUT = g_scr.ER1; }
    else             { W = W2; bias = b2; OUT = g_scr.ER2; }
    const float* A = g_scr.RF;
    const int M = NR, N = EHD, K = EHD;

    __shared__ float As[16][128];
    __shared__ float Bs[16][64];
    int mb = blockIdx.x * 128, nb = blockIdx.y * 64;
    int tid = threadIdx.x;
    int ty = tid >> 4;
    int tx = tid & 15;
    float acc[8][4];
    #pragma unroll
    for (int i = 0; i < 8; i++)
        #pragma unroll
        for (int j = 0; j < 4; j++) acc[i][j] = 0.f;

    for (int k0 = 0; k0 < K; k0 += 16) {
        #pragma unroll
        for (int l = 0; l < 8; l++) {
            int idx = tid + l * 256;
            int arr = idx >> 4, ak = idx & 15;
            int gm = mb + arr, gk = k0 + ak;
            As[ak][arr] = (gm < M && gk < K) ? A[(size_t)gm * K + gk] : 0.f;
        }
        #pragma unroll
        for (int l = 0; l < 4; l++) {
            int idx = tid + l * 256;
            int bn = idx & 63, bk = idx >> 6;
            int gk = k0 + bk, gnn = nb + bn;
            Bs[bk][bn] = (gk < K && gnn < N) ? W[(size_t)gk * N + gnn] : 0.f;
        }
        __syncthreads();
        #pragma unroll
        for (int k = 0; k < 16; k++) {
            float a[8], b[4];
            #pragma unroll
            for (int i = 0; i < 8; i++) a[i] = As[k][ty * 8 + i];
            #pragma unroll
            for (int j = 0; j < 4; j++) b[j] = Bs[k][tx * 4 + j];
            #pragma unroll
            for (int i = 0; i < 8; i++)
                #pragma unroll
                for (int j = 0; j < 4; j++) acc[i][j] += a[i] * b[j];
        }
        __syncthreads();
    }
    #pragma unroll
    for (int i = 0; i < 8; i++) {
        int gm = mb + ty * 8 + i;
        if (gm >= M) continue;
        #pragma unroll
        for (int j = 0; j < 4; j++) {
            int gnn = nb + tx * 4 + j;
            if (gnn >= N) continue;
            OUT[(size_t)gm * N + gnn] = acc[i][j] + bias[gnn];
        }
    }
}

// ------------------------------------------------------------------
// batched rowdot over ER matrices: cR_k = ER_k . ar_k
// ------------------------------------------------------------------
__global__ void k_rowdot3(const float* __restrict__ v0, const float* __restrict__ v1,
                          const float* __restrict__ v2) {
    int y = blockIdx.y;
    const float* Mtx; const float* v; float* out;
    if      (y == 0) { Mtx = g_scr.ER0; v = v0; out = g_scr.cR0; }
    else if (y == 1) { Mtx = g_scr.ER1; v = v1; out = g_scr.cR1; }
    else             { Mtx = g_scr.ER2; v = v2; out = g_scr.cR2; }
    int r = (blockIdx.x * blockDim.x + threadIdx.x) >> 5;
    int lane = threadIdx.x & 31;
    if (r >= NR) return;
    const float4* mr = (const float4*)(Mtx + (size_t)r * EHD);
    const float4* vv = (const float4*)v;
    float s = 0.f;
    float4 a = mr[lane], b = vv[lane];
    s += a.x*b.x + a.y*b.y + a.z*b.z + a.w*b.w;
    a = mr[32 + lane]; b = vv[32 + lane];
    s += a.x*b.x + a.y*b.y + a.z*b.z + a.w*b.w;
    if (lane < 11) {
        a = mr[64 + lane]; b = vv[64 + lane];
        s += a.x*b.x + a.y*b.y + a.z*b.z + a.w*b.w;
    }
    s = wredsum(s);
    if (lane == 0) out[r] = s;
}

// ------------------------------------------------------------------
// FUSED triple r2e
// ------------------------------------------------------------------
__global__ void k_r2e3(const float* __restrict__ ah, const float* __restrict__ at,
                       const float* __restrict__ ah1, const float* __restrict__ ai,
                       const float* __restrict__ aj) {
    int n = (blockIdx.x * blockDim.x + threadIdx.x) >> 5;
    if (n >= NN) return;
    int lane = threadIdx.x & 31;
    bool l2ok = (64 + lane) < 75;

    float4* zr = (float4*)(g_scr.Z + (size_t)n * EHD);
    float4 v0 = zr[lane];
    float4 v1 = zr[32 + lane];
    float4 v2 = l2ok ? zr[64 + lane] : make_float4(0.f, 0.f, 0.f, 0.f);

    auto dotv = [&](const float* w) -> float {
        const float4* wp = (const float4*)w;
        float4 q = wp[lane];
        float d = v0.x*q.x + v0.y*q.y + v0.z*q.z + v0.w*q.w;
        q = wp[32 + lane];
        d += v1.x*q.x + v1.y*q.y + v1.z*q.z + v1.w*q.w;
        if (l2ok) {
            q = wp[64 + lane];
            d += v2.x*q.x + v2.y*q.y + v2.z*q.z + v2.w*q.w;
        }
        return wredsum(d);
    };

    auto round = [&](const float* ER, const float* cR,
                     const int* off, const int* rels, const float* avec) {
        float xan = dotv(avec);
        int s0 = off[n], s1 = off[n + 1];
        float4 a0 = {0,0,0,0}, a1 = {0,0,0,0}, a2 = {0,0,0,0};
        if (s1 > s0) {
            float m = -1e30f;
            for (int p = s0 + lane; p < s1; p += 32)
                m = fmaxf(m, lrelu01(xan + cR[rels[p]]));
            m = wredmax(m);
            float den = 0.f;
            for (int p = s0 + lane; p < s1; p += 32)
                den += expf(lrelu01(xan + cR[rels[p]]) - m);
            den = wredsum(den);
            float inv = 1.f / den;
            for (int p = s0; p < s1; p++) {
                int r = rels[p];
                float w = expf(lrelu01(xan + cR[r]) - m) * inv;
                const float4* er = (const float4*)(ER + (size_t)r * EHD);
                float4 u0 = __ldg(er + lane);
                float4 u1 = __ldg(er + 32 + lane);
                a0.x += w*u0.x; a0.y += w*u0.y; a0.z += w*u0.z; a0.w += w*u0.w;
                a1.x += w*u1.x; a1.y += w*u1.y; a1.z += w*u1.z; a1.w += w*u1.w;
                if (l2ok) {
                    float4 u2 = __ldg(er + 64 + lane);
                    a2.x += w*u2.x; a2.y += w*u2.y; a2.z += w*u2.z; a2.w += w*u2.w;
                }
            }
        }
        v0.x += fmaxf(a0.x, 0.f); v0.y += fmaxf(a0.y, 0.f);
        v0.z += fmaxf(a0.z, 0.f); v0.w += fmaxf(a0.w, 0.f);
        v1.x += fmaxf(a1.x, 0.f); v1.y += fmaxf(a1.y, 0.f);
        v1.z += fmaxf(a1.z, 0.f); v1.w += fmaxf(a1.w, 0.f);
        v2.x += fmaxf(a2.x, 0.f); v2.y += fmaxf(a2.y, 0.f);
        v2.z += fmaxf(a2.z, 0.f); v2.w += fmaxf(a2.w, 0.f);
    };

    round(g_scr.ER0, g_scr.cR0, g_scr.off_h, g_scr.relh, ah);
    round(g_scr.ER1, g_scr.cR1, g_scr.off_t, g_scr.relt, at);
    round(g_scr.ER2, g_scr.cR2, g_scr.off_h, g_scr.relh, ah1);

    float dai = dotv(ai);
    float daj = dotv(aj);
    if (lane == 0) {
        g_scr.xa[n] = dai;
        g_scr.xj[n] = daj;
    }
    zr[lane] = v0;
    zr[32 + lane] = v1;
    if (l2ok) zr[64 + lane] = v2;
}

// ------------------------------------------------------------------
// final GAT + fc output
// ------------------------------------------------------------------
__global__ void k_gatfinal(const float* __restrict__ fcw, const float* __restrict__ fcb,
                           float* __restrict__ outp) {
    int n = (blockIdx.x * blockDim.x + threadIdx.x) >> 5;
    if (n >= NN) return;
    int lane = threadIdx.x & 31;
    int s0 = g_scr.off_all[n], s1 = g_scr.off_all[n + 1];
    bool l2ok = (64 + lane) < 75;
    float4 a0 = {0,0,0,0}, a1 = {0,0,0,0}, a2 = {0,0,0,0};

    if (s1 > s0) {
        float xin = g_scr.xa[n];
        float m = -1e30f;
        for (int p = s0 + lane; p < s1; p += 32)
            m = fmaxf(m, lrelu01(xin + g_scr.xj[g_scr.jall[p]]));
        m = wredmax(m);
        float den = 0.f;
        for (int p = s0 + lane; p < s1; p += 32)
            den += expf(lrelu01(xin + g_scr.xj[g_scr.jall[p]]) - m);
        den = wredsum(den);
        float inv = 1.f / den;
        for (int p = s0; p < s1; p++) {
            int j = g_scr.jall[p];
            float w = expf(lrelu01(xin + g_scr.xj[j]) - m) * inv;
            const float4* xr = (const float4*)(g_scr.Z + (size_t)j * EHD);
            float4 u0 = __ldg(xr + lane);
            float4 u1 = __ldg(xr + 32 + lane);
            a0.x += w*u0.x; a0.y += w*u0.y; a0.z += w*u0.z; a0.w += w*u0.w;
            a1.x += w*u1.x; a1.y += w*u1.y; a1.z += w*u1.z; a1.w += w*u1.w;
            if (l2ok) {
                float4 u2 = __ldg(xr + 64 + lane);
                a2.x += w*u2.x; a2.y += w*u2.y; a2.z += w*u2.z; a2.w += w*u2.w;
            }
        }
    }
    const float4* xn = (const float4*)(g_scr.Z + (size_t)n * EHD);
    const float4* f1 = (const float4*)fcw;
    const float4* f2 = (const float4*)(fcw + EHD);
    float local = 0.f;

    float4 v = xn[lane], q = f1[lane], g = f2[lane];
    local += v.x*q.x + v.y*q.y + v.z*q.z + v.w*q.w;
    local += fmaxf(a0.x,0.f)*g.x + fmaxf(a0.y,0.f)*g.y + fmaxf(a0.z,0.f)*g.z + fmaxf(a0.w,0.f)*g.w;
    v = xn[32+lane]; q = f1[32+lane]; g = f2[32+lane];
    local += v.x*q.x + v.y*q.y + v.z*q.z + v.w*q.w;
    local += fmaxf(a1.x,0.f)*g.x + fmaxf(a1.y,0.f)*g.y + fmaxf(a1.z,0.f)*g.z + fmaxf(a1.w,0.f)*g.w;
    if (l2ok) {
        v = xn[64+lane]; q = f1[64+lane]; g = f2[64+lane];
        local += v.x*q.x + v.y*q.y + v.z*q.z + v.w*q.w;
        local += fmaxf(a2.x,0.f)*g.x + fmaxf(a2.y,0.f)*g.y + fmaxf(a2.z,0.f)*g.z + fmaxf(a2.w,0.f)*g.w;
    }
    local = wredsum(local);
    if (lane == 0) outp[n] = local + fcb[0];
}

// ------------------------------------------------------------------
// launcher
// ------------------------------------------------------------------
extern "C" void kernel_launch(void* const* d_in, const int* in_sizes, int n_in,
                              void* d_out, int out_size) {
    const float* x      = (const float*)d_in[0];
    const int*   ei     = (const int*)d_in[1];
    const int*   rel    = (const int*)d_in[2];
    const int*   eia    = (const int*)d_in[3];
    const float* hw1_w  = (const float*)d_in[5];
    const float* hw1_b  = (const float*)d_in[6];
    const float* hw2_w  = (const float*)d_in[7];
    const float* hw2_b  = (const float*)d_in[8];
    const float* tc1_w  = (const float*)d_in[9];
    const float* tc1_b  = (const float*)d_in[10];
    const float* sr1_w  = (const float*)d_in[11];
    const float* sr1_b  = (const float*)d_in[12];
    const float* wr_w   = (const float*)d_in[15];
    const float* wr_b   = (const float*)d_in[16];
    const float* wr1_w  = (const float*)d_in[17];
    const float* wr1_b  = (const float*)d_in[18];
    const float* wr2_w  = (const float*)d_in[19];
    const float* wr2_b  = (const float*)d_in[20];
    const float* ah_w   = (const float*)d_in[21];
    const float* ah1_w  = (const float*)d_in[22];
    const float* at_w   = (const float*)d_in[23];
    const float* ar1_w  = (const float*)d_in[24];
    const float* ar2_w  = (const float*)d_in[25];
    const float* ar3_w  = (const float*)d_in[26];
    const float* ai_w   = (const float*)d_in[27];
    const float* aj_w   = (const float*)d_in[28];
    const float* fc_w   = (const float*)d_in[29];
    const float* fc_b   = (const float*)d_in[30];
    float* out = (float*)d_out;

    const int* h  = ei;
    const int* t  = ei + NE;
    const int* jj = eia;
    const int* ii = eia + NEA;

    Scratch* g = nullptr;
    cudaGetSymbolAddress((void**)&g, g_scr);

    const int TPB = 256;
    const int NODE_BLKS = divup(NN * 32, TPB);

    cudaMemsetAsync(g->cnt_all, 0, (size_t)(3 * NN + NR) * sizeof(int));

    k_hist4<<<dim3(128, 4), TPB>>>(ii, h, t, rel);        // 1
    k_scan4<<<4, 1024>>>();                               // 2
    k_scatter4<<<dim3(512, 4), TPB>>>(ii, jj, h, t, rel); // 3

    dim3 gemmGrid300(divup(NN, 128), divup(EHD, 64));
    dim3 gemmGrid100(divup(NN, 128), divup(THD, 64));
    k_tgemm<<<gemmGrid300, 256>>>(x, hw1_w, hw1_b, g->Y, NN, EHD, EHD, 1);   // 4 (profiled)
    k_gcnhw<<<NODE_BLKS, TPB>>>(x, g->Y, g->X);
    k_tgemm<<<gemmGrid300, 256>>>(g->X, hw2_w, hw2_b, g->Y, NN, EHD, EHD, 1);
    k_gcnhw<<<NODE_BLKS, TPB>>>(g->X, g->Y, g->Z);
    k_tgemm<<<gemmGrid100, 256>>>(g->Z, tc1_w, tc1_b, g->S, NN, THD, EHD, 0);

    k_relmean<<<NR, 256>>>(sr1_w, sr1_b);
    dim3 gemmGridR(divup(NR, 128), divup(EHD, 64), 3);
    k_sgemm3<<<gemmGridR, 256>>>(wr_w, wr_b, wr1_w, wr1_b, wr2_w, wr2_b);
    k_rowdot3<<<dim3(divup(NR * 32, TPB), 3), TPB>>>(ar1_w, ar2_w, ar3_w);

    k_r2e3<<<NODE_BLKS, TPB>>>(ah_w, at_w, ah1_w, ai_w, aj_w);
    k_gatfinal<<<NODE_BLKS, TPB>>>(fc_w, fc_b, out);
    (void)in_sizes; (void)n_in; (void)out_size;
}